// round 6
// baseline (speedup 1.0000x reference)
#include <cuda_runtime.h>
#include <cuda_fp16.h>
#include <cstdint>

#define NP 200000
#define NH 500000
#define NG 20000
#define NE_T 800000
#define NE_E 1000000
#define NE_H 500000
#define NE_ALL (NE_T + NE_E + NE_H)
#define HD 128
#define KTOT 416            // [t 128 | e 128 | h 32 | P 128]
#define HCW 32              // Hcat padded row width (26 -> 32)
#define XHW 32              // Xh row: [mean26 | flag | pad5]
#define XSW 264             // smem X row stride (halfs)
#define ASW 40              // smem stage row stride (halfs)
#define SCAN_N (3 * NP)
#define SCAN_BLOCKS ((SCAN_N + 2047) / 2048)
#define SMEM_FUSED ((128 * XSW + 128 * ASW + 128 * ASW) * 2)

// -------- static scratch (no allocations anywhere) --------
__device__ __half g_P0[(size_t)NP * HD];     // 51.2 MB
__device__ __half g_P1[(size_t)NP * HD];     // 51.2 MB
__device__ __half g_Hc[(size_t)NH * HCW];    // 32 MB (raw hist concat)
__device__ __half g_Xh[(size_t)NP * XHW];    // 12.8 MB (hist agg, layer-invariant)
__device__ __half g_Wbh[2 * HD * KTOT];      // fused weights [layer][o][k(416)]
__device__ float g_bSum[2 * HD];
__device__ float g_GC[NG];
__device__ int g_cnt[SCAN_N];
__device__ int g_cur[SCAN_N];
__device__ int g_offs[SCAN_N];
__device__ int g_bsum[SCAN_BLOCKS];
__device__ int g_sorted[NE_ALL];

// ------------------------------- utility ------------------------------------
__global__ void zero_buf(float* p, size_t n) {
    for (size_t i = (size_t)blockIdx.x * blockDim.x + threadIdx.x; i < n;
         i += (size_t)gridDim.x * blockDim.x)
        p[i] = 0.0f;
}

__global__ void counti_k(const int* __restrict__ edge, int ne, int* __restrict__ cnt) {
    int i = blockIdx.x * blockDim.x + threadIdx.x;
    if (i < ne) atomicAdd(&cnt[edge[ne + i]], 1);
}

__global__ void gcount_k(const int* __restrict__ batch, float* __restrict__ gc) {
    int i = blockIdx.x * blockDim.x + threadIdx.x;
    if (i < NP) atomicAdd(&gc[batch[i]], 1.0f);
}

// ------------------------------- scan (exclusive) ----------------------------
__global__ void scan1(const int* __restrict__ in, int* __restrict__ out, int* __restrict__ bsum) {
    __shared__ int ts[256];
    int base = blockIdx.x * 2048 + threadIdx.x * 8;
    int v[8];
    int s = 0;
#pragma unroll
    for (int j = 0; j < 8; j++) {
        int idx = base + j;
        v[j] = (idx < SCAN_N) ? in[idx] : 0;
        s += v[j];
    }
    ts[threadIdx.x] = s;
    __syncthreads();
    for (int off = 1; off < 256; off <<= 1) {
        int t = (threadIdx.x >= off) ? ts[threadIdx.x - off] : 0;
        __syncthreads();
        ts[threadIdx.x] += t;
        __syncthreads();
    }
    int run = ts[threadIdx.x] - s;
    if (threadIdx.x == 255) bsum[blockIdx.x] = ts[255];
#pragma unroll
    for (int j = 0; j < 8; j++) {
        int idx = base + j;
        if (idx < SCAN_N) out[idx] = run;
        run += v[j];
    }
}

__global__ void scan2(int* bsum, int n) {
    __shared__ int ts[512];
    int v = (threadIdx.x < n) ? bsum[threadIdx.x] : 0;
    ts[threadIdx.x] = v;
    __syncthreads();
    for (int off = 1; off < 512; off <<= 1) {
        int t = (threadIdx.x >= off) ? ts[threadIdx.x - off] : 0;
        __syncthreads();
        ts[threadIdx.x] += t;
        __syncthreads();
    }
    if (threadIdx.x < n) bsum[threadIdx.x] = ts[threadIdx.x] - v;
}

__global__ void scan3(int* out, const int* __restrict__ bsum) {
    int idx = blockIdx.x * blockDim.x + threadIdx.x;
    if (idx < SCAN_N) out[idx] += bsum[idx >> 11];
}

__global__ void scatter_k(const int* __restrict__ edge, int ne, const int* __restrict__ offs,
                          int* __restrict__ cur, int* __restrict__ sorted) {
    int i = blockIdx.x * blockDim.x + threadIdx.x;
    if (i < ne) {
        int s = edge[i], d = edge[ne + i];
        int pos = offs[d] + atomicAdd(&cur[d], 1);
        sorted[pos] = s;
    }
}

// ------ fused per-layer weight [layer][o][k(416)] with hist-encoder fold -----
__global__ void build_w(const float* __restrict__ sWl, const float* __restrict__ sWr,
                        const float* __restrict__ sb, const float* __restrict__ Wh,
                        const float* __restrict__ bh, __half* __restrict__ Wbh,
                        float* __restrict__ bS) {
    int i = blockIdx.x * blockDim.x + threadIdx.x;
    if (i >= 2 * HD * KTOT) return;
    int l = i / (HD * KTOT);
    int rem = i - l * HD * KTOT;
    int o = rem / KTOT;
    int k = rem - o * KTOT;
    float v;
    if (k < 256) {
        int part = k >> 7, kk = k & 127;
        v = sWl[(((size_t)(l * 3 + part)) * HD + o) * HD + kk];
    } else if (k < 282) {
        int c = k - 256;
        float s = 0.f;
        const float* wl = sWl + ((size_t)(l * 3 + 2) * HD + o) * HD;
        for (int j = 0; j < HD; j++) s += wl[j] * Wh[j * 26 + c];
        v = s;
    } else if (k == 282) {
        float s = 0.f;
        const float* wl = sWl + ((size_t)(l * 3 + 2) * HD + o) * HD;
        for (int j = 0; j < HD; j++) s += wl[j] * bh[j];
        v = s;
    } else if (k < 288) {
        v = 0.f;
    } else {
        int kk = k - 288;
        v = sWr[(((size_t)(l * 3 + 0)) * HD + o) * HD + kk] +
            sWr[(((size_t)(l * 3 + 1)) * HD + o) * HD + kk] +
            sWr[(((size_t)(l * 3 + 2)) * HD + o) * HD + kk];
    }
    Wbh[i] = __float2half(v);
    if (i < 2 * HD) {
        int l2 = i >> 7, o2 = i & 127;
        bS[i] = sb[(l2 * 3 + 0) * HD + o2] + sb[(l2 * 3 + 1) * HD + o2] +
                sb[(l2 * 3 + 2) * HD + o2];
    }
}

// --------------------------- player encoder ----------------------------------
__global__ __launch_bounds__(128) void enc_p(const float* __restrict__ xp,
                                             const float* __restrict__ embp,
                                             const float* __restrict__ Wp,
                                             const float* __restrict__ bp,
                                             __half* __restrict__ out) {
    __shared__ float f[8][85];
    int r0 = blockIdx.x * 8;
    int tid = threadIdx.x;
    for (int idx = tid; idx < 8 * 85; idx += 128) {
        int r = idx / 85, k = idx - r * 85;
        const float* x = xp + (size_t)(r0 + r) * 10;
        float v;
        if (k < 5) {
            v = x[k == 0 ? 0 : k + 5];
        } else {
            int j = (k - 5) >> 4, e = (k - 5) & 15;
            int ci = (int)x[1 + j];
            ci = min(max(ci, 0), 199);
            v = embp[((size_t)j * 200 + ci) * 16 + e];
        }
        f[r][k] = v;
    }
    __syncthreads();
    float acc[8];
#pragma unroll
    for (int r = 0; r < 8; r++) acc[r] = bp[tid];
    const float* w = Wp + tid * 85;
    for (int k = 0; k < 85; k++) {
        float wk = __ldg(w + k);
#pragma unroll
        for (int r = 0; r < 8; r++) acc[r] += f[r][k] * wk;
    }
#pragma unroll
    for (int r = 0; r < 8; r++) out[(size_t)(r0 + r) * HD + tid] = __float2half(acc[r]);
}

// -------------- raw hist concat (26 dims, padded to 32 halfs) ----------------
__global__ __launch_bounds__(256) void build_hcat(const float* __restrict__ xh,
                                                  const float* __restrict__ e0,
                                                  const float* __restrict__ e3,
                                                  __half* __restrict__ Hc) {
    int r = blockIdx.x * blockDim.x + threadIdx.x;
    if (r >= NH) return;
    const float* x = xh + (size_t)r * 8;
    float f[32];
    f[0] = x[1]; f[1] = x[2]; f[2] = x[4]; f[3] = x[5]; f[4] = x[6]; f[5] = x[7];
    int c0 = min(max((int)x[0], 0), 1999);
    int c3 = min(max((int)x[3], 0), 9);
#pragma unroll
    for (int j = 0; j < 16; j++) f[6 + j] = e0[c0 * 16 + j];
#pragma unroll
    for (int j = 0; j < 4; j++) f[22 + j] = e3[c3 * 4 + j];
#pragma unroll
    for (int j = 26; j < 32; j++) f[j] = 0.f;
    __half h[32];
#pragma unroll
    for (int j = 0; j < 32; j++) h[j] = __float2half(f[j]);
#pragma unroll
    for (int q = 0; q < 4; q++)
        *(uint4*)(Hc + (size_t)r * HCW + q * 8) = *(uint4*)&h[q * 8];
}

// ------------- hist gather: half-warp per node -> Xh[node][32] ---------------
__global__ __launch_bounds__(256) void agg_h(const __half* __restrict__ Hc,
                                             const int* __restrict__ sorted,
                                             const int* __restrict__ offs,
                                             const int* __restrict__ cnt,
                                             __half* __restrict__ Xh) {
    int hw = (blockIdx.x * blockDim.x + threadIdx.x) >> 4;
    int lane = threadIdx.x & 15;
    if (hw >= NP) return;
    int start = offs[hw], c = cnt[hw];
    float2 a = make_float2(0.f, 0.f);
    for (int e = 0; e < c; e++) {
        int s = __ldg(sorted + start + e);
        unsigned int v = __ldg((const unsigned int*)(Hc + (size_t)s * HCW + lane * 2));
        float2 f = __half22float2(*(__half2*)&v);
        a.x += f.x; a.y += f.y;
    }
    float inv = 1.0f / fmaxf((float)c, 1.0f);
    int col = lane * 2;
    float v0 = a.x * inv, v1 = a.y * inv;
    if (col == 26) { v0 = (c > 0) ? 1.f : 0.f; v1 = 0.f; }
    else if (col > 26) { v0 = 0.f; v1 = 0.f; }
    __half2 o = __floats2half2_rn(v0, v1);
    *(__half2*)(Xh + (size_t)hw * XHW + col) = o;
}

// --------------------- warp gather of mean(128-dim rows) ---------------------
__device__ __forceinline__ float4 gather_mean128(const __half* __restrict__ src,
                                                 const int* __restrict__ sorted,
                                                 int start, int c, int lane) {
    float4 a = make_float4(0.f, 0.f, 0.f, 0.f);
    for (int e0 = 0; e0 < c; e0 += 32) {
        int my = (e0 + lane < c) ? sorted[start + e0 + lane] : 0;
        int n = min(32, c - e0);
        int e = 0;
        for (; e + 4 <= n; e += 4) {
            int s0 = __shfl_sync(0xFFFFFFFFu, my, e);
            int s1 = __shfl_sync(0xFFFFFFFFu, my, e + 1);
            int s2 = __shfl_sync(0xFFFFFFFFu, my, e + 2);
            int s3 = __shfl_sync(0xFFFFFFFFu, my, e + 3);
            uint2 v0 = __ldg((const uint2*)(src + (size_t)s0 * HD + lane * 4));
            uint2 v1 = __ldg((const uint2*)(src + (size_t)s1 * HD + lane * 4));
            uint2 v2 = __ldg((const uint2*)(src + (size_t)s2 * HD + lane * 4));
            uint2 v3 = __ldg((const uint2*)(src + (size_t)s3 * HD + lane * 4));
            float2 f;
            f = __half22float2(*(__half2*)&v0.x); a.x += f.x; a.y += f.y;
            f = __half22float2(*(__half2*)&v0.y); a.z += f.x; a.w += f.y;
            f = __half22float2(*(__half2*)&v1.x); a.x += f.x; a.y += f.y;
            f = __half22float2(*(__half2*)&v1.y); a.z += f.x; a.w += f.y;
            f = __half22float2(*(__half2*)&v2.x); a.x += f.x; a.y += f.y;
            f = __half22float2(*(__half2*)&v2.y); a.z += f.x; a.w += f.y;
            f = __half22float2(*(__half2*)&v3.x); a.x += f.x; a.y += f.y;
            f = __half22float2(*(__half2*)&v3.y); a.z += f.x; a.w += f.y;
        }
        for (; e < n; e++) {
            int s = __shfl_sync(0xFFFFFFFFu, my, e);
            uint2 v = __ldg((const uint2*)(src + (size_t)s * HD + lane * 4));
            float2 f;
            f = __half22float2(*(__half2*)&v.x); a.x += f.x; a.y += f.y;
            f = __half22float2(*(__half2*)&v.y); a.z += f.x; a.w += f.y;
        }
    }
    return a;
}

// ------------------------------- fp16 MMA ------------------------------------
__device__ __forceinline__ void mma_f16(float* c, const unsigned int* a, const unsigned int* b) {
    asm volatile(
        "mma.sync.aligned.m16n8k16.row.col.f32.f16.f16.f32 "
        "{%0,%1,%2,%3}, {%4,%5,%6,%7}, {%8,%9}, {%0,%1,%2,%3};"
        : "+f"(c[0]), "+f"(c[1]), "+f"(c[2]), "+f"(c[3])
        : "r"(a[0]), "r"(a[1]), "r"(a[2]), "r"(a[3]), "r"(b[0]), "r"(b[1]));
}

// -------- fused layer: gather t/e means into smem, then 128x128 GEMM ---------
// C = relu([aggT | aggE | Xh | P](row,416) @ Wbh[o][k].T + bS); optional pool.
__global__ __launch_bounds__(256, 2) void sage_fused(
    const __half* __restrict__ P, const __half* __restrict__ Xh,
    const __half* __restrict__ Wbh, const float* __restrict__ bS,
    const int* __restrict__ sorted, const int* __restrict__ offs,
    const int* __restrict__ cnt,
    __half* __restrict__ out, const int* __restrict__ batch,
    const float* __restrict__ Wc, float* __restrict__ pool_out, int do_pool) {
    extern __shared__ __half sh[];
    __half* Xs = sh;                         // [128][XSW=264] t|e slabs
    __half* Asb = sh + 128 * XSW;            // [128][40] stage for h/P chunks
    __half* Bsb = Asb + 128 * ASW;           // [128][40]
    int tid = threadIdx.x, wid = tid >> 5, lane = tid & 31;
    int gr = lane >> 2, tg = lane & 3;
    int rowBase = blockIdx.x * 128;
    int wm = (wid >> 1) * 32, wn = (wid & 1) * 64;

    // ---- gather phase: warp w handles rows w*16 .. w*16+15 ----
    for (int ni = 0; ni < 16; ni++) {
        int r = wid * 16 + ni;
        int node = rowBase + r;
        if (node < NP) {
            int st = offs[node], c = cnt[node];
            float4 a = gather_mean128(P, sorted, st, c, lane);
            float inv = 1.0f / fmaxf((float)c, 1.0f);
            __half2 o0 = __floats2half2_rn(a.x * inv, a.y * inv);
            __half2 o1 = __floats2half2_rn(a.z * inv, a.w * inv);
            uint2 ov; ov.x = *(unsigned int*)&o0; ov.y = *(unsigned int*)&o1;
            *(uint2*)&Xs[r * XSW + lane * 4] = ov;
            st = offs[NP + node]; c = cnt[NP + node];
            a = gather_mean128(P, sorted, st, c, lane);
            inv = 1.0f / fmaxf((float)c, 1.0f);
            o0 = __floats2half2_rn(a.x * inv, a.y * inv);
            o1 = __floats2half2_rn(a.z * inv, a.w * inv);
            ov.x = *(unsigned int*)&o0; ov.y = *(unsigned int*)&o1;
            *(uint2*)&Xs[r * XSW + 128 + lane * 4] = ov;
        } else {
            uint2 z = make_uint2(0u, 0u);
            *(uint2*)&Xs[r * XSW + lane * 4] = z;
            *(uint2*)&Xs[r * XSW + 128 + lane * 4] = z;
        }
    }
    __syncthreads();

    float acc[2][8][4];
#pragma unroll
    for (int i = 0; i < 2; i++)
#pragma unroll
        for (int j = 0; j < 8; j++)
#pragma unroll
            for (int k = 0; k < 4; k++) acc[i][j][k] = 0.f;

    for (int kc = 0; kc < KTOT; kc += 32) {
        bool fromX = (kc < 256);
        if (!fromX) {
#pragma unroll
            for (int t = 0; t < 2; t++) {
                int q = tid + t * 256;
                int r = q >> 2, c8 = (q & 3) * 8;
                int row = min(rowBase + r, NP - 1);
                const __half* sp = (kc < 288) ? (Xh + (size_t)row * XHW + (kc - 256) + c8)
                                              : (P + (size_t)row * HD + (kc - 288) + c8);
                *(uint4*)&Asb[r * ASW + c8] = *(const uint4*)sp;
            }
        }
#pragma unroll
        for (int t = 0; t < 2; t++) {
            int q = tid + t * 256;
            int o = q >> 2, c8 = (q & 3) * 8;
            *(uint4*)&Bsb[o * ASW + c8] = *(const uint4*)(Wbh + (size_t)o * KTOT + kc + c8);
        }
        __syncthreads();
#pragma unroll
        for (int ks = 0; ks < 2; ks++) {
            int k0 = ks * 16;
            unsigned int a[2][4];
#pragma unroll
            for (int mt = 0; mt < 2; mt++) {
                int r = wm + mt * 16 + gr;
                if (fromX) {
                    a[mt][0] = *(const unsigned int*)&Xs[r * XSW + kc + k0 + 2 * tg];
                    a[mt][1] = *(const unsigned int*)&Xs[(r + 8) * XSW + kc + k0 + 2 * tg];
                    a[mt][2] = *(const unsigned int*)&Xs[r * XSW + kc + k0 + 2 * tg + 8];
                    a[mt][3] = *(const unsigned int*)&Xs[(r + 8) * XSW + kc + k0 + 2 * tg + 8];
                } else {
                    a[mt][0] = *(const unsigned int*)&Asb[r * ASW + k0 + 2 * tg];
                    a[mt][1] = *(const unsigned int*)&Asb[(r + 8) * ASW + k0 + 2 * tg];
                    a[mt][2] = *(const unsigned int*)&Asb[r * ASW + k0 + 2 * tg + 8];
                    a[mt][3] = *(const unsigned int*)&Asb[(r + 8) * ASW + k0 + 2 * tg + 8];
                }
            }
#pragma unroll
            for (int nt = 0; nt < 8; nt++) {
                int n = wn + nt * 8 + gr;
                unsigned int b[2];
                b[0] = *(const unsigned int*)&Bsb[n * ASW + k0 + 2 * tg];
                b[1] = *(const unsigned int*)&Bsb[n * ASW + k0 + 2 * tg + 8];
                mma_f16(acc[0][nt], a[0], b);
                mma_f16(acc[1][nt], a[1], b);
            }
        }
        __syncthreads();
    }

    if (do_pool) {
        float ps[4] = {0.f, 0.f, 0.f, 0.f};
#pragma unroll
        for (int mt = 0; mt < 2; mt++)
#pragma unroll
            for (int nt = 0; nt < 8; nt++) {
                int col = wn + nt * 8 + 2 * tg;
                float w0 = Wc[col], w1 = Wc[col + 1];
                float b0 = bS[col], b1 = bS[col + 1];
                ps[mt * 2 + 0] += fmaxf(acc[mt][nt][0] + b0, 0.f) * w0 +
                                  fmaxf(acc[mt][nt][1] + b1, 0.f) * w1;
                ps[mt * 2 + 1] += fmaxf(acc[mt][nt][2] + b0, 0.f) * w0 +
                                  fmaxf(acc[mt][nt][3] + b1, 0.f) * w1;
            }
#pragma unroll
        for (int j = 0; j < 4; j++) {
            ps[j] += __shfl_xor_sync(0xFFFFFFFFu, ps[j], 1);
            ps[j] += __shfl_xor_sync(0xFFFFFFFFu, ps[j], 2);
        }
        if (tg == 0) {
#pragma unroll
            for (int mt = 0; mt < 2; mt++) {
                int r0 = rowBase + wm + mt * 16 + gr;
                int r1 = r0 + 8;
                if (r0 < NP) atomicAdd(&pool_out[batch[r0]], ps[mt * 2]);
                if (r1 < NP) atomicAdd(&pool_out[batch[r1]], ps[mt * 2 + 1]);
            }
        }
    } else {
#pragma unroll
        for (int mt = 0; mt < 2; mt++) {
#pragma unroll
            for (int nt = 0; nt < 8; nt++) {
                int col = wn + nt * 8 + 2 * tg;
                float b0 = bS[col], b1 = bS[col + 1];
                int r0 = rowBase + wm + mt * 16 + gr;
                if (r0 < NP) {
                    __half2 v = __floats2half2_rn(fmaxf(acc[mt][nt][0] + b0, 0.f),
                                                  fmaxf(acc[mt][nt][1] + b1, 0.f));
                    *(__half2*)(out + (size_t)r0 * HD + col) = v;
                }
                int r1 = r0 + 8;
                if (r1 < NP) {
                    __half2 v = __floats2half2_rn(fmaxf(acc[mt][nt][2] + b0, 0.f),
                                                  fmaxf(acc[mt][nt][3] + b1, 0.f));
                    *(__half2*)(out + (size_t)r1 * HD + col) = v;
                }
            }
        }
    }
}

__global__ void fin_k(float* out, const float* gc, const float* __restrict__ bc) {
    int g = blockIdx.x * blockDim.x + threadIdx.x;
    if (g < NG) out[g] = out[g] / fmaxf(gc[g], 1.0f) + bc[0];
}

// -------------------------------- launcher -----------------------------------
extern "C" void kernel_launch(void* const* d_in, const int* in_sizes, int n_in,
                              void* d_out, int out_size) {
    const float* x_player = (const float*)d_in[0];
    const float* x_hist   = (const float*)d_in[1];
    const int*   e_t      = (const int*)d_in[2];
    const int*   e_e      = (const int*)d_in[3];
    const int*   e_h      = (const int*)d_in[4];
    const int*   batch    = (const int*)d_in[5];
    const float* emb_p    = (const float*)d_in[6];
    const float* emb_h0   = (const float*)d_in[7];
    const float* emb_h3   = (const float*)d_in[8];
    const float* Wp       = (const float*)d_in[9];
    const float* bp       = (const float*)d_in[10];
    const float* Wh       = (const float*)d_in[11];
    const float* bh       = (const float*)d_in[12];
    const float* sWl      = (const float*)d_in[13];
    const float* sb       = (const float*)d_in[14];
    const float* sWr      = (const float*)d_in[15];
    const float* Wc       = (const float*)d_in[16];
    const float* bc       = (const float*)d_in[17];
    float* out = (float*)d_out;

    __half *P0, *P1, *Hc, *Xh, *Wbh;
    float *bS, *GC;
    int *cnt, *cur, *offs, *bsum, *sorted;
    cudaGetSymbolAddress((void**)&P0, g_P0);
    cudaGetSymbolAddress((void**)&P1, g_P1);
    cudaGetSymbolAddress((void**)&Hc, g_Hc);
    cudaGetSymbolAddress((void**)&Xh, g_Xh);
    cudaGetSymbolAddress((void**)&Wbh, g_Wbh);
    cudaGetSymbolAddress((void**)&bS, g_bSum);
    cudaGetSymbolAddress((void**)&GC, g_GC);
    cudaGetSymbolAddress((void**)&cnt, g_cnt);
    cudaGetSymbolAddress((void**)&cur, g_cur);
    cudaGetSymbolAddress((void**)&offs, g_offs);
    cudaGetSymbolAddress((void**)&bsum, g_bsum);
    cudaGetSymbolAddress((void**)&sorted, g_sorted);

    static int smem_set = 0;
    if (!smem_set) {
        cudaFuncSetAttribute(sage_fused, cudaFuncAttributeMaxDynamicSharedMemorySize,
                             SMEM_FUSED);
        smem_set = 1;
    }

    // ---- CSR build ----
    zero_buf<<<512, 256>>>((float*)cnt, SCAN_N);
    zero_buf<<<512, 256>>>((float*)cur, SCAN_N);
    counti_k<<<(NE_T + 255) / 256, 256>>>(e_t, NE_T, cnt);
    counti_k<<<(NE_E + 255) / 256, 256>>>(e_e, NE_E, cnt + NP);
    counti_k<<<(NE_H + 255) / 256, 256>>>(e_h, NE_H, cnt + 2 * NP);
    scan1<<<SCAN_BLOCKS, 256>>>(cnt, offs, bsum);
    scan2<<<1, 512>>>(bsum, SCAN_BLOCKS);
    scan3<<<(SCAN_N + 255) / 256, 256>>>(offs, bsum);
    scatter_k<<<(NE_T + 255) / 256, 256>>>(e_t, NE_T, offs, cur, sorted);
    scatter_k<<<(NE_E + 255) / 256, 256>>>(e_e, NE_E, offs + NP, cur + NP, sorted);
    scatter_k<<<(NE_H + 255) / 256, 256>>>(e_h, NE_H, offs + 2 * NP, cur + 2 * NP, sorted);

    // ---- weights + encoders ----
    build_w<<<(2 * HD * KTOT + 255) / 256, 256>>>(sWl, sWr, sb, Wh, bh, Wbh, bS);
    enc_p<<<NP / 8, 128>>>(x_player, emb_p, Wp, bp, P0);
    build_hcat<<<(NH + 255) / 256, 256>>>(x_hist, emb_h0, emb_h3, Hc);

    // ---- hist aggregation (layer-invariant) ----
    agg_h<<<NP / 16, 256>>>(Hc, sorted, offs + 2 * NP, cnt + 2 * NP, Xh);

    int blocks = (NP + 127) / 128;

    // ---- layer 0 (fused gather + GEMM) ----
    sage_fused<<<blocks, 256, SMEM_FUSED>>>(P0, Xh, Wbh, bS, sorted, offs, cnt,
                                            P1, batch, Wc, out, 0);

    // ---- layer 1 (fused gather + GEMM + pool) ----
    zero_buf<<<(NG + 255) / 256, 256>>>(out, NG);
    zero_buf<<<(NG + 255) / 256, 256>>>(GC, NG);
    gcount_k<<<(NP + 255) / 256, 256>>>(batch, GC);
    sage_fused<<<blocks, 256, SMEM_FUSED>>>(P1, Xh, Wbh + (size_t)HD * KTOT, bS + HD,
                                            sorted, offs, cnt, P0, batch, Wc, out, 1);

    fin_k<<<(NG + 255) / 256, 256>>>(out, GC, bc);
}

// round 7
// speedup vs baseline: 1.2287x; 1.2287x over previous
#include <cuda_runtime.h>
#include <cuda_fp16.h>
#include <cstdint>

#define NP 200000
#define NH 500000
#define NG 20000
#define NE_T 800000
#define NE_E 1000000
#define NE_H 500000
#define NE_ALL (NE_T + NE_E + NE_H)
#define HD 128
#define XW 288              // X row: [aggT 128 | aggE 128 | aggH26 | flag | pad5]
#define KTOT 416            // 288 + 128 (P)
#define HCW 32              // Hcat padded row width (26 -> 32)
#define ASW 40              // smem stage row stride (halfs)
#define SCAN_N (3 * NP)
#define SCAN_BLOCKS ((SCAN_N + 2047) / 2048)

// -------- static scratch (no allocations anywhere) --------
__device__ __half g_P0[(size_t)NP * HD];     // 51.2 MB
__device__ __half g_P1[(size_t)NP * HD];     // 51.2 MB
__device__ __half g_Hc[(size_t)NH * HCW];    // 32 MB (raw hist concat)
__device__ __half g_X[(size_t)NP * XW];      // 115.2 MB
__device__ __half g_Wbh[2 * HD * KTOT];      // fused weights [layer][o][k(416)]
__device__ float g_bSum[2 * HD];
__device__ float g_GC[NG];
__device__ int g_cnt[SCAN_N];
__device__ int g_cur[SCAN_N];
__device__ int g_offs[SCAN_N];
__device__ int g_bsum[SCAN_BLOCKS];
__device__ int g_sorted[NE_ALL];

// ------------------------------- utility ------------------------------------
__global__ void zero_buf(float* p, size_t n) {
    for (size_t i = (size_t)blockIdx.x * blockDim.x + threadIdx.x; i < n;
         i += (size_t)gridDim.x * blockDim.x)
        p[i] = 0.0f;
}

__global__ void counti_k(const int* __restrict__ edge, int ne, int* __restrict__ cnt) {
    int i = blockIdx.x * blockDim.x + threadIdx.x;
    if (i < ne) atomicAdd(&cnt[edge[ne + i]], 1);
}

__global__ void gcount_k(const int* __restrict__ batch, float* __restrict__ gc) {
    int i = blockIdx.x * blockDim.x + threadIdx.x;
    if (i < NP) atomicAdd(&gc[batch[i]], 1.0f);
}

// ------------------------------- scan (exclusive) ----------------------------
__global__ void scan1(const int* __restrict__ in, int* __restrict__ out, int* __restrict__ bsum) {
    __shared__ int ts[256];
    int base = blockIdx.x * 2048 + threadIdx.x * 8;
    int v[8];
    int s = 0;
#pragma unroll
    for (int j = 0; j < 8; j++) {
        int idx = base + j;
        v[j] = (idx < SCAN_N) ? in[idx] : 0;
        s += v[j];
    }
    ts[threadIdx.x] = s;
    __syncthreads();
    for (int off = 1; off < 256; off <<= 1) {
        int t = (threadIdx.x >= off) ? ts[threadIdx.x - off] : 0;
        __syncthreads();
        ts[threadIdx.x] += t;
        __syncthreads();
    }
    int run = ts[threadIdx.x] - s;
    if (threadIdx.x == 255) bsum[blockIdx.x] = ts[255];
#pragma unroll
    for (int j = 0; j < 8; j++) {
        int idx = base + j;
        if (idx < SCAN_N) out[idx] = run;
        run += v[j];
    }
}

__global__ void scan2(int* bsum, int n) {
    __shared__ int ts[512];
    int v = (threadIdx.x < n) ? bsum[threadIdx.x] : 0;
    ts[threadIdx.x] = v;
    __syncthreads();
    for (int off = 1; off < 512; off <<= 1) {
        int t = (threadIdx.x >= off) ? ts[threadIdx.x - off] : 0;
        __syncthreads();
        ts[threadIdx.x] += t;
        __syncthreads();
    }
    if (threadIdx.x < n) bsum[threadIdx.x] = ts[threadIdx.x] - v;
}

__global__ void scan3(int* out, const int* __restrict__ bsum) {
    int idx = blockIdx.x * blockDim.x + threadIdx.x;
    if (idx < SCAN_N) out[idx] += bsum[idx >> 11];
}

__global__ void scatter_k(const int* __restrict__ edge, int ne, const int* __restrict__ offs,
                          int* __restrict__ cur, int* __restrict__ sorted) {
    int i = blockIdx.x * blockDim.x + threadIdx.x;
    if (i < ne) {
        int s = edge[i], d = edge[ne + i];
        int pos = offs[d] + atomicAdd(&cur[d], 1);
        sorted[pos] = s;
    }
}

// ------ fused per-layer weight [layer][o][k(416)] with hist-encoder fold -----
__global__ void build_w(const float* __restrict__ sWl, const float* __restrict__ sWr,
                        const float* __restrict__ sb, const float* __restrict__ Wh,
                        const float* __restrict__ bh, __half* __restrict__ Wbh,
                        float* __restrict__ bS) {
    int i = blockIdx.x * blockDim.x + threadIdx.x;
    if (i >= 2 * HD * KTOT) return;
    int l = i / (HD * KTOT);
    int rem = i - l * HD * KTOT;
    int o = rem / KTOT;
    int k = rem - o * KTOT;
    float v;
    if (k < 256) {
        int part = k >> 7, kk = k & 127;
        v = sWl[(((size_t)(l * 3 + part)) * HD + o) * HD + kk];
    } else if (k < 282) {
        int c = k - 256;
        float s = 0.f;
        const float* wl = sWl + ((size_t)(l * 3 + 2) * HD + o) * HD;
        for (int j = 0; j < HD; j++) s += wl[j] * Wh[j * 26 + c];
        v = s;
    } else if (k == 282) {
        float s = 0.f;
        const float* wl = sWl + ((size_t)(l * 3 + 2) * HD + o) * HD;
        for (int j = 0; j < HD; j++) s += wl[j] * bh[j];
        v = s;
    } else if (k < 288) {
        v = 0.f;
    } else {
        int kk = k - 288;
        v = sWr[(((size_t)(l * 3 + 0)) * HD + o) * HD + kk] +
            sWr[(((size_t)(l * 3 + 1)) * HD + o) * HD + kk] +
            sWr[(((size_t)(l * 3 + 2)) * HD + o) * HD + kk];
    }
    Wbh[i] = __float2half(v);
    if (i < 2 * HD) {
        int l2 = i >> 7, o2 = i & 127;
        bS[i] = sb[(l2 * 3 + 0) * HD + o2] + sb[(l2 * 3 + 1) * HD + o2] +
                sb[(l2 * 3 + 2) * HD + o2];
    }
}

// --------------------------- player encoder ----------------------------------
__global__ __launch_bounds__(128) void enc_p(const float* __restrict__ xp,
                                             const float* __restrict__ embp,
                                             const float* __restrict__ Wp,
                                             const float* __restrict__ bp,
                                             __half* __restrict__ out) {
    __shared__ float f[8][85];
    int r0 = blockIdx.x * 8;
    int tid = threadIdx.x;
    for (int idx = tid; idx < 8 * 85; idx += 128) {
        int r = idx / 85, k = idx - r * 85;
        const float* x = xp + (size_t)(r0 + r) * 10;
        float v;
        if (k < 5) {
            v = x[k == 0 ? 0 : k + 5];
        } else {
            int j = (k - 5) >> 4, e = (k - 5) & 15;
            int ci = (int)x[1 + j];
            ci = min(max(ci, 0), 199);
            v = embp[((size_t)j * 200 + ci) * 16 + e];
        }
        f[r][k] = v;
    }
    __syncthreads();
    float acc[8];
#pragma unroll
    for (int r = 0; r < 8; r++) acc[r] = bp[tid];
    const float* w = Wp + tid * 85;
    for (int k = 0; k < 85; k++) {
        float wk = __ldg(w + k);
#pragma unroll
        for (int r = 0; r < 8; r++) acc[r] += f[r][k] * wk;
    }
#pragma unroll
    for (int r = 0; r < 8; r++) out[(size_t)(r0 + r) * HD + tid] = __float2half(acc[r]);
}

// -------------- raw hist concat (26 dims, padded to 32 halfs) ----------------
__global__ __launch_bounds__(256) void build_hcat(const float* __restrict__ xh,
                                                  const float* __restrict__ e0,
                                                  const float* __restrict__ e3,
                                                  __half* __restrict__ Hc) {
    int r = blockIdx.x * blockDim.x + threadIdx.x;
    if (r >= NH) return;
    const float* x = xh + (size_t)r * 8;
    float f[32];
    f[0] = x[1]; f[1] = x[2]; f[2] = x[4]; f[3] = x[5]; f[4] = x[6]; f[5] = x[7];
    int c0 = min(max((int)x[0], 0), 1999);
    int c3 = min(max((int)x[3], 0), 9);
#pragma unroll
    for (int j = 0; j < 16; j++) f[6 + j] = e0[c0 * 16 + j];
#pragma unroll
    for (int j = 0; j < 4; j++) f[22 + j] = e3[c3 * 4 + j];
#pragma unroll
    for (int j = 26; j < 32; j++) f[j] = 0.f;
    __half h[32];
#pragma unroll
    for (int j = 0; j < 32; j++) h[j] = __float2half(f[j]);
#pragma unroll
    for (int q = 0; q < 4; q++)
        *(uint4*)(Hc + (size_t)r * HCW + q * 8) = *(uint4*)&h[q * 8];
}

// ------------- hist gather: half-warp per node -> X[node][256..287] ----------
__global__ __launch_bounds__(256) void agg_h(const __half* __restrict__ Hc,
                                             const int* __restrict__ sorted,
                                             const int* __restrict__ offs,
                                             const int* __restrict__ cnt,
                                             __half* __restrict__ X) {
    int hw = (blockIdx.x * blockDim.x + threadIdx.x) >> 4;
    int lane = threadIdx.x & 15;
    if (hw >= NP) return;
    int start = offs[hw], c = cnt[hw];
    float2 a = make_float2(0.f, 0.f);
    for (int e = 0; e < c; e++) {
        int s = __ldg(sorted + start + e);
        unsigned int v = __ldg((const unsigned int*)(Hc + (size_t)s * HCW + lane * 2));
        float2 f = __half22float2(*(__half2*)&v);
        a.x += f.x; a.y += f.y;
    }
    float inv = 1.0f / fmaxf((float)c, 1.0f);
    int col = lane * 2;
    float v0 = a.x * inv, v1 = a.y * inv;
    if (col == 26) { v0 = (c > 0) ? 1.f : 0.f; v1 = 0.f; }
    else if (col > 26) { v0 = 0.f; v1 = 0.f; }
    __half2 o = __floats2half2_rn(v0, v1);
    *(__half2*)(X + (size_t)hw * XW + 256 + col) = o;
}

// ------------- t/e gather: HALF-WARP per (node, type), uint4 lanes -----------
__device__ __forceinline__ void acc8(float* a, uint4 v) {
    float2 f;
    f = __half22float2(*(__half2*)&v.x); a[0] += f.x; a[1] += f.y;
    f = __half22float2(*(__half2*)&v.y); a[2] += f.x; a[3] += f.y;
    f = __half22float2(*(__half2*)&v.z); a[4] += f.x; a[5] += f.y;
    f = __half22float2(*(__half2*)&v.w); a[6] += f.x; a[7] += f.y;
}

__global__ __launch_bounds__(256) void agg_te(const __half* __restrict__ P,
                                              const int* __restrict__ sorted,
                                              const int* __restrict__ offs,
                                              const int* __restrict__ cnt,
                                              __half* __restrict__ X) {
    int g = blockIdx.x * blockDim.x + threadIdx.x;
    int hw = g >> 4;                 // half-warp id
    int lane = threadIdx.x & 15;     // lane within half-warp
    int hbase = threadIdx.x & 16;    // 0 or 16
    unsigned int mask = 0xFFFFu << hbase;
    int node = hw >> 1;
    int type = hw & 1;
    if (node >= NP) return;
    int start = offs[type * NP + node];
    int c = cnt[type * NP + node];
    float a[8] = {0.f, 0.f, 0.f, 0.f, 0.f, 0.f, 0.f, 0.f};
    for (int e0 = 0; e0 < c; e0 += 16) {
        int my = (e0 + lane < c) ? sorted[start + e0 + lane] : 0;
        int n = min(16, c - e0);
        int e = 0;
        for (; e + 4 <= n; e += 4) {
            int s0 = __shfl_sync(mask, my, hbase + e);
            int s1 = __shfl_sync(mask, my, hbase + e + 1);
            int s2 = __shfl_sync(mask, my, hbase + e + 2);
            int s3 = __shfl_sync(mask, my, hbase + e + 3);
            uint4 v0 = __ldg((const uint4*)(P + (size_t)s0 * HD + lane * 8));
            uint4 v1 = __ldg((const uint4*)(P + (size_t)s1 * HD + lane * 8));
            uint4 v2 = __ldg((const uint4*)(P + (size_t)s2 * HD + lane * 8));
            uint4 v3 = __ldg((const uint4*)(P + (size_t)s3 * HD + lane * 8));
            acc8(a, v0); acc8(a, v1); acc8(a, v2); acc8(a, v3);
        }
        for (; e < n; e++) {
            int s = __shfl_sync(mask, my, hbase + e);
            uint4 v = __ldg((const uint4*)(P + (size_t)s * HD + lane * 8));
            acc8(a, v);
        }
    }
    float inv = 1.0f / fmaxf((float)c, 1.0f);
    __half2 h0 = __floats2half2_rn(a[0] * inv, a[1] * inv);
    __half2 h1 = __floats2half2_rn(a[2] * inv, a[3] * inv);
    __half2 h2 = __floats2half2_rn(a[4] * inv, a[5] * inv);
    __half2 h3 = __floats2half2_rn(a[6] * inv, a[7] * inv);
    uint4 ov;
    ov.x = *(unsigned int*)&h0; ov.y = *(unsigned int*)&h1;
    ov.z = *(unsigned int*)&h2; ov.w = *(unsigned int*)&h3;
    *(uint4*)(X + (size_t)node * XW + type * 128 + lane * 8) = ov;
}

// ------------------------------- cp.async ------------------------------------
__device__ __forceinline__ void cp16(void* smem, const void* gmem) {
    unsigned int s = (unsigned int)__cvta_generic_to_shared(smem);
    asm volatile("cp.async.cg.shared.global [%0], [%1], 16;" :: "r"(s), "l"(gmem));
}
__device__ __forceinline__ void cp_commit() { asm volatile("cp.async.commit_group;"); }
template <int N>
__device__ __forceinline__ void cp_wait() {
    asm volatile("cp.async.wait_group %0;" :: "n"(N));
}

// ------------------------------- fp16 MMA ------------------------------------
__device__ __forceinline__ void mma_f16(float* c, const unsigned int* a, const unsigned int* b) {
    asm volatile(
        "mma.sync.aligned.m16n8k16.row.col.f32.f16.f16.f32 "
        "{%0,%1,%2,%3}, {%4,%5,%6,%7}, {%8,%9}, {%0,%1,%2,%3};"
        : "+f"(c[0]), "+f"(c[1]), "+f"(c[2]), "+f"(c[3])
        : "r"(a[0]), "r"(a[1]), "r"(a[2]), "r"(a[3]), "r"(b[0]), "r"(b[1]));
}

// C(128x128 per block) = relu([X | P](row,416) @ Wbh[o][k].T + bS)
// Double-buffered cp.async pipeline over 13 K-chunks.
__global__ __launch_bounds__(256) void sage_mma(const __half* __restrict__ X,
                                                const __half* __restrict__ P,
                                                const __half* __restrict__ Wbh,
                                                const float* __restrict__ bS,
                                                __half* __restrict__ out,
                                                const int* __restrict__ batch,
                                                const float* __restrict__ Wc,
                                                float* __restrict__ pool_out,
                                                int do_pool) {
    __shared__ __half As[2][128 * ASW];
    __shared__ __half Bs[2][128 * ASW];
    int tid = threadIdx.x, wid = tid >> 5, lane = tid & 31;
    int gr = lane >> 2, tg = lane & 3;
    int rowBase = blockIdx.x * 128;
    int wm = (wid >> 1) * 32, wn = (wid & 1) * 64;

    // per-thread load coords
    int lr = tid >> 2;            // 0..63 (x2 via +64)
    int lc8 = (tid & 3) * 8;

    auto issue = [&](int kc, int buf) {
#pragma unroll
        for (int t = 0; t < 2; t++) {
            int r = lr + t * 64;
            int row = min(rowBase + r, NP - 1);
            const __half* sp = (kc < XW) ? (X + (size_t)row * XW + kc + lc8)
                                         : (P + (size_t)row * HD + (kc - XW) + lc8);
            cp16(&As[buf][r * ASW + lc8], sp);
            cp16(&Bs[buf][r * ASW + lc8], Wbh + (size_t)r * KTOT + kc + lc8);
        }
    };

    float acc[2][8][4];
#pragma unroll
    for (int i = 0; i < 2; i++)
#pragma unroll
        for (int j = 0; j < 8; j++)
#pragma unroll
            for (int k = 0; k < 4; k++) acc[i][j][k] = 0.f;

    const int NC = KTOT / 32;  // 13
    issue(0, 0);
    cp_commit();
    for (int i = 0; i < NC; i++) {
        if (i + 1 < NC) {
            issue((i + 1) * 32, (i + 1) & 1);
            cp_commit();
            cp_wait<1>();
        } else {
            cp_wait<0>();
        }
        __syncthreads();
        const __half* Ab = As[i & 1];
        const __half* Bb = Bs[i & 1];
#pragma unroll
        for (int ks = 0; ks < 2; ks++) {
            int k0 = ks * 16;
            unsigned int a[2][4];
#pragma unroll
            for (int mt = 0; mt < 2; mt++) {
                int r = wm + mt * 16 + gr;
                a[mt][0] = *(const unsigned int*)&Ab[r * ASW + k0 + 2 * tg];
                a[mt][1] = *(const unsigned int*)&Ab[(r + 8) * ASW + k0 + 2 * tg];
                a[mt][2] = *(const unsigned int*)&Ab[r * ASW + k0 + 2 * tg + 8];
                a[mt][3] = *(const unsigned int*)&Ab[(r + 8) * ASW + k0 + 2 * tg + 8];
            }
#pragma unroll
            for (int nt = 0; nt < 8; nt++) {
                int n = wn + nt * 8 + gr;
                unsigned int b[2];
                b[0] = *(const unsigned int*)&Bb[n * ASW + k0 + 2 * tg];
                b[1] = *(const unsigned int*)&Bb[n * ASW + k0 + 2 * tg + 8];
                mma_f16(acc[0][nt], a[0], b);
                mma_f16(acc[1][nt], a[1], b);
            }
        }
        __syncthreads();
    }

    if (do_pool) {
        float ps[4] = {0.f, 0.f, 0.f, 0.f};
#pragma unroll
        for (int mt = 0; mt < 2; mt++)
#pragma unroll
            for (int nt = 0; nt < 8; nt++) {
                int col = wn + nt * 8 + 2 * tg;
                float w0 = Wc[col], w1 = Wc[col + 1];
                float b0 = bS[col], b1 = bS[col + 1];
                ps[mt * 2 + 0] += fmaxf(acc[mt][nt][0] + b0, 0.f) * w0 +
                                  fmaxf(acc[mt][nt][1] + b1, 0.f) * w1;
                ps[mt * 2 + 1] += fmaxf(acc[mt][nt][2] + b0, 0.f) * w0 +
                                  fmaxf(acc[mt][nt][3] + b1, 0.f) * w1;
            }
#pragma unroll
        for (int j = 0; j < 4; j++) {
            ps[j] += __shfl_xor_sync(0xFFFFFFFFu, ps[j], 1);
            ps[j] += __shfl_xor_sync(0xFFFFFFFFu, ps[j], 2);
        }
        if (tg == 0) {
#pragma unroll
            for (int mt = 0; mt < 2; mt++) {
                int r0 = rowBase + wm + mt * 16 + gr;
                int r1 = r0 + 8;
                if (r0 < NP) atomicAdd(&pool_out[batch[r0]], ps[mt * 2]);
                if (r1 < NP) atomicAdd(&pool_out[batch[r1]], ps[mt * 2 + 1]);
            }
        }
    } else {
#pragma unroll
        for (int mt = 0; mt < 2; mt++) {
#pragma unroll
            for (int nt = 0; nt < 8; nt++) {
                int col = wn + nt * 8 + 2 * tg;
                float b0 = bS[col], b1 = bS[col + 1];
                int r0 = rowBase + wm + mt * 16 + gr;
                if (r0 < NP) {
                    __half2 v = __floats2half2_rn(fmaxf(acc[mt][nt][0] + b0, 0.f),
                                                  fmaxf(acc[mt][nt][1] + b1, 0.f));
                    *(__half2*)(out + (size_t)r0 * HD + col) = v;
                }
                int r1 = r0 + 8;
                if (r1 < NP) {
                    __half2 v = __floats2half2_rn(fmaxf(acc[mt][nt][2] + b0, 0.f),
                                                  fmaxf(acc[mt][nt][3] + b1, 0.f));
                    *(__half2*)(out + (size_t)r1 * HD + col) = v;
                }
            }
        }
    }
}

__global__ void fin_k(float* out, const float* gc, const float* __restrict__ bc) {
    int g = blockIdx.x * blockDim.x + threadIdx.x;
    if (g < NG) out[g] = out[g] / fmaxf(gc[g], 1.0f) + bc[0];
}

// -------------------------------- launcher -----------------------------------
extern "C" void kernel_launch(void* const* d_in, const int* in_sizes, int n_in,
                              void* d_out, int out_size) {
    const float* x_player = (const float*)d_in[0];
    const float* x_hist   = (const float*)d_in[1];
    const int*   e_t      = (const int*)d_in[2];
    const int*   e_e      = (const int*)d_in[3];
    const int*   e_h      = (const int*)d_in[4];
    const int*   batch    = (const int*)d_in[5];
    const float* emb_p    = (const float*)d_in[6];
    const float* emb_h0   = (const float*)d_in[7];
    const float* emb_h3   = (const float*)d_in[8];
    const float* Wp       = (const float*)d_in[9];
    const float* bp       = (const float*)d_in[10];
    const float* Wh       = (const float*)d_in[11];
    const float* bh       = (const float*)d_in[12];
    const float* sWl      = (const float*)d_in[13];
    const float* sb       = (const float*)d_in[14];
    const float* sWr      = (const float*)d_in[15];
    const float* Wc       = (const float*)d_in[16];
    const float* bc       = (const float*)d_in[17];
    float* out = (float*)d_out;

    __half *P0, *P1, *Hc, *X, *Wbh;
    float *bS, *GC;
    int *cnt, *cur, *offs, *bsum, *sorted;
    cudaGetSymbolAddress((void**)&P0, g_P0);
    cudaGetSymbolAddress((void**)&P1, g_P1);
    cudaGetSymbolAddress((void**)&Hc, g_Hc);
    cudaGetSymbolAddress((void**)&X, g_X);
    cudaGetSymbolAddress((void**)&Wbh, g_Wbh);
    cudaGetSymbolAddress((void**)&bS, g_bSum);
    cudaGetSymbolAddress((void**)&GC, g_GC);
    cudaGetSymbolAddress((void**)&cnt, g_cnt);
    cudaGetSymbolAddress((void**)&cur, g_cur);
    cudaGetSymbolAddress((void**)&offs, g_offs);
    cudaGetSymbolAddress((void**)&bsum, g_bsum);
    cudaGetSymbolAddress((void**)&sorted, g_sorted);

    // ---- CSR build ----
    zero_buf<<<512, 256>>>((float*)cnt, SCAN_N);
    zero_buf<<<512, 256>>>((float*)cur, SCAN_N);
    counti_k<<<(NE_T + 255) / 256, 256>>>(e_t, NE_T, cnt);
    counti_k<<<(NE_E + 255) / 256, 256>>>(e_e, NE_E, cnt + NP);
    counti_k<<<(NE_H + 255) / 256, 256>>>(e_h, NE_H, cnt + 2 * NP);
    scan1<<<SCAN_BLOCKS, 256>>>(cnt, offs, bsum);
    scan2<<<1, 512>>>(bsum, SCAN_BLOCKS);
    scan3<<<(SCAN_N + 255) / 256, 256>>>(offs, bsum);
    scatter_k<<<(NE_T + 255) / 256, 256>>>(e_t, NE_T, offs, cur, sorted);
    scatter_k<<<(NE_E + 255) / 256, 256>>>(e_e, NE_E, offs + NP, cur + NP, sorted);
    scatter_k<<<(NE_H + 255) / 256, 256>>>(e_h, NE_H, offs + 2 * NP, cur + 2 * NP, sorted);

    // ---- weights + encoders ----
    build_w<<<(2 * HD * KTOT + 255) / 256, 256>>>(sWl, sWr, sb, Wh, bh, Wbh, bS);
    enc_p<<<NP / 8, 128>>>(x_player, emb_p, Wp, bp, P0);
    build_hcat<<<(NH + 255) / 256, 256>>>(x_hist, emb_h0, emb_h3, Hc);

    // ---- hist aggregation (layer-invariant) -> X cols 256..287 ----
    agg_h<<<NP / 16, 256>>>(Hc, sorted, offs + 2 * NP, cnt + 2 * NP, X);

    int teBlocks = (NP * 2 * 16) / 256;  // half-warp per (node,type)
    int mmaBlocks = (NP + 127) / 128;

    // ---- layer 0 ----
    agg_te<<<teBlocks, 256>>>(P0, sorted, offs, cnt, X);
    sage_mma<<<mmaBlocks, 256>>>(X, P0, Wbh, bS, P1, batch, Wc, out, 0);

    // ---- layer 1 (pool fused into epilogue) ----
    zero_buf<<<(NG + 255) / 256, 256>>>(out, NG);
    zero_buf<<<(NG + 255) / 256, 256>>>(GC, NG);
    gcount_k<<<(NP + 255) / 256, 256>>>(batch, GC);
    agg_te<<<teBlocks, 256>>>(P1, sorted, offs, cnt, X);
    sage_mma<<<mmaBlocks, 256>>>(X, P1, Wbh + (size_t)HD * KTOT, bS + HD, P0,
                                 batch, Wc, out, 1);

    fin_k<<<(NG + 255) / 256, 256>>>(out, GC, bc);
}

// round 9
// speedup vs baseline: 1.2449x; 1.0132x over previous
#include <cuda_runtime.h>
#include <cuda_fp16.h>
#include <cstdint>

#define NP 200000
#define NH 500000
#define NG 20000
#define NE_T 800000
#define NE_E 1000000
#define NE_H 500000
#define NE_ALL (NE_T + NE_E + NE_H)
#define HD 128
#define XW 288              // X row: [aggT 128 | aggE 128 | aggH26 | flag | pad5]
#define KTOT 416            // 288 + 128 (P)
#define HCW 32              // Hcat padded row width (26 -> 32)
#define ASW 40              // smem stage row stride (halfs)
#define SCAN_N (3 * NP)
#define SCAN_BLOCKS ((SCAN_N + 2047) / 2048)

// -------- static scratch (no allocations anywhere) --------
__device__ __half g_P0[(size_t)NP * HD];
__device__ __half g_P1[(size_t)NP * HD];
__device__ __half g_Hc[(size_t)NH * HCW];
__device__ __half g_X[(size_t)NP * XW];
__device__ __half g_Wbh[2 * HD * KTOT];
__device__ float g_bSum[2 * HD];
__device__ float g_GC[NG];
__device__ int g_cnt[SCAN_N];
__device__ int g_cur[SCAN_N];
__device__ int g_offs[SCAN_N];
__device__ int g_bsum[SCAN_BLOCKS];
__device__ int g_sorted[NE_ALL];

// ------------------------------- utility ------------------------------------
__global__ void zero_buf(float* p, size_t n) {
    for (size_t i = (size_t)blockIdx.x * blockDim.x + threadIdx.x; i < n;
         i += (size_t)gridDim.x * blockDim.x)
        p[i] = 0.0f;
}

__global__ void zero2_k(int* a, int* b, int n) {
    int i = blockIdx.x * blockDim.x + threadIdx.x;
    if (i < n) { a[i] = 0; b[i] = 0; }
}

__global__ void count_all(const int* __restrict__ e_t, const int* __restrict__ e_e,
                          const int* __restrict__ e_h, int* __restrict__ cnt) {
    int i = blockIdx.x * blockDim.x + threadIdx.x;
    if (i < NE_T) {
        atomicAdd(&cnt[e_t[NE_T + i]], 1);
    } else if (i < NE_T + NE_E) {
        int j = i - NE_T;
        atomicAdd(&cnt[NP + e_e[NE_E + j]], 1);
    } else if (i < NE_ALL) {
        int j = i - NE_T - NE_E;
        atomicAdd(&cnt[2 * NP + e_h[NE_H + j]], 1);
    }
}

__global__ void scatter_all(const int* __restrict__ e_t, const int* __restrict__ e_e,
                            const int* __restrict__ e_h, const int* __restrict__ offs,
                            int* __restrict__ cur, int* __restrict__ sorted) {
    int i = blockIdx.x * blockDim.x + threadIdx.x;
    int s, d;
    if (i < NE_T) {
        s = e_t[i]; d = e_t[NE_T + i];
    } else if (i < NE_T + NE_E) {
        int j = i - NE_T;
        s = e_e[j]; d = NP + e_e[NE_E + j];
    } else if (i < NE_ALL) {
        int j = i - NE_T - NE_E;
        s = e_h[j]; d = 2 * NP + e_h[NE_H + j];
    } else return;
    int pos = offs[d] + atomicAdd(&cur[d], 1);
    sorted[pos] = s;
}

__global__ void gcount_k(const int* __restrict__ batch, float* __restrict__ gc) {
    int i = blockIdx.x * blockDim.x + threadIdx.x;
    if (i < NP) atomicAdd(&gc[batch[i]], 1.0f);
}

// ------------------------------- scan (exclusive) ----------------------------
__global__ void scan1(const int* __restrict__ in, int* __restrict__ out, int* __restrict__ bsum) {
    __shared__ int ts[256];
    int base = blockIdx.x * 2048 + threadIdx.x * 8;
    int v[8];
    int s = 0;
#pragma unroll
    for (int j = 0; j < 8; j++) {
        int idx = base + j;
        v[j] = (idx < SCAN_N) ? in[idx] : 0;
        s += v[j];
    }
    ts[threadIdx.x] = s;
    __syncthreads();
    for (int off = 1; off < 256; off <<= 1) {
        int t = (threadIdx.x >= off) ? ts[threadIdx.x - off] : 0;
        __syncthreads();
        ts[threadIdx.x] += t;
        __syncthreads();
    }
    int run = ts[threadIdx.x] - s;
    if (threadIdx.x == 255) bsum[blockIdx.x] = ts[255];
#pragma unroll
    for (int j = 0; j < 8; j++) {
        int idx = base + j;
        if (idx < SCAN_N) out[idx] = run;
        run += v[j];
    }
}

__global__ void scan2(int* bsum, int n) {
    __shared__ int ts[512];
    int v = (threadIdx.x < n) ? bsum[threadIdx.x] : 0;
    ts[threadIdx.x] = v;
    __syncthreads();
    for (int off = 1; off < 512; off <<= 1) {
        int t = (threadIdx.x >= off) ? ts[threadIdx.x - off] : 0;
        __syncthreads();
        ts[threadIdx.x] += t;
        __syncthreads();
    }
    if (threadIdx.x < n) bsum[threadIdx.x] = ts[threadIdx.x] - v;
}

__global__ void scan3(int* out, const int* __restrict__ bsum) {
    int idx = blockIdx.x * blockDim.x + threadIdx.x;
    if (idx < SCAN_N) out[idx] += bsum[idx >> 11];
}

// ------ fused per-layer weight [layer][o][k(416)] with hist-encoder fold -----
__global__ void build_w(const float* __restrict__ sWl, const float* __restrict__ sWr,
                        const float* __restrict__ sb, const float* __restrict__ Wh,
                        const float* __restrict__ bh, __half* __restrict__ Wbh,
                        float* __restrict__ bS) {
    int i = blockIdx.x * blockDim.x + threadIdx.x;
    if (i >= 2 * HD * KTOT) return;
    int l = i / (HD * KTOT);
    int rem = i - l * HD * KTOT;
    int o = rem / KTOT;
    int k = rem - o * KTOT;
    float v;
    if (k < 256) {
        int part = k >> 7, kk = k & 127;
        v = sWl[(((size_t)(l * 3 + part)) * HD + o) * HD + kk];
    } else if (k < 282) {
        int c = k - 256;
        float s = 0.f;
        const float* wl = sWl + ((size_t)(l * 3 + 2) * HD + o) * HD;
        for (int j = 0; j < HD; j++) s += wl[j] * Wh[j * 26 + c];
        v = s;
    } else if (k == 282) {
        float s = 0.f;
        const float* wl = sWl + ((size_t)(l * 3 + 2) * HD + o) * HD;
        for (int j = 0; j < HD; j++) s += wl[j] * bh[j];
        v = s;
    } else if (k < 288) {
        v = 0.f;
    } else {
        int kk = k - 288;
        v = sWr[(((size_t)(l * 3 + 0)) * HD + o) * HD + kk] +
            sWr[(((size_t)(l * 3 + 1)) * HD + o) * HD + kk] +
            sWr[(((size_t)(l * 3 + 2)) * HD + o) * HD + kk];
    }
    Wbh[i] = __float2half(v);
    if (i < 2 * HD) {
        int l2 = i >> 7, o2 = i & 127;
        bS[i] = sb[(l2 * 3 + 0) * HD + o2] + sb[(l2 * 3 + 1) * HD + o2] +
                sb[(l2 * 3 + 2) * HD + o2];
    }
}

// --------------------------- player encoder ----------------------------------
__global__ __launch_bounds__(128) void enc_p(const float* __restrict__ xp,
                                             const float* __restrict__ embp,
                                             const float* __restrict__ Wp,
                                             const float* __restrict__ bp,
                                             __half* __restrict__ out) {
    __shared__ float f[8][85];
    int r0 = blockIdx.x * 8;
    int tid = threadIdx.x;
    for (int idx = tid; idx < 8 * 85; idx += 128) {
        int r = idx / 85, k = idx - r * 85;
        const float* x = xp + (size_t)(r0 + r) * 10;
        float v;
        if (k < 5) {
            v = x[k == 0 ? 0 : k + 5];
        } else {
            int j = (k - 5) >> 4, e = (k - 5) & 15;
            int ci = (int)x[1 + j];
            ci = min(max(ci, 0), 199);
            v = embp[((size_t)j * 200 + ci) * 16 + e];
        }
        f[r][k] = v;
    }
    __syncthreads();
    float acc[8];
#pragma unroll
    for (int r = 0; r < 8; r++) acc[r] = bp[tid];
    const float* w = Wp + tid * 85;
    for (int k = 0; k < 85; k++) {
        float wk = __ldg(w + k);
#pragma unroll
        for (int r = 0; r < 8; r++) acc[r] += f[r][k] * wk;
    }
#pragma unroll
    for (int r = 0; r < 8; r++) out[(size_t)(r0 + r) * HD + tid] = __float2half(acc[r]);
}

// -------------- raw hist concat (26 dims, padded to 32 halfs) ----------------
__global__ __launch_bounds__(256) void build_hcat(const float* __restrict__ xh,
                                                  const float* __restrict__ e0,
                                                  const float* __restrict__ e3,
                                                  __half* __restrict__ Hc) {
    int r = blockIdx.x * blockDim.x + threadIdx.x;
    if (r >= NH) return;
    const float* x = xh + (size_t)r * 8;
    float f[32];
    f[0] = x[1]; f[1] = x[2]; f[2] = x[4]; f[3] = x[5]; f[4] = x[6]; f[5] = x[7];
    int c0 = min(max((int)x[0], 0), 1999);
    int c3 = min(max((int)x[3], 0), 9);
#pragma unroll
    for (int j = 0; j < 16; j++) f[6 + j] = e0[c0 * 16 + j];
#pragma unroll
    for (int j = 0; j < 4; j++) f[22 + j] = e3[c3 * 4 + j];
#pragma unroll
    for (int j = 26; j < 32; j++) f[j] = 0.f;
    __half h[32];
#pragma unroll
    for (int j = 0; j < 32; j++) h[j] = __float2half(f[j]);
#pragma unroll
    for (int q = 0; q < 4; q++)
        *(uint4*)(Hc + (size_t)r * HCW + q * 8) = *(uint4*)&h[q * 8];
}

// ------------- hist gather: half-warp per node -> X[node][256..287] ----------
__global__ __launch_bounds__(256) void agg_h(const __half* __restrict__ Hc,
                                             const int* __restrict__ sorted,
                                             const int* __restrict__ offs,
                                             const int* __restrict__ cnt,
                                             __half* __restrict__ X) {
    int hw = (blockIdx.x * blockDim.x + threadIdx.x) >> 4;
    int lane = threadIdx.x & 15;
    if (hw >= NP) return;
    int start = offs[hw], c = cnt[hw];
    float2 a = make_float2(0.f, 0.f);
    for (int e = 0; e < c; e++) {
        int s = __ldg(sorted + start + e);
        unsigned int v = __ldg((const unsigned int*)(Hc + (size_t)s * HCW + lane * 2));
        float2 f = __half22float2(*(__half2*)&v);
        a.x += f.x; a.y += f.y;
    }
    float inv = 1.0f / fmaxf((float)c, 1.0f);
    int col = lane * 2;
    float v0 = a.x * inv, v1 = a.y * inv;
    if (col == 26) { v0 = (c > 0) ? 1.f : 0.f; v1 = 0.f; }
    else if (col > 26) { v0 = 0.f; v1 = 0.f; }
    __half2 o = __floats2half2_rn(v0, v1);
    *(__half2*)(X + (size_t)hw * XW + 256 + col) = o;
}

// ------------- t/e gather: HALF-WARP per (node, type), uint4 lanes -----------
__device__ __forceinline__ void acc8(float* a, uint4 v) {
    float2 f;
    f = __half22float2(*(__half2*)&v.x); a[0] += f.x; a[1] += f.y;
    f = __half22float2(*(__half2*)&v.y); a[2] += f.x; a[3] += f.y;
    f = __half22float2(*(__half2*)&v.z); a[4] += f.x; a[5] += f.y;
    f = __half22float2(*(__half2*)&v.w); a[6] += f.x; a[7] += f.y;
}

__global__ __launch_bounds__(256) void agg_te(const __half* __restrict__ P,
                                              const int* __restrict__ sorted,
                                              const int* __restrict__ offs,
                                              const int* __restrict__ cnt,
                                              __half* __restrict__ X) {
    int g = blockIdx.x * blockDim.x + threadIdx.x;
    int hw = g >> 4;
    int lane = threadIdx.x & 15;
    int hbase = threadIdx.x & 16;
    unsigned int mask = 0xFFFFu << hbase;
    int node = hw >> 1;
    int type = hw & 1;
    if (node >= NP) return;
    int start = offs[type * NP + node];
    int c = cnt[type * NP + node];
    float a[8] = {0.f, 0.f, 0.f, 0.f, 0.f, 0.f, 0.f, 0.f};
    for (int e0 = 0; e0 < c; e0 += 16) {
        int my = (e0 + lane < c) ? sorted[start + e0 + lane] : 0;
        int n = min(16, c - e0);
        int e = 0;
        for (; e + 4 <= n; e += 4) {
            int s0 = __shfl_sync(mask, my, hbase + e);
            int s1 = __shfl_sync(mask, my, hbase + e + 1);
            int s2 = __shfl_sync(mask, my, hbase + e + 2);
            int s3 = __shfl_sync(mask, my, hbase + e + 3);
            uint4 v0 = __ldg((const uint4*)(P + (size_t)s0 * HD + lane * 8));
            uint4 v1 = __ldg((const uint4*)(P + (size_t)s1 * HD + lane * 8));
            uint4 v2 = __ldg((const uint4*)(P + (size_t)s2 * HD + lane * 8));
            uint4 v3 = __ldg((const uint4*)(P + (size_t)s3 * HD + lane * 8));
            acc8(a, v0); acc8(a, v1); acc8(a, v2); acc8(a, v3);
        }
        for (; e < n; e++) {
            int s = __shfl_sync(mask, my, hbase + e);
            uint4 v = __ldg((const uint4*)(P + (size_t)s * HD + lane * 8));
            acc8(a, v);
        }
    }
    float inv = 1.0f / fmaxf((float)c, 1.0f);
    __half2 h0 = __floats2half2_rn(a[0] * inv, a[1] * inv);
    __half2 h1 = __floats2half2_rn(a[2] * inv, a[3] * inv);
    __half2 h2 = __floats2half2_rn(a[4] * inv, a[5] * inv);
    __half2 h3 = __floats2half2_rn(a[6] * inv, a[7] * inv);
    uint4 ov;
    ov.x = *(unsigned int*)&h0; ov.y = *(unsigned int*)&h1;
    ov.z = *(unsigned int*)&h2; ov.w = *(unsigned int*)&h3;
    *(uint4*)(X + (size_t)node * XW + type * 128 + lane * 8) = ov;
}

// ------------------------------- cp.async ------------------------------------
__device__ __forceinline__ void cp16(void* smem, const void* gmem) {
    unsigned int s = (unsigned int)__cvta_generic_to_shared(smem);
    asm volatile("cp.async.cg.shared.global [%0], [%1], 16;" :: "r"(s), "l"(gmem));
}
__device__ __forceinline__ void cp_commit() { asm volatile("cp.async.commit_group;"); }
template <int N>
__device__ __forceinline__ void cp_wait() {
    asm volatile("cp.async.wait_group %0;" :: "n"(N));
}

// ------------------------------- fp16 MMA ------------------------------------
__device__ __forceinline__ void mma_f16(float* c, const unsigned int* a, const unsigned int* b) {
    asm volatile(
        "mma.sync.aligned.m16n8k16.row.col.f32.f16.f16.f32 "
        "{%0,%1,%2,%3}, {%4,%5,%6,%7}, {%8,%9}, {%0,%1,%2,%3};"
        : "+f"(c[0]), "+f"(c[1]), "+f"(c[2]), "+f"(c[3])
        : "r"(a[0]), "r"(a[1]), "r"(a[2]), "r"(a[3]), "r"(b[0]), "r"(b[1]));
}

__global__ __launch_bounds__(256) void sage_mma(const __half* __restrict__ X,
                                                const __half* __restrict__ P,
                                                const __half* __restrict__ Wbh,
                                                const float* __restrict__ bS,
                                                __half* __restrict__ out,
                                                const int* __restrict__ batch,
                                                const float* __restrict__ Wc,
                                                float* __restrict__ pool_out,
                                                int do_pool) {
    __shared__ __half As[2][128 * ASW];
    __shared__ __half Bs[2][128 * ASW];
    int tid = threadIdx.x, wid = tid >> 5, lane = tid & 31;
    int gr = lane >> 2, tg = lane & 3;
    int rowBase = blockIdx.x * 128;
    int wm = (wid >> 1) * 32, wn = (wid & 1) * 64;

    int lr = tid >> 2;
    int lc8 = (tid & 3) * 8;

    auto issue = [&](int kc, int buf) {
#pragma unroll
        for (int t = 0; t < 2; t++) {
            int r = lr + t * 64;
            int row = min(rowBase + r, NP - 1);
            const __half* sp = (kc < XW) ? (X + (size_t)row * XW + kc + lc8)
                                         : (P + (size_t)row * HD + (kc - XW) + lc8);
            cp16(&As[buf][r * ASW + lc8], sp);
            cp16(&Bs[buf][r * ASW + lc8], Wbh + (size_t)r * KTOT + kc + lc8);
        }
    };

    float acc[2][8][4];
#pragma unroll
    for (int i = 0; i < 2; i++)
#pragma unroll
        for (int j = 0; j < 8; j++)
#pragma unroll
            for (int k = 0; k < 4; k++) acc[i][j][k] = 0.f;

    const int NC = KTOT / 32;
    issue(0, 0);
    cp_commit();
    for (int i = 0; i < NC; i++) {
        if (i + 1 < NC) {
            issue((i + 1) * 32, (i + 1) & 1);
            cp_commit();
            cp_wait<1>();
        } else {
            cp_wait<0>();
        }
        __syncthreads();
        const __half* Ab = As[i & 1];
        const __half* Bb = Bs[i & 1];
#pragma unroll
        for (int ks = 0; ks < 2; ks++) {
            int k0 = ks * 16;
            unsigned int a[2][4];
#pragma unroll
            for (int mt = 0; mt < 2; mt++) {
                int r = wm + mt * 16 + gr;
                a[mt][0] = *(const unsigned int*)&Ab[r * ASW + k0 + 2 * tg];
                a[mt][1] = *(const unsigned int*)&Ab[(r + 8) * ASW + k0 + 2 * tg];
                a[mt][2] = *(const unsigned int*)&Ab[r * ASW + k0 + 2 * tg + 8];
                a[mt][3] = *(const unsigned int*)&Ab[(r + 8) * ASW + k0 + 2 * tg + 8];
            }
#pragma unroll
            for (int nt = 0; nt < 8; nt++) {
                int n = wn + nt * 8 + gr;
                unsigned int b[2];
                b[0] = *(const unsigned int*)&Bb[n * ASW + k0 + 2 * tg];
                b[1] = *(const unsigned int*)&Bb[n * ASW + k0 + 2 * tg + 8];
                mma_f16(acc[0][nt], a[0], b);
                mma_f16(acc[1][nt], a[1], b);
            }
        }
        __syncthreads();
    }

    if (do_pool) {
        float ps[4] = {0.f, 0.f, 0.f, 0.f};
#pragma unroll
        for (int mt = 0; mt < 2; mt++)
#pragma unroll
            for (int nt = 0; nt < 8; nt++) {
                int col = wn + nt * 8 + 2 * tg;
                float w0 = Wc[col], w1 = Wc[col + 1];
                float b0 = bS[col], b1 = bS[col + 1];
                ps[mt * 2 + 0] += fmaxf(acc[mt][nt][0] + b0, 0.f) * w0 +
                                  fmaxf(acc[mt][nt][1] + b1, 0.f) * w1;
                ps[mt * 2 + 1] += fmaxf(acc[mt][nt][2] + b0, 0.f) * w0 +
                                  fmaxf(acc[mt][nt][3] + b1, 0.f) * w1;
            }
#pragma unroll
        for (int j = 0; j < 4; j++) {
            ps[j] += __shfl_xor_sync(0xFFFFFFFFu, ps[j], 1);
            ps[j] += __shfl_xor_sync(0xFFFFFFFFu, ps[j], 2);
        }
        if (tg == 0) {
#pragma unroll
            for (int mt = 0; mt < 2; mt++) {
                int r0 = rowBase + wm + mt * 16 + gr;
                int r1 = r0 + 8;
                if (r0 < NP) atomicAdd(&pool_out[batch[r0]], ps[mt * 2]);
                if (r1 < NP) atomicAdd(&pool_out[batch[r1]], ps[mt * 2 + 1]);
            }
        }
    } else {
#pragma unroll
        for (int mt = 0; mt < 2; mt++) {
#pragma unroll
            for (int nt = 0; nt < 8; nt++) {
                int col = wn + nt * 8 + 2 * tg;
                float b0 = bS[col], b1 = bS[col + 1];
                int r0 = rowBase + wm + mt * 16 + gr;
                if (r0 < NP) {
                    __half2 v = __floats2half2_rn(fmaxf(acc[mt][nt][0] + b0, 0.f),
                                                  fmaxf(acc[mt][nt][1] + b1, 0.f));
                    *(__half2*)(out + (size_t)r0 * HD + col) = v;
                }
                int r1 = r0 + 8;
                if (r1 < NP) {
                    __half2 v = __floats2half2_rn(fmaxf(acc[mt][nt][2] + b0, 0.f),
                                                  fmaxf(acc[mt][nt][3] + b1, 0.f));
                    *(__half2*)(out + (size_t)r1 * HD + col) = v;
                }
            }
        }
    }
}

__global__ void fin_k(float* out, const float* gc, const float* __restrict__ bc) {
    int g = blockIdx.x * blockDim.x + threadIdx.x;
    if (g < NG) out[g] = out[g] / fmaxf(gc[g], 1.0f) + bc[0];
}

// -------------------------------- launcher -----------------------------------
extern "C" void kernel_launch(void* const* d_in, const int* in_sizes, int n_in,
                              void* d_out, int out_size) {
    const float* x_player = (const float*)d_in[0];
    const float* x_hist   = (const float*)d_in[1];
    const int*   e_t      = (const int*)d_in[2];
    const int*   e_e      = (const int*)d_in[3];
    const int*   e_h      = (const int*)d_in[4];
    const int*   batch    = (const int*)d_in[5];
    const float* emb_p    = (const float*)d_in[6];
    const float* emb_h0   = (const float*)d_in[7];
    const float* emb_h3   = (const float*)d_in[8];
    const float* Wp       = (const float*)d_in[9];
    const float* bp       = (const float*)d_in[10];
    const float* Wh       = (const float*)d_in[11];
    const float* bh       = (const float*)d_in[12];
    const float* sWl      = (const float*)d_in[13];
    const float* sb       = (const float*)d_in[14];
    const float* sWr      = (const float*)d_in[15];
    const float* Wc       = (const float*)d_in[16];
    const float* bc       = (const float*)d_in[17];
    float* out = (float*)d_out;

    __half *P0, *P1, *Hc, *X, *Wbh;
    float *bS, *GC;
    int *cnt, *cur, *offs, *bsum, *sorted;
    cudaGetSymbolAddress((void**)&P0, g_P0);
    cudaGetSymbolAddress((void**)&P1, g_P1);
    cudaGetSymbolAddress((void**)&Hc, g_Hc);
    cudaGetSymbolAddress((void**)&X, g_X);
    cudaGetSymbolAddress((void**)&Wbh, g_Wbh);
    cudaGetSymbolAddress((void**)&bS, g_bSum);
    cudaGetSymbolAddress((void**)&GC, g_GC);
    cudaGetSymbolAddress((void**)&cnt, g_cnt);
    cudaGetSymbolAddress((void**)&cur, g_cur);
    cudaGetSymbolAddress((void**)&offs, g_offs);
    cudaGetSymbolAddress((void**)&bsum, g_bsum);
    cudaGetSymbolAddress((void**)&sorted, g_sorted);

    // ---- CSR build (fused: 6 launches) ----
    zero2_k<<<(SCAN_N + 255) / 256, 256>>>(cnt, cur, SCAN_N);
    count_all<<<(NE_ALL + 255) / 256, 256>>>(e_t, e_e, e_h, cnt);
    scan1<<<SCAN_BLOCKS, 256>>>(cnt, offs, bsum);
    scan2<<<1, 512>>>(bsum, SCAN_BLOCKS);
    scan3<<<(SCAN_N + 255) / 256, 256>>>(offs, bsum);
    scatter_all<<<(NE_ALL + 255) / 256, 256>>>(e_t, e_e, e_h, offs, cur, sorted);

    // ---- weights + encoders ----
    build_w<<<(2 * HD * KTOT + 255) / 256, 256>>>(sWl, sWr, sb, Wh, bh, Wbh, bS);
    enc_p<<<NP / 8, 128>>>(x_player, emb_p, Wp, bp, P0);
    build_hcat<<<(NH + 255) / 256, 256>>>(x_hist, emb_h0, emb_h3, Hc);

    // ---- hist aggregation (layer-invariant) -> X cols 256..287 ----
    agg_h<<<NP / 16, 256>>>(Hc, sorted, offs + 2 * NP, cnt + 2 * NP, X);

    int teBlocks = (NP * 2 * 16) / 256;
    int mmaBlocks = (NP + 127) / 128;

    // ---- layer 0 ----
    agg_te<<<teBlocks, 256>>>(P0, sorted, offs, cnt, X);
    sage_mma<<<mmaBlocks, 256>>>(X, P0, Wbh, bS, P1, batch, Wc, out, 0);

    // ---- layer 1 (pool fused into epilogue) ----
    zero_buf<<<(NG + 255) / 256, 256>>>(out, NG);
    zero_buf<<<(NG + 255) / 256, 256>>>(GC, NG);
    gcount_k<<<(NP + 255) / 256, 256>>>(batch, GC);
    agg_te<<<teBlocks, 256>>>(P1, sorted, offs, cnt, X);
    sage_mma<<<mmaBlocks, 256>>>(X, P1, Wbh + (size_t)HD * KTOT, bS + HD, P0,
                                 batch, Wc, out, 1);

    fin_k<<<(NG + 255) / 256, 256>>>(out, GC, bc);
}

// round 10
// speedup vs baseline: 1.8216x; 1.4633x over previous
#include <cuda_runtime.h>
#include <cuda_fp16.h>
#include <cstdint>

#define NP 200000
#define NH 500000
#define NG 20000
#define NE_T 800000
#define NE_E 1000000
#define NE_H 500000
#define NE_ALL (NE_T + NE_E + NE_H)
#define HD 128
#define RPW 96              // raw player row width (85 -> 96)
#define HCW 32              // raw hist row width (26 -> 32)
#define K0 320              // layer-0 K: t96 | e96 | h32 | self96
#define K1 416              // layer-1 K: t128 | e128 | h32 | P128
#define ASW 40              // smem stage row stride (halfs)
#define SCAN_N (3 * NP)
#define SCAN_BLOCKS ((SCAN_N + 2047) / 2048)

// -------- static scratch (no allocations anywhere) --------
__device__ __half g_Rp[(size_t)NP * RPW];    // 38.4 MB raw player concat
__device__ __half g_P1[(size_t)NP * HD];     // 51.2 MB layer-0 output
__device__ __half g_Hc[(size_t)NH * HCW];    // 32 MB raw hist concat
__device__ __half g_Xh[(size_t)NP * 32];     // 12.8 MB hist agg (layer-invariant)
__device__ __half g_X[(size_t)NP * 256];     // t|e agg (L0 uses stride 192, L1 256)
__device__ __half g_Wb0[HD * K0];
__device__ __half g_Wb1[HD * K1];
__device__ float g_bSum[2 * HD];
__device__ float g_GC[NG];
__device__ int g_cnt[SCAN_N];
__device__ int g_cur[SCAN_N];
__device__ int g_offs[SCAN_N];
__device__ int g_bsum[SCAN_BLOCKS];
__device__ int g_sorted[NE_ALL];

// ------------------------------- utility ------------------------------------
__global__ void zero_buf(float* p, size_t n) {
    for (size_t i = (size_t)blockIdx.x * blockDim.x + threadIdx.x; i < n;
         i += (size_t)gridDim.x * blockDim.x)
        p[i] = 0.0f;
}

__global__ void zero2_k(int* a, int* b, int n) {
    int i = blockIdx.x * blockDim.x + threadIdx.x;
    if (i < n) { a[i] = 0; b[i] = 0; }
}

__global__ void count_all(const int* __restrict__ e_t, const int* __restrict__ e_e,
                          const int* __restrict__ e_h, int* __restrict__ cnt) {
    int i = blockIdx.x * blockDim.x + threadIdx.x;
    if (i < NE_T) {
        atomicAdd(&cnt[e_t[NE_T + i]], 1);
    } else if (i < NE_T + NE_E) {
        int j = i - NE_T;
        atomicAdd(&cnt[NP + e_e[NE_E + j]], 1);
    } else if (i < NE_ALL) {
        int j = i - NE_T - NE_E;
        atomicAdd(&cnt[2 * NP + e_h[NE_H + j]], 1);
    }
}

__global__ void scatter_all(const int* __restrict__ e_t, const int* __restrict__ e_e,
                            const int* __restrict__ e_h, const int* __restrict__ offs,
                            int* __restrict__ cur, int* __restrict__ sorted) {
    int i = blockIdx.x * blockDim.x + threadIdx.x;
    int s, d;
    if (i < NE_T) {
        s = e_t[i]; d = e_t[NE_T + i];
    } else if (i < NE_T + NE_E) {
        int j = i - NE_T;
        s = e_e[j]; d = NP + e_e[NE_E + j];
    } else if (i < NE_ALL) {
        int j = i - NE_T - NE_E;
        s = e_h[j]; d = 2 * NP + e_h[NE_H + j];
    } else return;
    int pos = offs[d] + atomicAdd(&cur[d], 1);
    sorted[pos] = s;
}

__global__ void gcount_k(const int* __restrict__ batch, float* __restrict__ gc) {
    int i = blockIdx.x * blockDim.x + threadIdx.x;
    if (i < NP) atomicAdd(&gc[batch[i]], 1.0f);
}

// ------------------------------- scan (exclusive) ----------------------------
__global__ void scan1(const int* __restrict__ in, int* __restrict__ out, int* __restrict__ bsum) {
    __shared__ int ts[256];
    int base = blockIdx.x * 2048 + threadIdx.x * 8;
    int v[8];
    int s = 0;
#pragma unroll
    for (int j = 0; j < 8; j++) {
        int idx = base + j;
        v[j] = (idx < SCAN_N) ? in[idx] : 0;
        s += v[j];
    }
    ts[threadIdx.x] = s;
    __syncthreads();
    for (int off = 1; off < 256; off <<= 1) {
        int t = (threadIdx.x >= off) ? ts[threadIdx.x - off] : 0;
        __syncthreads();
        ts[threadIdx.x] += t;
        __syncthreads();
    }
    int run = ts[threadIdx.x] - s;
    if (threadIdx.x == 255) bsum[blockIdx.x] = ts[255];
#pragma unroll
    for (int j = 0; j < 8; j++) {
        int idx = base + j;
        if (idx < SCAN_N) out[idx] = run;
        run += v[j];
    }
}

__global__ void scan2(int* bsum, int n) {
    __shared__ int ts[512];
    int v = (threadIdx.x < n) ? bsum[threadIdx.x] : 0;
    ts[threadIdx.x] = v;
    __syncthreads();
    for (int off = 1; off < 512; off <<= 1) {
        int t = (threadIdx.x >= off) ? ts[threadIdx.x - off] : 0;
        __syncthreads();
        ts[threadIdx.x] += t;
        __syncthreads();
    }
    if (threadIdx.x < n) bsum[threadIdx.x] = ts[threadIdx.x] - v;
}

__global__ void scan3(int* out, const int* __restrict__ bsum) {
    int idx = blockIdx.x * blockDim.x + threadIdx.x;
    if (idx < SCAN_N) out[idx] += bsum[idx >> 11];
}

// -------------------- raw player concat -> Rp[NP][96] ------------------------
__global__ __launch_bounds__(256) void build_rp(const float* __restrict__ xp,
                                                const float* __restrict__ embp,
                                                __half* __restrict__ Rp) {
    int r = blockIdx.x * blockDim.x + threadIdx.x;
    if (r >= NP) return;
    const float* x = xp + (size_t)r * 10;
    __half h[RPW];
    h[0] = __float2half(x[0]);
    h[1] = __float2half(x[6]);
    h[2] = __float2half(x[7]);
    h[3] = __float2half(x[8]);
    h[4] = __float2half(x[9]);
#pragma unroll
    for (int j = 0; j < 5; j++) {
        int ci = min(max((int)x[1 + j], 0), 199);
        const float* e = embp + ((size_t)j * 200 + ci) * 16;
#pragma unroll
        for (int t = 0; t < 16; t++) h[5 + j * 16 + t] = __float2half(e[t]);
    }
#pragma unroll
    for (int t = 85; t < RPW; t++) h[t] = __float2half(0.f);
#pragma unroll
    for (int q = 0; q < RPW / 8; q++)
        *(uint4*)(Rp + (size_t)r * RPW + q * 8) = *(uint4*)&h[q * 8];
}

// -------------- raw hist concat (26 dims, padded to 32 halfs) ----------------
__global__ __launch_bounds__(256) void build_hcat(const float* __restrict__ xh,
                                                  const float* __restrict__ e0,
                                                  const float* __restrict__ e3,
                                                  __half* __restrict__ Hc) {
    int r = blockIdx.x * blockDim.x + threadIdx.x;
    if (r >= NH) return;
    const float* x = xh + (size_t)r * 8;
    float f[32];
    f[0] = x[1]; f[1] = x[2]; f[2] = x[4]; f[3] = x[5]; f[4] = x[6]; f[5] = x[7];
    int c0 = min(max((int)x[0], 0), 1999);
    int c3 = min(max((int)x[3], 0), 9);
#pragma unroll
    for (int j = 0; j < 16; j++) f[6 + j] = e0[c0 * 16 + j];
#pragma unroll
    for (int j = 0; j < 4; j++) f[22 + j] = e3[c3 * 4 + j];
#pragma unroll
    for (int j = 26; j < 32; j++) f[j] = 0.f;
    __half h[32];
#pragma unroll
    for (int j = 0; j < 32; j++) h[j] = __float2half(f[j]);
#pragma unroll
    for (int q = 0; q < 4; q++)
        *(uint4*)(Hc + (size_t)r * HCW + q * 8) = *(uint4*)&h[q * 8];
}

// ------- layer-0 fused weight [o][320] with encoder folds + bias -------------
// k<96: (Wl_t@Wp | Wl_t@bp flag) | 96..191: same for e | 192..223: hist fold
// 224..319: WrS0@Wp (self); bias: sum sb(l0) + WrS0@bp
__global__ void build_w0(const float* __restrict__ sWl, const float* __restrict__ sWr,
                         const float* __restrict__ sb, const float* __restrict__ Wp,
                         const float* __restrict__ bp, const float* __restrict__ Wh,
                         const float* __restrict__ bh, __half* __restrict__ Wb0,
                         float* __restrict__ bS) {
    int i = blockIdx.x * blockDim.x + threadIdx.x;
    if (i >= HD * K0) return;
    int o = i / K0, k = i - o * K0;
    float v = 0.f;
    if (k < 192) {
        int type = k / 96, kt = k - type * 96;
        const float* wl = sWl + ((size_t)type * HD + o) * HD;  // layer0, part=type
        if (kt < 85) {
            for (int j = 0; j < HD; j++) v += wl[j] * Wp[j * 85 + kt];
        } else if (kt == 85) {
            for (int j = 0; j < HD; j++) v += wl[j] * bp[j];
        }
    } else if (k < 224) {
        int kh = k - 192;
        const float* wl = sWl + ((size_t)2 * HD + o) * HD;     // layer0, part=2
        if (kh < 26) {
            for (int j = 0; j < HD; j++) v += wl[j] * Wh[j * 26 + kh];
        } else if (kh == 26) {
            for (int j = 0; j < HD; j++) v += wl[j] * bh[j];
        }
    } else {
        int ks = k - 224;
        if (ks < 85) {
            for (int j = 0; j < HD; j++) {
                float wr = sWr[((size_t)0 * HD + o) * HD + j] +
                           sWr[((size_t)1 * HD + o) * HD + j] +
                           sWr[((size_t)2 * HD + o) * HD + j];
                v += wr * Wp[j * 85 + ks];
            }
        }
    }
    Wb0[o * K0 + k] = __float2half(v);
    if (k == 0) {
        float b = sb[0 * HD + o] + sb[1 * HD + o] + sb[2 * HD + o];
        for (int j = 0; j < HD; j++) {
            float wr = sWr[((size_t)0 * HD + o) * HD + j] +
                       sWr[((size_t)1 * HD + o) * HD + j] +
                       sWr[((size_t)2 * HD + o) * HD + j];
            b += wr * bp[j];
        }
        bS[o] = b;
    }
}

// ------- layer-1 fused weight [o][416] (standard + hist fold) ----------------
__global__ void build_w1(const float* __restrict__ sWl, const float* __restrict__ sWr,
                         const float* __restrict__ sb, const float* __restrict__ Wh,
                         const float* __restrict__ bh, __half* __restrict__ Wb1,
                         float* __restrict__ bS) {
    int i = blockIdx.x * blockDim.x + threadIdx.x;
    if (i >= HD * K1) return;
    int o = i / K1, k = i - o * K1;
    float v = 0.f;
    if (k < 256) {
        int part = k >> 7, kk = k & 127;
        v = sWl[((size_t)(3 + part) * HD + o) * HD + kk];
    } else if (k < 282) {
        int kh = k - 256;
        const float* wl = sWl + ((size_t)(3 + 2) * HD + o) * HD;
        for (int j = 0; j < HD; j++) v += wl[j] * Wh[j * 26 + kh];
    } else if (k == 282) {
        const float* wl = sWl + ((size_t)(3 + 2) * HD + o) * HD;
        for (int j = 0; j < HD; j++) v += wl[j] * bh[j];
    } else if (k < 288) {
        v = 0.f;
    } else {
        int kk = k - 288;
        v = sWr[((size_t)(3 + 0) * HD + o) * HD + kk] +
            sWr[((size_t)(3 + 1) * HD + o) * HD + kk] +
            sWr[((size_t)(3 + 2) * HD + o) * HD + kk];
    }
    Wb1[o * K1 + k] = __float2half(v);
    if (k == 0)
        bS[HD + o] = sb[(3 + 0) * HD + o] + sb[(3 + 1) * HD + o] + sb[(3 + 2) * HD + o];
}

// ------------- hist gather: half-warp per node -> Xh[node][32] ---------------
__global__ __launch_bounds__(256) void agg_h(const __half* __restrict__ Hc,
                                             const int* __restrict__ sorted,
                                             const int* __restrict__ offs,
                                             const int* __restrict__ cnt,
                                             __half* __restrict__ Xh) {
    int hw = (blockIdx.x * blockDim.x + threadIdx.x) >> 4;
    int lane = threadIdx.x & 15;
    if (hw >= NP) return;
    int start = offs[hw], c = cnt[hw];
    float2 a = make_float2(0.f, 0.f);
    for (int e = 0; e < c; e++) {
        int s = __ldg(sorted + start + e);
        unsigned int v = __ldg((const unsigned int*)(Hc + (size_t)s * HCW + lane * 2));
        float2 f = __half22float2(*(__half2*)&v);
        a.x += f.x; a.y += f.y;
    }
    float inv = 1.0f / fmaxf((float)c, 1.0f);
    int col = lane * 2;
    float v0 = a.x * inv, v1 = a.y * inv;
    if (col == 26) { v0 = (c > 0) ? 1.f : 0.f; v1 = 0.f; }
    else if (col > 26) { v0 = 0.f; v1 = 0.f; }
    __half2 o = __floats2half2_rn(v0, v1);
    *(__half2*)(Xh + (size_t)hw * 32 + col) = o;
}

// --------- t/e gather: half-warp per (node,type); SRCW = 96 (L0) / 128 (L1) --
__device__ __forceinline__ void acc8(float* a, uint4 v) {
    float2 f;
    f = __half22float2(*(__half2*)&v.x); a[0] += f.x; a[1] += f.y;
    f = __half22float2(*(__half2*)&v.y); a[2] += f.x; a[3] += f.y;
    f = __half22float2(*(__half2*)&v.z); a[4] += f.x; a[5] += f.y;
    f = __half22float2(*(__half2*)&v.w); a[6] += f.x; a[7] += f.y;
}

template <int SRCW>
__global__ __launch_bounds__(256) void agg_te_t(const __half* __restrict__ src,
                                                const int* __restrict__ sorted,
                                                const int* __restrict__ offs,
                                                const int* __restrict__ cnt,
                                                __half* __restrict__ X) {
    constexpr int NL = SRCW / 8;  // lanes doing IO (12 or 16)
    int g = blockIdx.x * blockDim.x + threadIdx.x;
    int hw = g >> 4;
    int lane = threadIdx.x & 15;
    int hbase = threadIdx.x & 16;
    unsigned int mask = 0xFFFFu << hbase;
    int node = hw >> 1;
    int type = hw & 1;
    if (node >= NP) return;
    int start = offs[type * NP + node];
    int c = cnt[type * NP + node];
    bool io = (lane < NL);
    float a[8] = {0.f, 0.f, 0.f, 0.f, 0.f, 0.f, 0.f, 0.f};
    for (int e0 = 0; e0 < c; e0 += 16) {
        int my = (e0 + lane < c) ? sorted[start + e0 + lane] : 0;
        int n = min(16, c - e0);
        int e = 0;
        for (; e + 4 <= n; e += 4) {
            int s0 = __shfl_sync(mask, my, hbase + e);
            int s1 = __shfl_sync(mask, my, hbase + e + 1);
            int s2 = __shfl_sync(mask, my, hbase + e + 2);
            int s3 = __shfl_sync(mask, my, hbase + e + 3);
            if (io) {
                uint4 v0 = __ldg((const uint4*)(src + (size_t)s0 * SRCW + lane * 8));
                uint4 v1 = __ldg((const uint4*)(src + (size_t)s1 * SRCW + lane * 8));
                uint4 v2 = __ldg((const uint4*)(src + (size_t)s2 * SRCW + lane * 8));
                uint4 v3 = __ldg((const uint4*)(src + (size_t)s3 * SRCW + lane * 8));
                acc8(a, v0); acc8(a, v1); acc8(a, v2); acc8(a, v3);
            }
        }
        for (; e < n; e++) {
            int s = __shfl_sync(mask, my, hbase + e);
            if (io) {
                uint4 v = __ldg((const uint4*)(src + (size_t)s * SRCW + lane * 8));
                acc8(a, v);
            }
        }
    }
    if (!io) return;
    float inv = 1.0f / fmaxf((float)c, 1.0f);
    __half2 h0 = __floats2half2_rn(a[0] * inv, a[1] * inv);
    __half2 h1 = __floats2half2_rn(a[2] * inv, a[3] * inv);
    __half2 h2 = __floats2half2_rn(a[4] * inv, a[5] * inv);
    __half2 h3 = __floats2half2_rn(a[6] * inv, a[7] * inv);
    if (SRCW == RPW && lane == 10) {
        // col 85 within slab = encoder-bias flag
        h2 = __floats2half2_rn(a[4] * inv, (c > 0) ? 1.f : 0.f);
        h3 = __floats2half2_rn(0.f, 0.f);
    }
    uint4 ov;
    ov.x = *(unsigned int*)&h0; ov.y = *(unsigned int*)&h1;
    ov.z = *(unsigned int*)&h2; ov.w = *(unsigned int*)&h3;
    *(uint4*)(X + (size_t)node * (2 * SRCW) + type * SRCW + lane * 8) = ov;
}

// ------------------------------- cp.async ------------------------------------
__device__ __forceinline__ void cp16(void* smem, const void* gmem) {
    unsigned int s = (unsigned int)__cvta_generic_to_shared(smem);
    asm volatile("cp.async.cg.shared.global [%0], [%1], 16;" :: "r"(s), "l"(gmem));
}
__device__ __forceinline__ void cp_commit() { asm volatile("cp.async.commit_group;"); }
template <int N>
__device__ __forceinline__ void cp_wait() {
    asm volatile("cp.async.wait_group %0;" :: "n"(N));
}

// ------------------------------- fp16 MMA ------------------------------------
__device__ __forceinline__ void mma_f16(float* c, const unsigned int* a, const unsigned int* b) {
    asm volatile(
        "mma.sync.aligned.m16n8k16.row.col.f32.f16.f16.f32 "
        "{%0,%1,%2,%3}, {%4,%5,%6,%7}, {%8,%9}, {%0,%1,%2,%3};"
        : "+f"(c[0]), "+f"(c[1]), "+f"(c[2]), "+f"(c[3])
        : "r"(a[0]), "r"(a[1]), "r"(a[2]), "r"(a[3]), "r"(b[0]), "r"(b[1]));
}

// C(128x128 per block) = relu(A(row, kTot) @ Wb[o][k].T + bS)
// A sources: kc < xtew -> Xte (stride xtew); kc < xtew+32 -> Xh; else Ps (stride psw).
__global__ __launch_bounds__(256) void sage_mma(const __half* __restrict__ Xte, int xtew,
                                                const __half* __restrict__ Xh,
                                                const __half* __restrict__ Ps, int psw,
                                                const __half* __restrict__ Wb, int wstride,
                                                int nChunks,
                                                const float* __restrict__ bS,
                                                __half* __restrict__ out,
                                                const int* __restrict__ batch,
                                                const float* __restrict__ Wc,
                                                float* __restrict__ pool_out,
                                                int do_pool) {
    __shared__ __half As[2][128 * ASW];
    __shared__ __half Bs[2][128 * ASW];
    int tid = threadIdx.x, wid = tid >> 5, lane = tid & 31;
    int gr = lane >> 2, tg = lane & 3;
    int rowBase = blockIdx.x * 128;
    int wm = (wid >> 1) * 32, wn = (wid & 1) * 64;

    int lr = tid >> 2;
    int lc8 = (tid & 3) * 8;

    auto issue = [&](int kc, int buf) {
#pragma unroll
        for (int t = 0; t < 2; t++) {
            int r = lr + t * 64;
            int row = min(rowBase + r, NP - 1);
            const __half* sp;
            if (kc < xtew)
                sp = Xte + (size_t)row * xtew + kc + lc8;
            else if (kc < xtew + 32)
                sp = Xh + (size_t)row * 32 + (kc - xtew) + lc8;
            else
                sp = Ps + (size_t)row * psw + (kc - xtew - 32) + lc8;
            cp16(&As[buf][r * ASW + lc8], sp);
            cp16(&Bs[buf][r * ASW + lc8], Wb + (size_t)r * wstride + kc + lc8);
        }
    };

    float acc[2][8][4];
#pragma unroll
    for (int i = 0; i < 2; i++)
#pragma unroll
        for (int j = 0; j < 8; j++)
#pragma unroll
            for (int k = 0; k < 4; k++) acc[i][j][k] = 0.f;

    issue(0, 0);
    cp_commit();
    for (int i = 0; i < nChunks; i++) {
        if (i + 1 < nChunks) {
            issue((i + 1) * 32, (i + 1) & 1);
            cp_commit();
            cp_wait<1>();
        } else {
            cp_wait<0>();
        }
        __syncthreads();
        const __half* Ab = As[i & 1];
        const __half* Bb = Bs[i & 1];
#pragma unroll
        for (int ks = 0; ks < 2; ks++) {
            int k0 = ks * 16;
            unsigned int a[2][4];
#pragma unroll
            for (int mt = 0; mt < 2; mt++) {
                int r = wm + mt * 16 + gr;
                a[mt][0] = *(const unsigned int*)&Ab[r * ASW + k0 + 2 * tg];
                a[mt][1] = *(const unsigned int*)&Ab[(r + 8) * ASW + k0 + 2 * tg];
                a[mt][2] = *(const unsigned int*)&Ab[r * ASW + k0 + 2 * tg + 8];
                a[mt][3] = *(const unsigned int*)&Ab[(r + 8) * ASW + k0 + 2 * tg + 8];
            }
#pragma unroll
            for (int nt = 0; nt < 8; nt++) {
                int n = wn + nt * 8 + gr;
                unsigned int b[2];
                b[0] = *(const unsigned int*)&Bb[n * ASW + k0 + 2 * tg];
                b[1] = *(const unsigned int*)&Bb[n * ASW + k0 + 2 * tg + 8];
                mma_f16(acc[0][nt], a[0], b);
                mma_f16(acc[1][nt], a[1], b);
            }
        }
        __syncthreads();
    }

    if (do_pool) {
        float ps[4] = {0.f, 0.f, 0.f, 0.f};
#pragma unroll
        for (int mt = 0; mt < 2; mt++)
#pragma unroll
            for (int nt = 0; nt < 8; nt++) {
                int col = wn + nt * 8 + 2 * tg;
                float w0 = Wc[col], w1 = Wc[col + 1];
                float b0 = bS[col], b1 = bS[col + 1];
                ps[mt * 2 + 0] += fmaxf(acc[mt][nt][0] + b0, 0.f) * w0 +
                                  fmaxf(acc[mt][nt][1] + b1, 0.f) * w1;
                ps[mt * 2 + 1] += fmaxf(acc[mt][nt][2] + b0, 0.f) * w0 +
                                  fmaxf(acc[mt][nt][3] + b1, 0.f) * w1;
            }
#pragma unroll
        for (int j = 0; j < 4; j++) {
            ps[j] += __shfl_xor_sync(0xFFFFFFFFu, ps[j], 1);
            ps[j] += __shfl_xor_sync(0xFFFFFFFFu, ps[j], 2);
        }
        if (tg == 0) {
#pragma unroll
            for (int mt = 0; mt < 2; mt++) {
                int r0 = rowBase + wm + mt * 16 + gr;
                int r1 = r0 + 8;
                if (r0 < NP) atomicAdd(&pool_out[batch[r0]], ps[mt * 2]);
                if (r1 < NP) atomicAdd(&pool_out[batch[r1]], ps[mt * 2 + 1]);
            }
        }
    } else {
#pragma unroll
        for (int mt = 0; mt < 2; mt++) {
#pragma unroll
            for (int nt = 0; nt < 8; nt++) {
                int col = wn + nt * 8 + 2 * tg;
                float b0 = bS[col], b1 = bS[col + 1];
                int r0 = rowBase + wm + mt * 16 + gr;
                if (r0 < NP) {
                    __half2 v = __floats2half2_rn(fmaxf(acc[mt][nt][0] + b0, 0.f),
                                                  fmaxf(acc[mt][nt][1] + b1, 0.f));
                    *(__half2*)(out + (size_t)r0 * HD + col) = v;
                }
                int r1 = r0 + 8;
                if (r1 < NP) {
                    __half2 v = __floats2half2_rn(fmaxf(acc[mt][nt][2] + b0, 0.f),
                                                  fmaxf(acc[mt][nt][3] + b1, 0.f));
                    *(__half2*)(out + (size_t)r1 * HD + col) = v;
                }
            }
        }
    }
}

__global__ void fin_k(float* out, const float* gc, const float* __restrict__ bc) {
    int g = blockIdx.x * blockDim.x + threadIdx.x;
    if (g < NG) out[g] = out[g] / fmaxf(gc[g], 1.0f) + bc[0];
}

// -------------------------------- launcher -----------------------------------
extern "C" void kernel_launch(void* const* d_in, const int* in_sizes, int n_in,
                              void* d_out, int out_size) {
    const float* x_player = (const float*)d_in[0];
    const float* x_hist   = (const float*)d_in[1];
    const int*   e_t      = (const int*)d_in[2];
    const int*   e_e      = (const int*)d_in[3];
    const int*   e_h      = (const int*)d_in[4];
    const int*   batch    = (const int*)d_in[5];
    const float* emb_p    = (const float*)d_in[6];
    const float* emb_h0   = (const float*)d_in[7];
    const float* emb_h3   = (const float*)d_in[8];
    const float* Wp       = (const float*)d_in[9];
    const float* bp       = (const float*)d_in[10];
    const float* Wh       = (const float*)d_in[11];
    const float* bh       = (const float*)d_in[12];
    const float* sWl      = (const float*)d_in[13];
    const float* sb       = (const float*)d_in[14];
    const float* sWr      = (const float*)d_in[15];
    const float* Wc       = (const float*)d_in[16];
    const float* bc       = (const float*)d_in[17];
    float* out = (float*)d_out;

    __half *Rp, *P1, *Hc, *Xh, *X, *Wb0, *Wb1;
    float *bS, *GC;
    int *cnt, *cur, *offs, *bsum, *sorted;
    cudaGetSymbolAddress((void**)&Rp, g_Rp);
    cudaGetSymbolAddress((void**)&P1, g_P1);
    cudaGetSymbolAddress((void**)&Hc, g_Hc);
    cudaGetSymbolAddress((void**)&Xh, g_Xh);
    cudaGetSymbolAddress((void**)&X, g_X);
    cudaGetSymbolAddress((void**)&Wb0, g_Wb0);
    cudaGetSymbolAddress((void**)&Wb1, g_Wb1);
    cudaGetSymbolAddress((void**)&bS, g_bSum);
    cudaGetSymbolAddress((void**)&GC, g_GC);
    cudaGetSymbolAddress((void**)&cnt, g_cnt);
    cudaGetSymbolAddress((void**)&cur, g_cur);
    cudaGetSymbolAddress((void**)&offs, g_offs);
    cudaGetSymbolAddress((void**)&bsum, g_bsum);
    cudaGetSymbolAddress((void**)&sorted, g_sorted);

    // ---- CSR build ----
    zero2_k<<<(SCAN_N + 255) / 256, 256>>>(cnt, cur, SCAN_N);
    count_all<<<(NE_ALL + 255) / 256, 256>>>(e_t, e_e, e_h, cnt);
    scan1<<<SCAN_BLOCKS, 256>>>(cnt, offs, bsum);
    scan2<<<1, 512>>>(bsum, SCAN_BLOCKS);
    scan3<<<(SCAN_N + 255) / 256, 256>>>(offs, bsum);
    scatter_all<<<(NE_ALL + 255) / 256, 256>>>(e_t, e_e, e_h, offs, cur, sorted);

    // ---- raw features + weights ----
    build_rp<<<(NP + 255) / 256, 256>>>(x_player, emb_p, Rp);
    build_hcat<<<(NH + 255) / 256, 256>>>(x_hist, emb_h0, emb_h3, Hc);
    build_w0<<<(HD * K0 + 255) / 256, 256>>>(sWl, sWr, sb, Wp, bp, Wh, bh, Wb0, bS);
    build_w1<<<(HD * K1 + 255) / 256, 256>>>(sWl, sWr, sb, Wh, bh, Wb1, bS);

    // ---- hist aggregation (layer-invariant) ----
    agg_h<<<NP / 16, 256>>>(Hc, sorted, offs + 2 * NP, cnt + 2 * NP, Xh);

    int teBlocks = (NP * 2 * 16) / 256;
    int mmaBlocks = (NP + 127) / 128;

    // ---- layer 0: raw-feature gathers + folded GEMM (K=320) ----
    agg_te_t<RPW><<<teBlocks, 256>>>(Rp, sorted, offs, cnt, X);
    sage_mma<<<mmaBlocks, 256>>>(X, 192, Xh, Rp, RPW, Wb0, K0, K0 / 32, bS,
                                 P1, batch, Wc, out, 0);

    // ---- layer 1: P1 gathers + GEMM (K=416) + fused pool ----
    zero_buf<<<(NG + 255) / 256, 256>>>(out, NG);
    zero_buf<<<(NG + 255) / 256, 256>>>(GC, NG);
    gcount_k<<<(NP + 255) / 256, 256>>>(batch, GC);
    agg_te_t<HD><<<teBlocks, 256>>>(P1, sorted, offs, cnt, X);
    sage_mma<<<mmaBlocks, 256>>>(X, 256, Xh, P1, HD, Wb1, K1, K1 / 32, bS + HD,
                                 P1, batch, Wc, out, 1);

    fin_k<<<(NG + 255) / 256, 256>>>(out, GC, bc);
}

// round 12
// speedup vs baseline: 1.8274x; 1.0032x over previous
#include <cuda_runtime.h>
#include <cuda_fp16.h>
#include <cstdint>

#define NP 200000
#define NH 500000
#define NG 20000
#define NE_T 800000
#define NE_E 1000000
#define NE_H 500000
#define NE_ALL (NE_T + NE_E + NE_H)
#define HD 128
#define RPW 96              // raw player row width (85 -> 96)
#define HCW 32              // raw hist row width (26 -> 32)
#define K0 320              // layer-0 K: t96 | e96 | h32 | self96
#define K1 416              // layer-1 K: t128 | e128 | h32 | P128
#define ASW 40              // smem stage row stride (halfs)
#define SCAN_N (3 * NP)
#define SCAN_BLOCKS ((SCAN_N + 2047) / 2048)

// prologue block ranges
#define B_RP ((NP + 255) / 256)          // 782
#define B_HC ((NH + 255) / 256)          // 1954
#define B_W0 (HD * K0 / 256)             // 160
#define B_W1 (HD * K1 / 256)             // 208
#define B_ZO ((NG + 255) / 256)          // 79
#define B_GC ((NP + 255) / 256)          // 782
#define PRO_BLOCKS (B_RP + B_HC + B_W0 + B_W1 + B_ZO + B_GC)

// agg0 block ranges
#define TE_BLOCKS (NP * 2 * 16 / 256)    // 25000
#define AH_BLOCKS (NP * 16 / 256)        // 12500

// -------- static scratch (no allocations anywhere; zero-initialized) --------
__device__ __half g_Rp[(size_t)NP * RPW];
__device__ __half g_P1[(size_t)NP * HD];
__device__ __half g_Hc[(size_t)NH * HCW];
__device__ __half g_Xh[(size_t)NP * 32];
__device__ __half g_X[(size_t)NP * 256];
__device__ __half g_Wb0[HD * K0];
__device__ __half g_Wb1[HD * K1];
__device__ float g_bSum[2 * HD];
__device__ float g_GC[NG];
__device__ int g_cnt[SCAN_N];
__device__ int g_cur[SCAN_N];
__device__ int g_offs[SCAN_N];
__device__ int g_bsum[SCAN_BLOCKS];
__device__ int g_sorted[NE_ALL];

// ---------------------------- CSR build kernels ------------------------------
__global__ void count_all(const int* __restrict__ e_t, const int* __restrict__ e_e,
                          const int* __restrict__ e_h, int* __restrict__ cnt) {
    int i = blockIdx.x * blockDim.x + threadIdx.x;
    if (i < NE_T) {
        atomicAdd(&cnt[e_t[NE_T + i]], 1);
    } else if (i < NE_T + NE_E) {
        int j = i - NE_T;
        atomicAdd(&cnt[NP + e_e[NE_E + j]], 1);
    } else if (i < NE_ALL) {
        int j = i - NE_T - NE_E;
        atomicAdd(&cnt[2 * NP + e_h[NE_H + j]], 1);
    }
}

__global__ void scatter_all(const int* __restrict__ e_t, const int* __restrict__ e_e,
                            const int* __restrict__ e_h, const int* __restrict__ offs,
                            int* __restrict__ cur, int* __restrict__ sorted) {
    int i = blockIdx.x * blockDim.x + threadIdx.x;
    int s, d;
    if (i < NE_T) {
        s = e_t[i]; d = e_t[NE_T + i];
    } else if (i < NE_T + NE_E) {
        int j = i - NE_T;
        s = e_e[j]; d = NP + e_e[NE_E + j];
    } else if (i < NE_ALL) {
        int j = i - NE_T - NE_E;
        s = e_h[j]; d = 2 * NP + e_h[NE_H + j];
    } else return;
    int pos = offs[d] + atomicAdd(&cur[d], 1);
    sorted[pos] = s;
}

__global__ void scan1(const int* __restrict__ in, int* __restrict__ out, int* __restrict__ bsum) {
    __shared__ int ts[256];
    int base = blockIdx.x * 2048 + threadIdx.x * 8;
    int v[8];
    int s = 0;
#pragma unroll
    for (int j = 0; j < 8; j++) {
        int idx = base + j;
        v[j] = (idx < SCAN_N) ? in[idx] : 0;
        s += v[j];
    }
    ts[threadIdx.x] = s;
    __syncthreads();
    for (int off = 1; off < 256; off <<= 1) {
        int t = (threadIdx.x >= off) ? ts[threadIdx.x - off] : 0;
        __syncthreads();
        ts[threadIdx.x] += t;
        __syncthreads();
    }
    int run = ts[threadIdx.x] - s;
    if (threadIdx.x == 255) bsum[blockIdx.x] = ts[255];
#pragma unroll
    for (int j = 0; j < 8; j++) {
        int idx = base + j;
        if (idx < SCAN_N) out[idx] = run;
        run += v[j];
    }
}

__global__ void scan2(int* bsum, int n) {
    __shared__ int ts[512];
    int v = (threadIdx.x < n) ? bsum[threadIdx.x] : 0;
    ts[threadIdx.x] = v;
    __syncthreads();
    for (int off = 1; off < 512; off <<= 1) {
        int t = (threadIdx.x >= off) ? ts[threadIdx.x - off] : 0;
        __syncthreads();
        ts[threadIdx.x] += t;
        __syncthreads();
    }
    if (threadIdx.x < n) bsum[threadIdx.x] = ts[threadIdx.x] - v;
}

__global__ void scan3(int* out, const int* __restrict__ bsum) {
    int idx = blockIdx.x * blockDim.x + threadIdx.x;
    if (idx < SCAN_N) out[idx] += bsum[idx >> 11];
}

// ----------------------------- fused prologue --------------------------------
__global__ __launch_bounds__(256) void prologue_k(
    const float* __restrict__ xp, const float* __restrict__ embp,
    const float* __restrict__ xh, const float* __restrict__ e0,
    const float* __restrict__ e3,
    const float* __restrict__ sWl, const float* __restrict__ sWr,
    const float* __restrict__ sb, const float* __restrict__ Wp,
    const float* __restrict__ bp, const float* __restrict__ Wh,
    const float* __restrict__ bh, const int* __restrict__ batch,
    __half* __restrict__ Rp, __half* __restrict__ Hc,
    __half* __restrict__ Wb0, __half* __restrict__ Wb1,
    float* __restrict__ bS, float* __restrict__ out, float* __restrict__ gc) {
    int b = blockIdx.x;
    int t = threadIdx.x;
    if (b < B_RP) {
        // ---- raw player concat ----
        int r = b * 256 + t;
        if (r >= NP) return;
        const float* x = xp + (size_t)r * 10;
        __half h[RPW];
        h[0] = __float2half(x[0]);
        h[1] = __float2half(x[6]);
        h[2] = __float2half(x[7]);
        h[3] = __float2half(x[8]);
        h[4] = __float2half(x[9]);
#pragma unroll
        for (int j = 0; j < 5; j++) {
            int ci = min(max((int)x[1 + j], 0), 199);
            const float* e = embp + ((size_t)j * 200 + ci) * 16;
#pragma unroll
            for (int q = 0; q < 16; q++) h[5 + j * 16 + q] = __float2half(e[q]);
        }
#pragma unroll
        for (int q = 85; q < RPW; q++) h[q] = __float2half(0.f);
#pragma unroll
        for (int q = 0; q < RPW / 8; q++)
            *(uint4*)(Rp + (size_t)r * RPW + q * 8) = *(uint4*)&h[q * 8];
        return;
    }
    b -= B_RP;
    if (b < B_HC) {
        // ---- raw hist concat ----
        int r = b * 256 + t;
        if (r >= NH) return;
        const float* x = xh + (size_t)r * 8;
        float f[32];
        f[0] = x[1]; f[1] = x[2]; f[2] = x[4]; f[3] = x[5]; f[4] = x[6]; f[5] = x[7];
        int c0 = min(max((int)x[0], 0), 1999);
        int c3 = min(max((int)x[3], 0), 9);
#pragma unroll
        for (int j = 0; j < 16; j++) f[6 + j] = e0[c0 * 16 + j];
#pragma unroll
        for (int j = 0; j < 4; j++) f[22 + j] = e3[c3 * 4 + j];
#pragma unroll
        for (int j = 26; j < 32; j++) f[j] = 0.f;
        __half h[32];
#pragma unroll
        for (int j = 0; j < 32; j++) h[j] = __float2half(f[j]);
#pragma unroll
        for (int q = 0; q < 4; q++)
            *(uint4*)(Hc + (size_t)r * HCW + q * 8) = *(uint4*)&h[q * 8];
        return;
    }
    b -= B_HC;
    if (b < B_W0) {
        // ---- layer-0 fused weight with encoder folds ----
        int i = b * 256 + t;
        int o = i / K0, k = i - o * K0;
        float v = 0.f;
        if (k < 192) {
            int type = k / 96, kt = k - type * 96;
            const float* wl = sWl + ((size_t)type * HD + o) * HD;
            if (kt < 85) {
                for (int j = 0; j < HD; j++) v += wl[j] * Wp[j * 85 + kt];
            } else if (kt == 85) {
                for (int j = 0; j < HD; j++) v += wl[j] * bp[j];
            }
        } else if (k < 224) {
            int kh = k - 192;
            const float* wl = sWl + ((size_t)2 * HD + o) * HD;
            if (kh < 26) {
                for (int j = 0; j < HD; j++) v += wl[j] * Wh[j * 26 + kh];
            } else if (kh == 26) {
                for (int j = 0; j < HD; j++) v += wl[j] * bh[j];
            }
        } else {
            int ks = k - 224;
            if (ks < 85) {
                for (int j = 0; j < HD; j++) {
                    float wr = sWr[((size_t)0 * HD + o) * HD + j] +
                               sWr[((size_t)1 * HD + o) * HD + j] +
                               sWr[((size_t)2 * HD + o) * HD + j];
                    v += wr * Wp[j * 85 + ks];
                }
            }
        }
        Wb0[o * K0 + k] = __float2half(v);
        if (k == 0) {
            float bb = sb[0 * HD + o] + sb[1 * HD + o] + sb[2 * HD + o];
            for (int j = 0; j < HD; j++) {
                float wr = sWr[((size_t)0 * HD + o) * HD + j] +
                           sWr[((size_t)1 * HD + o) * HD + j] +
                           sWr[((size_t)2 * HD + o) * HD + j];
                bb += wr * bp[j];
            }
            bS[o] = bb;
        }
        return;
    }
    b -= B_W0;
    if (b < B_W1) {
        // ---- layer-1 fused weight ----
        int i = b * 256 + t;
        int o = i / K1, k = i - o * K1;
        float v = 0.f;
        if (k < 256) {
            int part = k >> 7, kk = k & 127;
            v = sWl[((size_t)(3 + part) * HD + o) * HD + kk];
        } else if (k < 282) {
            int kh = k - 256;
            const float* wl = sWl + ((size_t)(3 + 2) * HD + o) * HD;
            for (int j = 0; j < HD; j++) v += wl[j] * Wh[j * 26 + kh];
        } else if (k == 282) {
            const float* wl = sWl + ((size_t)(3 + 2) * HD + o) * HD;
            for (int j = 0; j < HD; j++) v += wl[j] * bh[j];
        } else if (k < 288) {
            v = 0.f;
        } else {
            int kk = k - 288;
            v = sWr[((size_t)(3 + 0) * HD + o) * HD + kk] +
                sWr[((size_t)(3 + 1) * HD + o) * HD + kk] +
                sWr[((size_t)(3 + 2) * HD + o) * HD + kk];
        }
        Wb1[o * K1 + k] = __float2half(v);
        if (k == 0)
            bS[HD + o] = sb[(3 + 0) * HD + o] + sb[(3 + 1) * HD + o] +
                         sb[(3 + 2) * HD + o];
        return;
    }
    b -= B_W1;
    if (b < B_ZO) {
        // ---- zero the (poisoned) output ----
        int i = b * 256 + t;
        if (i < NG) out[i] = 0.f;
        return;
    }
    b -= B_ZO;
    {
        // ---- graph counts (GC is zero at call entry: static init / fin_k reset) ----
        int i = b * 256 + t;
        if (i < NP) atomicAdd(&gc[batch[i]], 1.0f);
    }
}

// --------------------------- gather device bodies ----------------------------
__device__ __forceinline__ void acc8(float* a, uint4 v) {
    float2 f;
    f = __half22float2(*(__half2*)&v.x); a[0] += f.x; a[1] += f.y;
    f = __half22float2(*(__half2*)&v.y); a[2] += f.x; a[3] += f.y;
    f = __half22float2(*(__half2*)&v.z); a[4] += f.x; a[5] += f.y;
    f = __half22float2(*(__half2*)&v.w); a[6] += f.x; a[7] += f.y;
}

template <int SRCW>
__device__ __forceinline__ void agg_te_body(const __half* __restrict__ src,
                                            const int* __restrict__ sorted,
                                            const int* __restrict__ offs,
                                            const int* __restrict__ cnt,
                                            __half* __restrict__ X, int g) {
    constexpr int NL = SRCW / 8;
    int hw = g >> 4;
    int lane = threadIdx.x & 15;
    int hbase = threadIdx.x & 16;
    unsigned int mask = 0xFFFFu << hbase;
    int node = hw >> 1;
    int type = hw & 1;
    if (node >= NP) return;
    int start = offs[type * NP + node];
    int c = cnt[type * NP + node];
    bool io = (lane < NL);
    float a[8] = {0.f, 0.f, 0.f, 0.f, 0.f, 0.f, 0.f, 0.f};
    for (int e0 = 0; e0 < c; e0 += 16) {
        int my = (e0 + lane < c) ? sorted[start + e0 + lane] : 0;
        int n = min(16, c - e0);
        int e = 0;
        for (; e + 4 <= n; e += 4) {
            int s0 = __shfl_sync(mask, my, hbase + e);
            int s1 = __shfl_sync(mask, my, hbase + e + 1);
            int s2 = __shfl_sync(mask, my, hbase + e + 2);
            int s3 = __shfl_sync(mask, my, hbase + e + 3);
            if (io) {
                uint4 v0 = __ldg((const uint4*)(src + (size_t)s0 * SRCW + lane * 8));
                uint4 v1 = __ldg((const uint4*)(src + (size_t)s1 * SRCW + lane * 8));
                uint4 v2 = __ldg((const uint4*)(src + (size_t)s2 * SRCW + lane * 8));
                uint4 v3 = __ldg((const uint4*)(src + (size_t)s3 * SRCW + lane * 8));
                acc8(a, v0); acc8(a, v1); acc8(a, v2); acc8(a, v3);
            }
        }
        for (; e < n; e++) {
            int s = __shfl_sync(mask, my, hbase + e);
            if (io) {
                uint4 v = __ldg((const uint4*)(src + (size_t)s * SRCW + lane * 8));
                acc8(a, v);
            }
        }
    }
    if (!io) return;
    float inv = 1.0f / fmaxf((float)c, 1.0f);
    __half2 h0 = __floats2half2_rn(a[0] * inv, a[1] * inv);
    __half2 h1 = __floats2half2_rn(a[2] * inv, a[3] * inv);
    __half2 h2 = __floats2half2_rn(a[4] * inv, a[5] * inv);
    __half2 h3 = __floats2half2_rn(a[6] * inv, a[7] * inv);
    if (SRCW == RPW && lane == 10) {
        h2 = __floats2half2_rn(a[4] * inv, (c > 0) ? 1.f : 0.f);  // encoder-bias flag
        h3 = __floats2half2_rn(0.f, 0.f);
    }
    uint4 ov;
    ov.x = *(unsigned int*)&h0; ov.y = *(unsigned int*)&h1;
    ov.z = *(unsigned int*)&h2; ov.w = *(unsigned int*)&h3;
    *(uint4*)(X + (size_t)node * (2 * SRCW) + type * SRCW + lane * 8) = ov;
}

__device__ __forceinline__ void agg_h_body(const __half* __restrict__ Hc,
                                           const int* __restrict__ sorted,
                                           const int* __restrict__ offs,
                                           const int* __restrict__ cnt,
                                           __half* __restrict__ Xh, int idx) {
    int hw = idx >> 4;
    int lane = threadIdx.x & 15;
    if (hw >= NP) return;
    int start = offs[hw], c = cnt[hw];
    float2 a = make_float2(0.f, 0.f);
    for (int e = 0; e < c; e++) {
        int s = __ldg(sorted + start + e);
        unsigned int v = __ldg((const unsigned int*)(Hc + (size_t)s * HCW + lane * 2));
        float2 f = __half22float2(*(__half2*)&v);
        a.x += f.x; a.y += f.y;
    }
    float inv = 1.0f / fmaxf((float)c, 1.0f);
    int col = lane * 2;
    float v0 = a.x * inv, v1 = a.y * inv;
    if (col == 26) { v0 = (c > 0) ? 1.f : 0.f; v1 = 0.f; }
    else if (col > 26) { v0 = 0.f; v1 = 0.f; }
    __half2 o = __floats2half2_rn(v0, v1);
    *(__half2*)(Xh + (size_t)hw * 32 + col) = o;
}

// ---- layer-0 aggregation: t/e gathers (range 0) + hist gathers (range 1) ----
__global__ __launch_bounds__(256) void agg0_k(const __half* __restrict__ Rp,
                                              const __half* __restrict__ Hc,
                                              const int* __restrict__ sorted,
                                              const int* __restrict__ offs,
                                              const int* __restrict__ cnt,
                                              __half* __restrict__ X,
                                              __half* __restrict__ Xh) {
    if (blockIdx.x < TE_BLOCKS) {
        agg_te_body<RPW>(Rp, sorted, offs, cnt, X, blockIdx.x * 256 + threadIdx.x);
    } else {
        int idx = (blockIdx.x - TE_BLOCKS) * 256 + threadIdx.x;
        agg_h_body(Hc, sorted, offs + 2 * NP, cnt + 2 * NP, Xh, idx);
    }
}

__global__ __launch_bounds__(256) void agg1_k(const __half* __restrict__ P1,
                                              const int* __restrict__ sorted,
                                              const int* __restrict__ offs,
                                              const int* __restrict__ cnt,
                                              __half* __restrict__ X) {
    agg_te_body<HD>(P1, sorted, offs, cnt, X, blockIdx.x * 256 + threadIdx.x);
}

// ------------------------------- cp.async ------------------------------------
__device__ __forceinline__ void cp16(void* smem, const void* gmem) {
    unsigned int s = (unsigned int)__cvta_generic_to_shared(smem);
    asm volatile("cp.async.cg.shared.global [%0], [%1], 16;" :: "r"(s), "l"(gmem));
}
__device__ __forceinline__ void cp_commit() { asm volatile("cp.async.commit_group;"); }
template <int N>
__device__ __forceinline__ void cp_wait() {
    asm volatile("cp.async.wait_group %0;" :: "n"(N));
}

// ------------------------------- fp16 MMA ------------------------------------
__device__ __forceinline__ void mma_f16(float* c, const unsigned int* a, const unsigned int* b) {
    asm volatile(
        "mma.sync.aligned.m16n8k16.row.col.f32.f16.f16.f32 "
        "{%0,%1,%2,%3}, {%4,%5,%6,%7}, {%8,%9}, {%0,%1,%2,%3};"
        : "+f"(c[0]), "+f"(c[1]), "+f"(c[2]), "+f"(c[3])
        : "r"(a[0]), "r"(a[1]), "r"(a[2]), "r"(a[3]), "r"(b[0]), "r"(b[1]));
}

__global__ __launch_bounds__(256) void sage_mma(const __half* __restrict__ Xte, int xtew,
                                                const __half* __restrict__ Xh,
                                                const __half* __restrict__ Ps, int psw,
                                                const __half* __restrict__ Wb, int wstride,
                                                int nChunks,
                                                const float* __restrict__ bS,
                                                __half* __restrict__ out,
                                                const int* __restrict__ batch,
                                                const float* __restrict__ Wc,
                                                float* __restrict__ pool_out,
                                                int do_pool) {
    __shared__ __half As[2][128 * ASW];
    __shared__ __half Bs[2][128 * ASW];
    int tid = threadIdx.x, wid = tid >> 5, lane = tid & 31;
    int gr = lane >> 2, tg = lane & 3;
    int rowBase = blockIdx.x * 128;
    int wm = (wid >> 1) * 32, wn = (wid & 1) * 64;

    int lr = tid >> 2;
    int lc8 = (tid & 3) * 8;

    auto issue = [&](int kc, int buf) {
#pragma unroll
        for (int t = 0; t < 2; t++) {
            int r = lr + t * 64;
            int row = min(rowBase + r, NP - 1);
            const __half* sp;
            if (kc < xtew)
                sp = Xte + (size_t)row * xtew + kc + lc8;
            else if (kc < xtew + 32)
                sp = Xh + (size_t)row * 32 + (kc - xtew) + lc8;
            else
                sp = Ps + (size_t)row * psw + (kc - xtew - 32) + lc8;
            cp16(&As[buf][r * ASW + lc8], sp);
            cp16(&Bs[buf][r * ASW + lc8], Wb + (size_t)r * wstride + kc + lc8);
        }
    };

    float acc[2][8][4];
#pragma unroll
    for (int i = 0; i < 2; i++)
#pragma unroll
        for (int j = 0; j < 8; j++)
#pragma unroll
            for (int k = 0; k < 4; k++) acc[i][j][k] = 0.f;

    issue(0, 0);
    cp_commit();
    for (int i = 0; i < nChunks; i++) {
        if (i + 1 < nChunks) {
            issue((i + 1) * 32, (i + 1) & 1);
            cp_commit();
            cp_wait<1>();
        } else {
            cp_wait<0>();
        }
        __syncthreads();
        const __half* Ab = As[i & 1];
        const __half* Bb = Bs[i & 1];
#pragma unroll
        for (int ks = 0; ks < 2; ks++) {
            int k0 = ks * 16;
            unsigned int a[2][4];
#pragma unroll
            for (int mt = 0; mt < 2; mt++) {
                int r = wm + mt * 16 + gr;
                a[mt][0] = *(const unsigned int*)&Ab[r * ASW + k0 + 2 * tg];
                a[mt][1] = *(const unsigned int*)&Ab[(r + 8) * ASW + k0 + 2 * tg];
                a[mt][2] = *(const unsigned int*)&Ab[r * ASW + k0 + 2 * tg + 8];
                a[mt][3] = *(const unsigned int*)&Ab[(r + 8) * ASW + k0 + 2 * tg + 8];
            }
#pragma unroll
            for (int nt = 0; nt < 8; nt++) {
                int n = wn + nt * 8 + gr;
                unsigned int b[2];
                b[0] = *(const unsigned int*)&Bb[n * ASW + k0 + 2 * tg];
                b[1] = *(const unsigned int*)&Bb[n * ASW + k0 + 2 * tg + 8];
                mma_f16(acc[0][nt], a[0], b);
                mma_f16(acc[1][nt], a[1], b);
            }
        }
        __syncthreads();
    }

    if (do_pool) {
        float ps[4] = {0.f, 0.f, 0.f, 0.f};
#pragma unroll
        for (int mt = 0; mt < 2; mt++)
#pragma unroll
            for (int nt = 0; nt < 8; nt++) {
                int col = wn + nt * 8 + 2 * tg;
                float w0 = Wc[col], w1 = Wc[col + 1];
                float b0 = bS[col], b1 = bS[col + 1];
                ps[mt * 2 + 0] += fmaxf(acc[mt][nt][0] + b0, 0.f) * w0 +
                                  fmaxf(acc[mt][nt][1] + b1, 0.f) * w1;
                ps[mt * 2 + 1] += fmaxf(acc[mt][nt][2] + b0, 0.f) * w0 +
                                  fmaxf(acc[mt][nt][3] + b1, 0.f) * w1;
            }
#pragma unroll
        for (int j = 0; j < 4; j++) {
            ps[j] += __shfl_xor_sync(0xFFFFFFFFu, ps[j], 1);
            ps[j] += __shfl_xor_sync(0xFFFFFFFFu, ps[j], 2);
        }
        if (tg == 0) {
#pragma unroll
            for (int mt = 0; mt < 2; mt++) {
                int r0 = rowBase + wm + mt * 16 + gr;
                int r1 = r0 + 8;
                if (r0 < NP) atomicAdd(&pool_out[batch[r0]], ps[mt * 2]);
                if (r1 < NP) atomicAdd(&pool_out[batch[r1]], ps[mt * 2 + 1]);
            }
        }
    } else {
#pragma unroll
        for (int mt = 0; mt < 2; mt++) {
#pragma unroll
            for (int nt = 0; nt < 8; nt++) {
                int col = wn + nt * 8 + 2 * tg;
                float b0 = bS[col], b1 = bS[col + 1];
                int r0 = rowBase + wm + mt * 16 + gr;
                if (r0 < NP) {
                    __half2 v = __floats2half2_rn(fmaxf(acc[mt][nt][0] + b0, 0.f),
                                                  fmaxf(acc[mt][nt][1] + b1, 0.f));
                    *(__half2*)(out + (size_t)r0 * HD + col) = v;
                }
                int r1 = r0 + 8;
                if (r1 < NP) {
                    __half2 v = __floats2half2_rn(fmaxf(acc[mt][nt][2] + b0, 0.f),
                                                  fmaxf(acc[mt][nt][3] + b1, 0.f));
                    *(__half2*)(out + (size_t)r1 * HD + col) = v;
                }
            }
        }
    }
}

// -------- finalize + reset scratch state for the next (replayed) call --------
__global__ void fin_k(float* out, float* gc, const float* __restrict__ bc,
                      int* cnt, int* cur) {
    int g = blockIdx.x * blockDim.x + threadIdx.x;
    if (g < NG) {
        out[g] = out[g] / fmaxf(gc[g], 1.0f) + bc[0];
        gc[g] = 0.f;
    }
    if (g < SCAN_N) { cnt[g] = 0; cur[g] = 0; }
}

// -------------------------------- launcher -----------------------------------
extern "C" void kernel_launch(void* const* d_in, const int* in_sizes, int n_in,
                              void* d_out, int out_size) {
    const float* x_player = (const float*)d_in[0];
    const float* x_hist   = (const float*)d_in[1];
    const int*   e_t      = (const int*)d_in[2];
    const int*   e_e      = (const int*)d_in[3];
    const int*   e_h      = (const int*)d_in[4];
    const int*   batch    = (const int*)d_in[5];
    const float* emb_p    = (const float*)d_in[6];
    const float* emb_h0   = (const float*)d_in[7];
    const float* emb_h3   = (const float*)d_in[8];
    const float* Wp       = (const float*)d_in[9];
    const float* bp       = (const float*)d_in[10];
    const float* Wh       = (const float*)d_in[11];
    const float* bh       = (const float*)d_in[12];
    const float* sWl      = (const float*)d_in[13];
    const float* sb       = (const float*)d_in[14];
    const float* sWr      = (const float*)d_in[15];
    const float* Wc       = (const float*)d_in[16];
    const float* bc       = (const float*)d_in[17];
    float* out = (float*)d_out;

    __half *Rp, *P1, *Hc, *Xh, *X, *Wb0, *Wb1;
    float *bS, *GC;
    int *cnt, *cur, *offs, *bsum, *sorted;
    cudaGetSymbolAddress((void**)&Rp, g_Rp);
    cudaGetSymbolAddress((void**)&P1, g_P1);
    cudaGetSymbolAddress((void**)&Hc, g_Hc);
    cudaGetSymbolAddress((void**)&Xh, g_Xh);
    cudaGetSymbolAddress((void**)&X, g_X);
    cudaGetSymbolAddress((void**)&Wb0, g_Wb0);
    cudaGetSymbolAddress((void**)&Wb1, g_Wb1);
    cudaGetSymbolAddress((void**)&bS, g_bSum);
    cudaGetSymbolAddress((void**)&GC, g_GC);
    cudaGetSymbolAddress((void**)&cnt, g_cnt);
    cudaGetSymbolAddress((void**)&cur, g_cur);
    cudaGetSymbolAddress((void**)&offs, g_offs);
    cudaGetSymbolAddress((void**)&bsum, g_bsum);
    cudaGetSymbolAddress((void**)&sorted, g_sorted);

    // 1) fused prologue (features, weights, out-zero, graph counts)
    prologue_k<<<PRO_BLOCKS, 256>>>(x_player, emb_p, x_hist, emb_h0, emb_h3,
                                    sWl, sWr, sb, Wp, bp, Wh, bh, batch,
                                    Rp, Hc, Wb0, Wb1, bS, out, GC);

    // 2-6) CSR build (cnt/cur are zero at entry: static init / fin_k reset)
    count_all<<<(NE_ALL + 255) / 256, 256>>>(e_t, e_e, e_h, cnt);
    scan1<<<SCAN_BLOCKS, 256>>>(cnt, offs, bsum);
    scan2<<<1, 512>>>(bsum, SCAN_BLOCKS);
    scan3<<<(SCAN_N + 255) / 256, 256>>>(offs, bsum);
    scatter_all<<<(NE_ALL + 255) / 256, 256>>>(e_t, e_e, e_h, offs, cur, sorted);

    int mmaBlocks = (NP + 127) / 128;

    // 7) layer-0 gathers (t/e + hist fused)
    agg0_k<<<TE_BLOCKS + AH_BLOCKS, 256>>>(Rp, Hc, sorted, offs, cnt, X, Xh);

    // 8) layer-0 GEMM (K=320, folded encoder)
    sage_mma<<<mmaBlocks, 256>>>(X, 192, Xh, Rp, RPW, Wb0, K0, K0 / 32, bS,
                                 P1, batch, Wc, out, 0);

    // 9) layer-1 gathers
    agg1_k<<<TE_BLOCKS, 256>>>(P1, sorted, offs, cnt, X);

    // 10) layer-1 GEMM + fused pooling
    sage_mma<<<mmaBlocks, 256>>>(X, 256, Xh, P1, HD, Wb1, K1, K1 / 32, bS + HD,
                                 P1, batch, Wc, out, 1);

    // 11) finalize + state reset for next replay
    fin_k<<<(SCAN_N + 255) / 256, 256>>>(out, GC, bc, cnt, cur);
}

// round 13
// speedup vs baseline: 1.8704x; 1.0235x over previous
#include <cuda_runtime.h>
#include <cuda_fp16.h>
#include <cstdint>

#define NP 200000
#define NH 500000
#define NG 20000
#define NE_T 800000
#define NE_E 1000000
#define NE_H 500000
#define NE_ALL (NE_T + NE_E + NE_H)
#define HD 128
#define RPW 96              // raw player row width (85 -> 96)
#define HCW 32              // raw hist row width (26 -> 32)
#define K0 320              // layer-0 K: t96 | e96 | h32 | self96
#define K1 416              // layer-1 K: t128 | e128 | h32 | P128
#define ASW 40              // smem stage row stride (halfs)
#define SCAN_N (3 * NP)
#define SCAN_BLOCKS ((SCAN_N + 2047) / 2048)

// prologue block ranges
#define B_RP ((NP + 255) / 256)          // 782
#define B_HC ((NH + 255) / 256)          // 1954
#define B_W0 (HD * K0 / 256)             // 160
#define B_W1 (HD * K1 / 256)             // 208
#define B_ZO ((NG + 255) / 256)          // 79
#define B_GC ((NP + 255) / 256)          // 782
#define B_CNT ((NE_ALL + 255) / 256)     // 10157
#define PRO_BLOCKS (B_RP + B_HC + B_W0 + B_W1 + B_ZO + B_GC + B_CNT)

// agg0 block ranges
#define TE_BLOCKS (NP * 2 * 16 / 256)    // 25000
#define AH_BLOCKS (NP * 16 / 256)        // 12500

// -------- static scratch (no allocations anywhere; zero-initialized) --------
__device__ __half g_Rp[(size_t)NP * RPW];
__device__ __half g_P1[(size_t)NP * HD];
__device__ __half g_Hc[(size_t)NH * HCW];
__device__ __half g_Xh[(size_t)NP * 32];
__device__ __half g_X[(size_t)NP * 256];
__device__ __half g_Wb0[HD * K0];
__device__ __half g_Wb1[HD * K1];
__device__ float g_bSum[2 * HD];
__device__ float g_GC[NG];
__device__ int g_cnt[SCAN_N];
__device__ int g_cur[SCAN_N];
__device__ int g_offs[SCAN_N];
__device__ int g_bsum[SCAN_BLOCKS];
__device__ int g_sorted[NE_ALL];

// ---------------------------- CSR build kernels ------------------------------
__global__ void scatter_all(const int* __restrict__ e_t, const int* __restrict__ e_e,
                            const int* __restrict__ e_h, const int* __restrict__ offs,
                            int* __restrict__ cur, int* __restrict__ sorted) {
    int i = blockIdx.x * blockDim.x + threadIdx.x;
    int s, d;
    if (i < NE_T) {
        s = e_t[i]; d = e_t[NE_T + i];
    } else if (i < NE_T + NE_E) {
        int j = i - NE_T;
        s = e_e[j]; d = NP + e_e[NE_E + j];
    } else if (i < NE_ALL) {
        int j = i - NE_T - NE_E;
        s = e_h[j]; d = 2 * NP + e_h[NE_H + j];
    } else return;
    int pos = offs[d] + atomicAdd(&cur[d], 1);
    sorted[pos] = s;
}

__global__ void scan1(const int* __restrict__ in, int* __restrict__ out, int* __restrict__ bsum) {
    __shared__ int ts[256];
    int base = blockIdx.x * 2048 + threadIdx.x * 8;
    int v[8];
    int s = 0;
#pragma unroll
    for (int j = 0; j < 8; j++) {
        int idx = base + j;
        v[j] = (idx < SCAN_N) ? in[idx] : 0;
        s += v[j];
    }
    ts[threadIdx.x] = s;
    __syncthreads();
    for (int off = 1; off < 256; off <<= 1) {
        int t = (threadIdx.x >= off) ? ts[threadIdx.x - off] : 0;
        __syncthreads();
        ts[threadIdx.x] += t;
        __syncthreads();
    }
    int run = ts[threadIdx.x] - s;
    if (threadIdx.x == 255) bsum[blockIdx.x] = ts[255];
#pragma unroll
    for (int j = 0; j < 8; j++) {
        int idx = base + j;
        if (idx < SCAN_N) out[idx] = run;
        run += v[j];
    }
}

__global__ void scan2(int* bsum, int n) {
    __shared__ int ts[512];
    int v = (threadIdx.x < n) ? bsum[threadIdx.x] : 0;
    ts[threadIdx.x] = v;
    __syncthreads();
    for (int off = 1; off < 512; off <<= 1) {
        int t = (threadIdx.x >= off) ? ts[threadIdx.x - off] : 0;
        __syncthreads();
        ts[threadIdx.x] += t;
        __syncthreads();
    }
    if (threadIdx.x < n) bsum[threadIdx.x] = ts[threadIdx.x] - v;
}

__global__ void scan3(int* out, const int* __restrict__ bsum) {
    int idx = blockIdx.x * blockDim.x + threadIdx.x;
    if (idx < SCAN_N) out[idx] += bsum[idx >> 11];
}

// ----------------------------- fused prologue --------------------------------
// Ranges: raw-player | raw-hist | Wb0 | Wb1 | zero-out | graph-counts | edge-count
__global__ __launch_bounds__(256) void prologue_k(
    const float* __restrict__ xp, const float* __restrict__ embp,
    const float* __restrict__ xh, const float* __restrict__ e0,
    const float* __restrict__ e3,
    const float* __restrict__ sWl, const float* __restrict__ sWr,
    const float* __restrict__ sb, const float* __restrict__ Wp,
    const float* __restrict__ bp, const float* __restrict__ Wh,
    const float* __restrict__ bh, const int* __restrict__ batch,
    const int* __restrict__ e_t, const int* __restrict__ e_e,
    const int* __restrict__ e_h,
    __half* __restrict__ Rp, __half* __restrict__ Hc,
    __half* __restrict__ Wb0, __half* __restrict__ Wb1,
    float* __restrict__ bS, float* __restrict__ out, float* __restrict__ gc,
    int* __restrict__ cnt) {
    int b = blockIdx.x;
    int t = threadIdx.x;
    if (b < B_RP) {
        int r = b * 256 + t;
        if (r >= NP) return;
        const float* x = xp + (size_t)r * 10;
        __half h[RPW];
        h[0] = __float2half(x[0]);
        h[1] = __float2half(x[6]);
        h[2] = __float2half(x[7]);
        h[3] = __float2half(x[8]);
        h[4] = __float2half(x[9]);
#pragma unroll
        for (int j = 0; j < 5; j++) {
            int ci = min(max((int)x[1 + j], 0), 199);
            const float* e = embp + ((size_t)j * 200 + ci) * 16;
#pragma unroll
            for (int q = 0; q < 16; q++) h[5 + j * 16 + q] = __float2half(e[q]);
        }
#pragma unroll
        for (int q = 85; q < RPW; q++) h[q] = __float2half(0.f);
#pragma unroll
        for (int q = 0; q < RPW / 8; q++)
            *(uint4*)(Rp + (size_t)r * RPW + q * 8) = *(uint4*)&h[q * 8];
        return;
    }
    b -= B_RP;
    if (b < B_HC) {
        int r = b * 256 + t;
        if (r >= NH) return;
        const float* x = xh + (size_t)r * 8;
        float f[32];
        f[0] = x[1]; f[1] = x[2]; f[2] = x[4]; f[3] = x[5]; f[4] = x[6]; f[5] = x[7];
        int c0 = min(max((int)x[0], 0), 1999);
        int c3 = min(max((int)x[3], 0), 9);
#pragma unroll
        for (int j = 0; j < 16; j++) f[6 + j] = e0[c0 * 16 + j];
#pragma unroll
        for (int j = 0; j < 4; j++) f[22 + j] = e3[c3 * 4 + j];
#pragma unroll
        for (int j = 26; j < 32; j++) f[j] = 0.f;
        __half h[32];
#pragma unroll
        for (int j = 0; j < 32; j++) h[j] = __float2half(f[j]);
#pragma unroll
        for (int q = 0; q < 4; q++)
            *(uint4*)(Hc + (size_t)r * HCW + q * 8) = *(uint4*)&h[q * 8];
        return;
    }
    b -= B_HC;
    if (b < B_W0) {
        int i = b * 256 + t;
        int o = i / K0, k = i - o * K0;
        float v = 0.f;
        if (k < 192) {
            int type = k / 96, kt = k - type * 96;
            const float* wl = sWl + ((size_t)type * HD + o) * HD;
            if (kt < 85) {
                for (int j = 0; j < HD; j++) v += wl[j] * Wp[j * 85 + kt];
            } else if (kt == 85) {
                for (int j = 0; j < HD; j++) v += wl[j] * bp[j];
            }
        } else if (k < 224) {
            int kh = k - 192;
            const float* wl = sWl + ((size_t)2 * HD + o) * HD;
            if (kh < 26) {
                for (int j = 0; j < HD; j++) v += wl[j] * Wh[j * 26 + kh];
            } else if (kh == 26) {
                for (int j = 0; j < HD; j++) v += wl[j] * bh[j];
            }
        } else {
            int ks = k - 224;
            if (ks < 85) {
                for (int j = 0; j < HD; j++) {
                    float wr = sWr[((size_t)0 * HD + o) * HD + j] +
                               sWr[((size_t)1 * HD + o) * HD + j] +
                               sWr[((size_t)2 * HD + o) * HD + j];
                    v += wr * Wp[j * 85 + ks];
                }
            }
        }
        Wb0[o * K0 + k] = __float2half(v);
        if (k == 0) {
            float bb = sb[0 * HD + o] + sb[1 * HD + o] + sb[2 * HD + o];
            for (int j = 0; j < HD; j++) {
                float wr = sWr[((size_t)0 * HD + o) * HD + j] +
                           sWr[((size_t)1 * HD + o) * HD + j] +
                           sWr[((size_t)2 * HD + o) * HD + j];
                bb += wr * bp[j];
            }
            bS[o] = bb;
        }
        return;
    }
    b -= B_W0;
    if (b < B_W1) {
        int i = b * 256 + t;
        int o = i / K1, k = i - o * K1;
        float v = 0.f;
        if (k < 256) {
            int part = k >> 7, kk = k & 127;
            v = sWl[((size_t)(3 + part) * HD + o) * HD + kk];
        } else if (k < 282) {
            int kh = k - 256;
            const float* wl = sWl + ((size_t)(3 + 2) * HD + o) * HD;
            for (int j = 0; j < HD; j++) v += wl[j] * Wh[j * 26 + kh];
        } else if (k == 282) {
            const float* wl = sWl + ((size_t)(3 + 2) * HD + o) * HD;
            for (int j = 0; j < HD; j++) v += wl[j] * bh[j];
        } else if (k < 288) {
            v = 0.f;
        } else {
            int kk = k - 288;
            v = sWr[((size_t)(3 + 0) * HD + o) * HD + kk] +
                sWr[((size_t)(3 + 1) * HD + o) * HD + kk] +
                sWr[((size_t)(3 + 2) * HD + o) * HD + kk];
        }
        Wb1[o * K1 + k] = __float2half(v);
        if (k == 0)
            bS[HD + o] = sb[(3 + 0) * HD + o] + sb[(3 + 1) * HD + o] +
                         sb[(3 + 2) * HD + o];
        return;
    }
    b -= B_W1;
    if (b < B_ZO) {
        int i = b * 256 + t;
        if (i < NG) out[i] = 0.f;
        return;
    }
    b -= B_ZO;
    if (b < B_GC) {
        int i = b * 256 + t;
        if (i < NP) atomicAdd(&gc[batch[i]], 1.0f);
        return;
    }
    b -= B_GC;
    {
        // ---- edge degree count (cnt zero at entry: static init / fin_k reset) ----
        int i = b * 256 + t;
        if (i < NE_T) {
            atomicAdd(&cnt[e_t[NE_T + i]], 1);
        } else if (i < NE_T + NE_E) {
            int j = i - NE_T;
            atomicAdd(&cnt[NP + e_e[NE_E + j]], 1);
        } else if (i < NE_ALL) {
            int j = i - NE_T - NE_E;
            atomicAdd(&cnt[2 * NP + e_h[NE_H + j]], 1);
        }
    }
}

// --------------------------- gather device bodies ----------------------------
__device__ __forceinline__ void acc8(float* a, uint4 v) {
    float2 f;
    f = __half22float2(*(__half2*)&v.x); a[0] += f.x; a[1] += f.y;
    f = __half22float2(*(__half2*)&v.y); a[2] += f.x; a[3] += f.y;
    f = __half22float2(*(__half2*)&v.z); a[4] += f.x; a[5] += f.y;
    f = __half22float2(*(__half2*)&v.w); a[6] += f.x; a[7] += f.y;
}

template <int SRCW>
__device__ __forceinline__ void agg_te_body(const __half* __restrict__ src,
                                            const int* __restrict__ sorted,
                                            const int* __restrict__ offs,
                                            const int* __restrict__ cnt,
                                            __half* __restrict__ X, int g) {
    constexpr int NL = SRCW / 8;
    int hw = g >> 4;
    int lane = threadIdx.x & 15;
    int hbase = threadIdx.x & 16;
    unsigned int mask = 0xFFFFu << hbase;
    int node = hw >> 1;
    int type = hw & 1;
    if (node >= NP) return;
    int start = offs[type * NP + node];
    int c = cnt[type * NP + node];
    bool io = (lane < NL);
    float a[8] = {0.f, 0.f, 0.f, 0.f, 0.f, 0.f, 0.f, 0.f};
    for (int e0 = 0; e0 < c; e0 += 16) {
        int my = (e0 + lane < c) ? sorted[start + e0 + lane] : 0;
        int n = min(16, c - e0);
        int e = 0;
        for (; e + 4 <= n; e += 4) {
            int s0 = __shfl_sync(mask, my, hbase + e);
            int s1 = __shfl_sync(mask, my, hbase + e + 1);
            int s2 = __shfl_sync(mask, my, hbase + e + 2);
            int s3 = __shfl_sync(mask, my, hbase + e + 3);
            if (io) {
                uint4 v0 = __ldg((const uint4*)(src + (size_t)s0 * SRCW + lane * 8));
                uint4 v1 = __ldg((const uint4*)(src + (size_t)s1 * SRCW + lane * 8));
                uint4 v2 = __ldg((const uint4*)(src + (size_t)s2 * SRCW + lane * 8));
                uint4 v3 = __ldg((const uint4*)(src + (size_t)s3 * SRCW + lane * 8));
                acc8(a, v0); acc8(a, v1); acc8(a, v2); acc8(a, v3);
            }
        }
        for (; e < n; e++) {
            int s = __shfl_sync(mask, my, hbase + e);
            if (io) {
                uint4 v = __ldg((const uint4*)(src + (size_t)s * SRCW + lane * 8));
                acc8(a, v);
            }
        }
    }
    if (!io) return;
    float inv = 1.0f / fmaxf((float)c, 1.0f);
    __half2 h0 = __floats2half2_rn(a[0] * inv, a[1] * inv);
    __half2 h1 = __floats2half2_rn(a[2] * inv, a[3] * inv);
    __half2 h2 = __floats2half2_rn(a[4] * inv, a[5] * inv);
    __half2 h3 = __floats2half2_rn(a[6] * inv, a[7] * inv);
    if (SRCW == RPW && lane == 10) {
        h2 = __floats2half2_rn(a[4] * inv, (c > 0) ? 1.f : 0.f);  // encoder-bias flag
        h3 = __floats2half2_rn(0.f, 0.f);
    }
    uint4 ov;
    ov.x = *(unsigned int*)&h0; ov.y = *(unsigned int*)&h1;
    ov.z = *(unsigned int*)&h2; ov.w = *(unsigned int*)&h3;
    // streaming store: X is read back sequentially by the GEMM; keep the
    // randomly-gathered source table (Rp / P1) resident in L2 instead.
    __stcs((uint4*)(X + (size_t)node * (2 * SRCW) + type * SRCW + lane * 8), ov);
}

__device__ __forceinline__ void agg_h_body(const __half* __restrict__ Hc,
                                           const int* __restrict__ sorted,
                                           const int* __restrict__ offs,
                                           const int* __restrict__ cnt,
                                           __half* __restrict__ Xh, int idx) {
    int hw = idx >> 4;
    int lane = threadIdx.x & 15;
    if (hw >= NP) return;
    int start = offs[hw], c = cnt[hw];
    float2 a = make_float2(0.f, 0.f);
    for (int e = 0; e < c; e++) {
        int s = __ldg(sorted + start + e);
        unsigned int v = __ldg((const unsigned int*)(Hc + (size_t)s * HCW + lane * 2));
        float2 f = __half22float2(*(__half2*)&v);
        a.x += f.x; a.y += f.y;
    }
    float inv = 1.0f / fmaxf((float)c, 1.0f);
    int col = lane * 2;
    float v0 = a.x * inv, v1 = a.y * inv;
    if (col == 26) { v0 = (c > 0) ? 1.f : 0.f; v1 = 0.f; }
    else if (col > 26) { v0 = 0.f; v1 = 0.f; }
    __half2 o = __floats2half2_rn(v0, v1);
    __stcs((int*)(Xh + (size_t)hw * 32 + col), *(int*)&o);
}

// ---- layer-0 aggregation: t/e gathers (range 0) + hist gathers (range 1) ----
__global__ __launch_bounds__(256) void agg0_k(const __half* __restrict__ Rp,
                                              const __half* __restrict__ Hc,
                                              const int* __restrict__ sorted,
                                              const int* __restrict__ offs,
                                              const int* __restrict__ cnt,
                                              __half* __restrict__ X,
                                              __half* __restrict__ Xh) {
    if (blockIdx.x < TE_BLOCKS) {
        agg_te_body<RPW>(Rp, sorted, offs, cnt, X, blockIdx.x * 256 + threadIdx.x);
    } else {
        int idx = (blockIdx.x - TE_BLOCKS) * 256 + threadIdx.x;
        agg_h_body(Hc, sorted, offs + 2 * NP, cnt + 2 * NP, Xh, idx);
    }
}

__global__ __launch_bounds__(256) void agg1_k(const __half* __restrict__ P1,
                                              const int* __restrict__ sorted,
                                              const int* __restrict__ offs,
                                              const int* __restrict__ cnt,
                                              __half* __restrict__ X) {
    agg_te_body<HD>(P1, sorted, offs, cnt, X, blockIdx.x * 256 + threadIdx.x);
}

// ------------------------------- cp.async ------------------------------------
__device__ __forceinline__ void cp16(void* smem, const void* gmem) {
    unsigned int s = (unsigned int)__cvta_generic_to_shared(smem);
    asm volatile("cp.async.cg.shared.global [%0], [%1], 16;" :: "r"(s), "l"(gmem));
}
__device__ __forceinline__ void cp_commit() { asm volatile("cp.async.commit_group;"); }
template <int N>
__device__ __forceinline__ void cp_wait() {
    asm volatile("cp.async.wait_group %0;" :: "n"(N));
}

// ------------------------------- fp16 MMA ------------------------------------
__device__ __forceinline__ void mma_f16(float* c, const unsigned int* a, const unsigned int* b) {
    asm volatile(
        "mma.sync.aligned.m16n8k16.row.col.f32.f16.f16.f32 "
        "{%0,%1,%2,%3}, {%4,%5,%6,%7}, {%8,%9}, {%0,%1,%2,%3};"
        : "+f"(c[0]), "+f"(c[1]), "+f"(c[2]), "+f"(c[3])
        : "r"(a[0]), "r"(a[1]), "r"(a[2]), "r"(a[3]), "r"(b[0]), "r"(b[1]));
}

__global__ __launch_bounds__(256) void sage_mma(const __half* __restrict__ Xte, int xtew,
                                                const __half* __restrict__ Xh,
                                                const __half* __restrict__ Ps, int psw,
                                                const __half* __restrict__ Wb, int wstride,
                                                int nChunks,
                                                const float* __restrict__ bS,
                                                __half* __restrict__ out,
                                                const int* __restrict__ batch,
                                                const float* __restrict__ Wc,
                                                float* __restrict__ pool_out,
                                                int do_pool) {
    __shared__ __half As[2][128 * ASW];
    __shared__ __half Bs[2][128 * ASW];
    int tid = threadIdx.x, wid = tid >> 5, lane = tid & 31;
    int gr = lane >> 2, tg = lane & 3;
    int rowBase = blockIdx.x * 128;
    int wm = (wid >> 1) * 32, wn = (wid & 1) * 64;

    int lr = tid >> 2;
    int lc8 = (tid & 3) * 8;

    auto issue = [&](int kc, int buf) {
#pragma unroll
        for (int t = 0; t < 2; t++) {
            int r = lr + t * 64;
            int row = min(rowBase + r, NP - 1);
            const __half* sp;
            if (kc < xtew)
                sp = Xte + (size_t)row * xtew + kc + lc8;
            else if (kc < xtew + 32)
                sp = Xh + (size_t)row * 32 + (kc - xtew) + lc8;
            else
                sp = Ps + (size_t)row * psw + (kc - xtew - 32) + lc8;
            cp16(&As[buf][r * ASW + lc8], sp);
            cp16(&Bs[buf][r * ASW + lc8], Wb + (size_t)r * wstride + kc + lc8);
        }
    };

    float acc[2][8][4];
#pragma unroll
    for (int i = 0; i < 2; i++)
#pragma unroll
        for (int j = 0; j < 8; j++)
#pragma unroll
            for (int k = 0; k < 4; k++) acc[i][j][k] = 0.f;

    issue(0, 0);
    cp_commit();
    for (int i = 0; i < nChunks; i++) {
        if (i + 1 < nChunks) {
            issue((i + 1) * 32, (i + 1) & 1);
            cp_commit();
            cp_wait<1>();
        } else {
            cp_wait<0>();
        }
        __syncthreads();
        const __half* Ab = As[i & 1];
        const __half* Bb = Bs[i & 1];
#pragma unroll
        for (int ks = 0; ks < 2; ks++) {
            int k0 = ks * 16;
            unsigned int a[2][4];
#pragma unroll
            for (int mt = 0; mt < 2; mt++) {
                int r = wm + mt * 16 + gr;
                a[mt][0] = *(const unsigned int*)&Ab[r * ASW + k0 + 2 * tg];
                a[mt][1] = *(const unsigned int*)&Ab[(r + 8) * ASW + k0 + 2 * tg];
                a[mt][2] = *(const unsigned int*)&Ab[r * ASW + k0 + 2 * tg + 8];
                a[mt][3] = *(const unsigned int*)&Ab[(r + 8) * ASW + k0 + 2 * tg + 8];
            }
#pragma unroll
            for (int nt = 0; nt < 8; nt++) {
                int n = wn + nt * 8 + gr;
                unsigned int b[2];
                b[0] = *(const unsigned int*)&Bb[n * ASW + k0 + 2 * tg];
                b[1] = *(const unsigned int*)&Bb[n * ASW + k0 + 2 * tg + 8];
                mma_f16(acc[0][nt], a[0], b);
                mma_f16(acc[1][nt], a[1], b);
            }
        }
        __syncthreads();
    }

    if (do_pool) {
        float ps[4] = {0.f, 0.f, 0.f, 0.f};
#pragma unroll
        for (int mt = 0; mt < 2; mt++)
#pragma unroll
            for (int nt = 0; nt < 8; nt++) {
                int col = wn + nt * 8 + 2 * tg;
                float w0 = Wc[col], w1 = Wc[col + 1];
                float b0 = bS[col], b1 = bS[col + 1];
                ps[mt * 2 + 0] += fmaxf(acc[mt][nt][0] + b0, 0.f) * w0 +
                                  fmaxf(acc[mt][nt][1] + b1, 0.f) * w1;
                ps[mt * 2 + 1] += fmaxf(acc[mt][nt][2] + b0, 0.f) * w0 +
                                  fmaxf(acc[mt][nt][3] + b1, 0.f) * w1;
            }
#pragma unroll
        for (int j = 0; j < 4; j++) {
            ps[j] += __shfl_xor_sync(0xFFFFFFFFu, ps[j], 1);
            ps[j] += __shfl_xor_sync(0xFFFFFFFFu, ps[j], 2);
        }
        if (tg == 0) {
#pragma unroll
            for (int mt = 0; mt < 2; mt++) {
                int r0 = rowBase + wm + mt * 16 + gr;
                int r1 = r0 + 8;
                if (r0 < NP) atomicAdd(&pool_out[batch[r0]], ps[mt * 2]);
                if (r1 < NP) atomicAdd(&pool_out[batch[r1]], ps[mt * 2 + 1]);
            }
        }
    } else {
#pragma unroll
        for (int mt = 0; mt < 2; mt++) {
#pragma unroll
            for (int nt = 0; nt < 8; nt++) {
                int col = wn + nt * 8 + 2 * tg;
                float b0 = bS[col], b1 = bS[col + 1];
                int r0 = rowBase + wm + mt * 16 + gr;
                if (r0 < NP) {
                    __half2 v = __floats2half2_rn(fmaxf(acc[mt][nt][0] + b0, 0.f),
                                                  fmaxf(acc[mt][nt][1] + b1, 0.f));
                    *(__half2*)(out + (size_t)r0 * HD + col) = v;
                }
                int r1 = r0 + 8;
                if (r1 < NP) {
                    __half2 v = __floats2half2_rn(fmaxf(acc[mt][nt][2] + b0, 0.f),
                                                  fmaxf(acc[mt][nt][3] + b1, 0.f));
                    *(__half2*)(out + (size_t)r1 * HD + col) = v;
                }
            }
        }
    }
}

// -------- finalize + reset scratch state for the next (replayed) call --------
__global__ void fin_k(float* out, float* gc, const float* __restrict__ bc,
                      int* cnt, int* cur) {
    int g = blockIdx.x * blockDim.x + threadIdx.x;
    if (g < NG) {
        out[g] = out[g] / fmaxf(gc[g], 1.0f) + bc[0];
        gc[g] = 0.f;
    }
    if (g < SCAN_N) { cnt[g] = 0; cur[g] = 0; }
}

// -------------------------------- launcher -----------------------------------
extern "C" void kernel_launch(void* const* d_in, const int* in_sizes, int n_in,
                              void* d_out, int out_size) {
    const float* x_player = (const float*)d_in[0];
    const float* x_hist   = (const float*)d_in[1];
    const int*   e_t      = (const int*)d_in[2];
    const int*   e_e      = (const int*)d_in[3];
    const int*   e_h      = (const int*)d_in[4];
    const int*   batch    = (const int*)d_in[5];
    const float* emb_p    = (const float*)d_in[6];
    const float* emb_h0   = (const float*)d_in[7];
    const float* emb_h3   = (const float*)d_in[8];
    const float* Wp       = (const float*)d_in[9];
    const float* bp       = (const float*)d_in[10];
    const float* Wh       = (const float*)d_in[11];
    const float* bh       = (const float*)d_in[12];
    const float* sWl      = (const float*)d_in[13];
    const float* sb       = (const float*)d_in[14];
    const float* sWr      = (const float*)d_in[15];
    const float* Wc       = (const float*)d_in[16];
    const float* bc       = (const float*)d_in[17];
    float* out = (float*)d_out;

    __half *Rp, *P1, *Hc, *Xh, *X, *Wb0, *Wb1;
    float *bS, *GC;
    int *cnt, *cur, *offs, *bsum, *sorted;
    cudaGetSymbolAddress((void**)&Rp, g_Rp);
    cudaGetSymbolAddress((void**)&P1, g_P1);
    cudaGetSymbolAddress((void**)&Hc, g_Hc);
    cudaGetSymbolAddress((void**)&Xh, g_Xh);
    cudaGetSymbolAddress((void**)&X, g_X);
    cudaGetSymbolAddress((void**)&Wb0, g_Wb0);
    cudaGetSymbolAddress((void**)&Wb1, g_Wb1);
    cudaGetSymbolAddress((void**)&bS, g_bSum);
    cudaGetSymbolAddress((void**)&GC, g_GC);
    cudaGetSymbolAddress((void**)&cnt, g_cnt);
    cudaGetSymbolAddress((void**)&cur, g_cur);
    cudaGetSymbolAddress((void**)&offs, g_offs);
    cudaGetSymbolAddress((void**)&bsum, g_bsum);
    cudaGetSymbolAddress((void**)&sorted, g_sorted);

    // 1) fused prologue (features, weights, out-zero, graph counts, edge counts)
    prologue_k<<<PRO_BLOCKS, 256>>>(x_player, emb_p, x_hist, emb_h0, emb_h3,
                                    sWl, sWr, sb, Wp, bp, Wh, bh, batch,
                                    e_t, e_e, e_h,
                                    Rp, Hc, Wb0, Wb1, bS, out, GC, cnt);

    // 2-5) CSR scan + scatter
    scan1<<<SCAN_BLOCKS, 256>>>(cnt, offs, bsum);
    scan2<<<1, 512>>>(bsum, SCAN_BLOCKS);
    scan3<<<(SCAN_N + 255) / 256, 256>>>(offs, bsum);
    scatter_all<<<(NE_ALL + 255) / 256, 256>>>(e_t, e_e, e_h, offs, cur, sorted);

    int mmaBlocks = (NP + 127) / 128;

    // 6) layer-0 gathers (t/e + hist fused)
    agg0_k<<<TE_BLOCKS + AH_BLOCKS, 256>>>(Rp, Hc, sorted, offs, cnt, X, Xh);

    // 7) layer-0 GEMM (K=320, folded encoder)
    sage_mma<<<mmaBlocks, 256>>>(X, 192, Xh, Rp, RPW, Wb0, K0, K0 / 32, bS,
                                 P1, batch, Wc, out, 0);

    // 8) layer-1 gathers
    agg1_k<<<TE_BLOCKS, 256>>>(P1, sorted, offs, cnt, X);

    // 9) layer-1 GEMM + fused pooling
    sage_mma<<<mmaBlocks, 256>>>(X, 256, Xh, P1, HD, Wb1, K1, K1 / 32, bS + HD,
                                 P1, batch, Wc, out, 1);

    // 10) finalize + state reset for next replay
    fin_k<<<(SCAN_N + 255) / 256, 256>>>(out, GC, bc, cnt, cur);
}

// round 14
// speedup vs baseline: 1.9770x; 1.0570x over previous
#include <cuda_runtime.h>
#include <cuda_fp16.h>
#include <cstdint>

#define NP 200000
#define NH 500000
#define NG 20000
#define NE_T 800000
#define NE_E 1000000
#define NE_H 500000
#define NE_ALL (NE_T + NE_E + NE_H)
#define HD 128
#define RPW 96              // raw player row width (85 -> 96)
#define HCW 32              // raw hist row width (26 -> 32)
#define K0 320              // layer-0 K: t96 | e96 | h32 | self96
#define K1 416              // layer-1 K: t128 | e128 | h32 | P128
#define ASW 40              // smem stage row stride (halfs)
#define SCAN_N (3 * NP)
#define SCAN_BLOCKS ((SCAN_N + 2047) / 2048)

// prologue block ranges
#define B_RP ((NP + 255) / 256)          // 782
#define B_HC ((NH + 255) / 256)          // 1954
#define B_W0 (HD * K0 / 256)             // 160
#define B_W1 (HD * K1 / 256)             // 208
#define B_ZO ((NG + 255) / 256)          // 79
#define B_GC ((NP + 255) / 256)          // 782
#define B_CNT ((NE_ALL + 255) / 256)     // 10157
#define PRO_BLOCKS (B_RP + B_HC + B_W0 + B_W1 + B_ZO + B_GC + B_CNT)

// agg block ranges: one WARP per node (both edge types)
#define TE_BLOCKS (NP * 32 / 256)        // 25000
#define AH_BLOCKS (NP * 16 / 256)        // 12500

// -------- static scratch (no allocations anywhere; zero-initialized) --------
__device__ __half g_Rp[(size_t)NP * RPW];
__device__ __half g_P1[(size_t)NP * HD];
__device__ __half g_Hc[(size_t)NH * HCW];
__device__ __half g_Xh[(size_t)NP * 32];
__device__ __half g_X[(size_t)NP * 256];
__device__ __half g_Wb0[HD * K0];
__device__ __half g_Wb1[HD * K1];
__device__ float g_bSum[2 * HD];
__device__ float g_GC[NG];
__device__ int g_cnt[SCAN_N];
__device__ int g_cur[SCAN_N];
__device__ int g_offs[SCAN_N];
__device__ int g_bsum[SCAN_BLOCKS];
__device__ int g_sorted[NE_ALL];

// ---------------------------- CSR build kernels ------------------------------
__global__ void scatter_all(const int* __restrict__ e_t, const int* __restrict__ e_e,
                            const int* __restrict__ e_h, const int* __restrict__ offs,
                            int* __restrict__ cur, int* __restrict__ sorted) {
    int i = blockIdx.x * blockDim.x + threadIdx.x;
    int s, d;
    if (i < NE_T) {
        s = e_t[i]; d = e_t[NE_T + i];
    } else if (i < NE_T + NE_E) {
        int j = i - NE_T;
        s = e_e[j]; d = NP + e_e[NE_E + j];
    } else if (i < NE_ALL) {
        int j = i - NE_T - NE_E;
        s = e_h[j]; d = 2 * NP + e_h[NE_H + j];
    } else return;
    int pos = offs[d] + atomicAdd(&cur[d], 1);
    sorted[pos] = s;
}

__global__ void scan1(const int* __restrict__ in, int* __restrict__ out, int* __restrict__ bsum) {
    __shared__ int ts[256];
    int base = blockIdx.x * 2048 + threadIdx.x * 8;
    int v[8];
    int s = 0;
#pragma unroll
    for (int j = 0; j < 8; j++) {
        int idx = base + j;
        v[j] = (idx < SCAN_N) ? in[idx] : 0;
        s += v[j];
    }
    ts[threadIdx.x] = s;
    __syncthreads();
    for (int off = 1; off < 256; off <<= 1) {
        int t = (threadIdx.x >= off) ? ts[threadIdx.x - off] : 0;
        __syncthreads();
        ts[threadIdx.x] += t;
        __syncthreads();
    }
    int run = ts[threadIdx.x] - s;
    if (threadIdx.x == 255) bsum[blockIdx.x] = ts[255];
#pragma unroll
    for (int j = 0; j < 8; j++) {
        int idx = base + j;
        if (idx < SCAN_N) out[idx] = run;
        run += v[j];
    }
}

__global__ void scan2(int* bsum, int n) {
    __shared__ int ts[512];
    int v = (threadIdx.x < n) ? bsum[threadIdx.x] : 0;
    ts[threadIdx.x] = v;
    __syncthreads();
    for (int off = 1; off < 512; off <<= 1) {
        int t = (threadIdx.x >= off) ? ts[threadIdx.x - off] : 0;
        __syncthreads();
        ts[threadIdx.x] += t;
        __syncthreads();
    }
    if (threadIdx.x < n) bsum[threadIdx.x] = ts[threadIdx.x] - v;
}

__global__ void scan3(int* out, const int* __restrict__ bsum) {
    int idx = blockIdx.x * blockDim.x + threadIdx.x;
    if (idx < SCAN_N) out[idx] += bsum[idx >> 11];
}

// ----------------------------- fused prologue --------------------------------
__global__ __launch_bounds__(256) void prologue_k(
    const float* __restrict__ xp, const float* __restrict__ embp,
    const float* __restrict__ xh, const float* __restrict__ e0,
    const float* __restrict__ e3,
    const float* __restrict__ sWl, const float* __restrict__ sWr,
    const float* __restrict__ sb, const float* __restrict__ Wp,
    const float* __restrict__ bp, const float* __restrict__ Wh,
    const float* __restrict__ bh, const int* __restrict__ batch,
    const int* __restrict__ e_t, const int* __restrict__ e_e,
    const int* __restrict__ e_h,
    __half* __restrict__ Rp, __half* __restrict__ Hc,
    __half* __restrict__ Wb0, __half* __restrict__ Wb1,
    float* __restrict__ bS, float* __restrict__ out, float* __restrict__ gc,
    int* __restrict__ cnt) {
    int b = blockIdx.x;
    int t = threadIdx.x;
    if (b < B_RP) {
        int r = b * 256 + t;
        if (r >= NP) return;
        const float* x = xp + (size_t)r * 10;
        __half h[RPW];
        h[0] = __float2half(x[0]);
        h[1] = __float2half(x[6]);
        h[2] = __float2half(x[7]);
        h[3] = __float2half(x[8]);
        h[4] = __float2half(x[9]);
#pragma unroll
        for (int j = 0; j < 5; j++) {
            int ci = min(max((int)x[1 + j], 0), 199);
            const float* e = embp + ((size_t)j * 200 + ci) * 16;
#pragma unroll
            for (int q = 0; q < 16; q++) h[5 + j * 16 + q] = __float2half(e[q]);
        }
#pragma unroll
        for (int q = 85; q < RPW; q++) h[q] = __float2half(0.f);
#pragma unroll
        for (int q = 0; q < RPW / 8; q++)
            *(uint4*)(Rp + (size_t)r * RPW + q * 8) = *(uint4*)&h[q * 8];
        return;
    }
    b -= B_RP;
    if (b < B_HC) {
        int r = b * 256 + t;
        if (r >= NH) return;
        const float* x = xh + (size_t)r * 8;
        float f[32];
        f[0] = x[1]; f[1] = x[2]; f[2] = x[4]; f[3] = x[5]; f[4] = x[6]; f[5] = x[7];
        int c0 = min(max((int)x[0], 0), 1999);
        int c3 = min(max((int)x[3], 0), 9);
#pragma unroll
        for (int j = 0; j < 16; j++) f[6 + j] = e0[c0 * 16 + j];
#pragma unroll
        for (int j = 0; j < 4; j++) f[22 + j] = e3[c3 * 4 + j];
#pragma unroll
        for (int j = 26; j < 32; j++) f[j] = 0.f;
        __half h[32];
#pragma unroll
        for (int j = 0; j < 32; j++) h[j] = __float2half(f[j]);
#pragma unroll
        for (int q = 0; q < 4; q++)
            *(uint4*)(Hc + (size_t)r * HCW + q * 8) = *(uint4*)&h[q * 8];
        return;
    }
    b -= B_HC;
    if (b < B_W0) {
        int i = b * 256 + t;
        int o = i / K0, k = i - o * K0;
        float v = 0.f;
        if (k < 192) {
            int type = k / 96, kt = k - type * 96;
            const float* wl = sWl + ((size_t)type * HD + o) * HD;
            if (kt < 85) {
                for (int j = 0; j < HD; j++) v += wl[j] * Wp[j * 85 + kt];
            } else if (kt == 85) {
                for (int j = 0; j < HD; j++) v += wl[j] * bp[j];
            }
        } else if (k < 224) {
            int kh = k - 192;
            const float* wl = sWl + ((size_t)2 * HD + o) * HD;
            if (kh < 26) {
                for (int j = 0; j < HD; j++) v += wl[j] * Wh[j * 26 + kh];
            } else if (kh == 26) {
                for (int j = 0; j < HD; j++) v += wl[j] * bh[j];
            }
        } else {
            int ks = k - 224;
            if (ks < 85) {
                for (int j = 0; j < HD; j++) {
                    float wr = sWr[((size_t)0 * HD + o) * HD + j] +
                               sWr[((size_t)1 * HD + o) * HD + j] +
                               sWr[((size_t)2 * HD + o) * HD + j];
                    v += wr * Wp[j * 85 + ks];
                }
            }
        }
        Wb0[o * K0 + k] = __float2half(v);
        if (k == 0) {
            float bb = sb[0 * HD + o] + sb[1 * HD + o] + sb[2 * HD + o];
            for (int j = 0; j < HD; j++) {
                float wr = sWr[((size_t)0 * HD + o) * HD + j] +
                           sWr[((size_t)1 * HD + o) * HD + j] +
                           sWr[((size_t)2 * HD + o) * HD + j];
                bb += wr * bp[j];
            }
            bS[o] = bb;
        }
        return;
    }
    b -= B_W0;
    if (b < B_W1) {
        int i = b * 256 + t;
        int o = i / K1, k = i - o * K1;
        float v = 0.f;
        if (k < 256) {
            int part = k >> 7, kk = k & 127;
            v = sWl[((size_t)(3 + part) * HD + o) * HD + kk];
        } else if (k < 282) {
            int kh = k - 256;
            const float* wl = sWl + ((size_t)(3 + 2) * HD + o) * HD;
            for (int j = 0; j < HD; j++) v += wl[j] * Wh[j * 26 + kh];
        } else if (k == 282) {
            const float* wl = sWl + ((size_t)(3 + 2) * HD + o) * HD;
            for (int j = 0; j < HD; j++) v += wl[j] * bh[j];
        } else if (k < 288) {
            v = 0.f;
        } else {
            int kk = k - 288;
            v = sWr[((size_t)(3 + 0) * HD + o) * HD + kk] +
                sWr[((size_t)(3 + 1) * HD + o) * HD + kk] +
                sWr[((size_t)(3 + 2) * HD + o) * HD + kk];
        }
        Wb1[o * K1 + k] = __float2half(v);
        if (k == 0)
            bS[HD + o] = sb[(3 + 0) * HD + o] + sb[(3 + 1) * HD + o] +
                         sb[(3 + 2) * HD + o];
        return;
    }
    b -= B_W1;
    if (b < B_ZO) {
        int i = b * 256 + t;
        if (i < NG) out[i] = 0.f;
        return;
    }
    b -= B_ZO;
    if (b < B_GC) {
        int i = b * 256 + t;
        if (i < NP) atomicAdd(&gc[batch[i]], 1.0f);
        return;
    }
    b -= B_GC;
    {
        int i = b * 256 + t;
        if (i < NE_T) {
            atomicAdd(&cnt[e_t[NE_T + i]], 1);
        } else if (i < NE_T + NE_E) {
            int j = i - NE_T;
            atomicAdd(&cnt[NP + e_e[NE_E + j]], 1);
        } else if (i < NE_ALL) {
            int j = i - NE_T - NE_E;
            atomicAdd(&cnt[2 * NP + e_h[NE_H + j]], 1);
        }
    }
}

// --------------------------- gather device bodies ----------------------------
__device__ __forceinline__ void acc8(float* a, uint4 v) {
    float2 f;
    f = __half22float2(*(__half2*)&v.x); a[0] += f.x; a[1] += f.y;
    f = __half22float2(*(__half2*)&v.y); a[2] += f.x; a[3] += f.y;
    f = __half22float2(*(__half2*)&v.z); a[4] += f.x; a[5] += f.y;
    f = __half22float2(*(__half2*)&v.w); a[6] += f.x; a[7] += f.y;
}

// predicated load: zero vector when s < 0 (fp16 +0 adds exactly nothing)
template <int SRCW>
__device__ __forceinline__ uint4 ld_row(const __half* __restrict__ src, int s, int lane) {
    if (s >= 0) return __ldg((const uint4*)(src + (size_t)s * SRCW + lane * 8));
    return make_uint4(0u, 0u, 0u, 0u);
}

// One WARP per node: lanes 0-15 aggregate the teammate list, lanes 16-31 the
// enemy list, in a single warp-uniform loop over cmax = max(c_t, c_e) so both
// streams' loads co-issue (no half-warp divergence; MLP 8/warp).
template <int SRCW>
__device__ __forceinline__ void agg_te_body(const __half* __restrict__ src,
                                            const int* __restrict__ sorted,
                                            const int* __restrict__ offs,
                                            const int* __restrict__ cnt,
                                            __half* __restrict__ X, int node) {
    constexpr int NL = SRCW / 8;
    int lane16 = threadIdx.x & 15;
    int hbase = threadIdx.x & 16;
    int type = hbase >> 4;
    if (node >= NP) return;
    int start = offs[type * NP + node];
    int c = cnt[type * NP + node];
    int cmax = max(c, __shfl_xor_sync(0xFFFFFFFFu, c, 16));
    bool io = (lane16 < NL);
    float a[8] = {0.f, 0.f, 0.f, 0.f, 0.f, 0.f, 0.f, 0.f};
    for (int e0 = 0; e0 < cmax; e0 += 16) {
        int my = (e0 + lane16 < c) ? sorted[start + e0 + lane16] : -1;
        int nmax = min(16, cmax - e0);
        int e = 0;
        for (; e + 4 <= nmax; e += 4) {
            int s0 = __shfl_sync(0xFFFFFFFFu, my, hbase + e);
            int s1 = __shfl_sync(0xFFFFFFFFu, my, hbase + e + 1);
            int s2 = __shfl_sync(0xFFFFFFFFu, my, hbase + e + 2);
            int s3 = __shfl_sync(0xFFFFFFFFu, my, hbase + e + 3);
            if (io) {
                uint4 v0 = ld_row<SRCW>(src, s0, lane16);
                uint4 v1 = ld_row<SRCW>(src, s1, lane16);
                uint4 v2 = ld_row<SRCW>(src, s2, lane16);
                uint4 v3 = ld_row<SRCW>(src, s3, lane16);
                acc8(a, v0); acc8(a, v1); acc8(a, v2); acc8(a, v3);
            }
        }
        for (; e < nmax; e++) {
            int s = __shfl_sync(0xFFFFFFFFu, my, hbase + e);
            if (io) {
                uint4 v = ld_row<SRCW>(src, s, lane16);
                acc8(a, v);
            }
        }
    }
    if (!io) return;
    float inv = 1.0f / fmaxf((float)c, 1.0f);
    __half2 h0 = __floats2half2_rn(a[0] * inv, a[1] * inv);
    __half2 h1 = __floats2half2_rn(a[2] * inv, a[3] * inv);
    __half2 h2 = __floats2half2_rn(a[4] * inv, a[5] * inv);
    __half2 h3 = __floats2half2_rn(a[6] * inv, a[7] * inv);
    if (SRCW == RPW && lane16 == 10) {
        h2 = __floats2half2_rn(a[4] * inv, (c > 0) ? 1.f : 0.f);  // encoder-bias flag
        h3 = __floats2half2_rn(0.f, 0.f);
    }
    uint4 ov;
    ov.x = *(unsigned int*)&h0; ov.y = *(unsigned int*)&h1;
    ov.z = *(unsigned int*)&h2; ov.w = *(unsigned int*)&h3;
    // streaming store: X is read back sequentially by the GEMM
    __stcs((uint4*)(X + (size_t)node * (2 * SRCW) + type * SRCW + lane16 * 8), ov);
}

__device__ __forceinline__ void agg_h_body(const __half* __restrict__ Hc,
                                           const int* __restrict__ sorted,
                                           const int* __restrict__ offs,
                                           const int* __restrict__ cnt,
                                           __half* __restrict__ Xh, int idx) {
    int hw = idx >> 4;
    int lane = threadIdx.x & 15;
    if (hw >= NP) return;
    int start = offs[hw], c = cnt[hw];
    float2 a = make_float2(0.f, 0.f);
    for (int e = 0; e < c; e++) {
        int s = __ldg(sorted + start + e);
        unsigned int v = __ldg((const unsigned int*)(Hc + (size_t)s * HCW + lane * 2));
        float2 f = __half22float2(*(__half2*)&v);
        a.x += f.x; a.y += f.y;
    }
    float inv = 1.0f / fmaxf((float)c, 1.0f);
    int col = lane * 2;
    float v0 = a.x * inv, v1 = a.y * inv;
    if (col == 26) { v0 = (c > 0) ? 1.f : 0.f; v1 = 0.f; }
    else if (col > 26) { v0 = 0.f; v1 = 0.f; }
    __half2 o = __floats2half2_rn(v0, v1);
    __stcs((int*)(Xh + (size_t)hw * 32 + col), *(int*)&o);
}

// ---- layer-0 aggregation: t/e gathers (range 0) + hist gathers (range 1) ----
__global__ __launch_bounds__(256) void agg0_k(const __half* __restrict__ Rp,
                                              const __half* __restrict__ Hc,
                                              const int* __restrict__ sorted,
                                              const int* __restrict__ offs,
                                              const int* __restrict__ cnt,
                                              __half* __restrict__ X,
                                              __half* __restrict__ Xh) {
    if (blockIdx.x < TE_BLOCKS) {
        int node = (blockIdx.x * 256 + threadIdx.x) >> 5;
        agg_te_body<RPW>(Rp, sorted, offs, cnt, X, node);
    } else {
        int idx = (blockIdx.x - TE_BLOCKS) * 256 + threadIdx.x;
        agg_h_body(Hc, sorted, offs + 2 * NP, cnt + 2 * NP, Xh, idx);
    }
}

__global__ __launch_bounds__(256) void agg1_k(const __half* __restrict__ P1,
                                              const int* __restrict__ sorted,
                                              const int* __restrict__ offs,
                                              const int* __restrict__ cnt,
                                              __half* __restrict__ X) {
    int node = (blockIdx.x * 256 + threadIdx.x) >> 5;
    agg_te_body<HD>(P1, sorted, offs, cnt, X, node);
}

// ------------------------------- cp.async ------------------------------------
__device__ __forceinline__ void cp16(void* smem, const void* gmem) {
    unsigned int s = (unsigned int)__cvta_generic_to_shared(smem);
    asm volatile("cp.async.cg.shared.global [%0], [%1], 16;" :: "r"(s), "l"(gmem));
}
__device__ __forceinline__ void cp_commit() { asm volatile("cp.async.commit_group;"); }
template <int N>
__device__ __forceinline__ void cp_wait() {
    asm volatile("cp.async.wait_group %0;" :: "n"(N));
}

// ------------------------------- fp16 MMA ------------------------------------
__device__ __forceinline__ void mma_f16(float* c, const unsigned int* a, const unsigned int* b) {
    asm volatile(
        "mma.sync.aligned.m16n8k16.row.col.f32.f16.f16.f32 "
        "{%0,%1,%2,%3}, {%4,%5,%6,%7}, {%8,%9}, {%0,%1,%2,%3};"
        : "+f"(c[0]), "+f"(c[1]), "+f"(c[2]), "+f"(c[3])
        : "r"(a[0]), "r"(a[1]), "r"(a[2]), "r"(a[3]), "r"(b[0]), "r"(b[1]));
}

__global__ __launch_bounds__(256) void sage_mma(const __half* __restrict__ Xte, int xtew,
                                                const __half* __restrict__ Xh,
                                                const __half* __restrict__ Ps, int psw,
                                                const __half* __restrict__ Wb, int wstride,
                                                int nChunks,
                                                const float* __restrict__ bS,
                                                __half* __restrict__ out,
                                                const int* __restrict__ batch,
                                                const float* __restrict__ Wc,
                                                float* __restrict__ pool_out,
                                                int do_pool) {
    __shared__ __half As[2][128 * ASW];
    __shared__ __half Bs[2][128 * ASW];
    int tid = threadIdx.x, wid = tid >> 5, lane = tid & 31;
    int gr = lane >> 2, tg = lane & 3;
    int rowBase = blockIdx.x * 128;
    int wm = (wid >> 1) * 32, wn = (wid & 1) * 64;

    int lr = tid >> 2;
    int lc8 = (tid & 3) * 8;

    auto issue = [&](int kc, int buf) {
#pragma unroll
        for (int t = 0; t < 2; t++) {
            int r = lr + t * 64;
            int row = min(rowBase + r, NP - 1);
            const __half* sp;
            if (kc < xtew)
                sp = Xte + (size_t)row * xtew + kc + lc8;
            else if (kc < xtew + 32)
                sp = Xh + (size_t)row * 32 + (kc - xtew) + lc8;
            else
                sp = Ps + (size_t)row * psw + (kc - xtew - 32) + lc8;
            cp16(&As[buf][r * ASW + lc8], sp);
            cp16(&Bs[buf][r * ASW + lc8], Wb + (size_t)r * wstride + kc + lc8);
        }
    };

    float acc[2][8][4];
#pragma unroll
    for (int i = 0; i < 2; i++)
#pragma unroll
        for (int j = 0; j < 8; j++)
#pragma unroll
            for (int k = 0; k < 4; k++) acc[i][j][k] = 0.f;

    issue(0, 0);
    cp_commit();
    for (int i = 0; i < nChunks; i++) {
        if (i + 1 < nChunks) {
            issue((i + 1) * 32, (i + 1) & 1);
            cp_commit();
            cp_wait<1>();
        } else {
            cp_wait<0>();
        }
        __syncthreads();
        const __half* Ab = As[i & 1];
        const __half* Bb = Bs[i & 1];
#pragma unroll
        for (int ks = 0; ks < 2; ks++) {
            int k0 = ks * 16;
            unsigned int a[2][4];
#pragma unroll
            for (int mt = 0; mt < 2; mt++) {
                int r = wm + mt * 16 + gr;
                a[mt][0] = *(const unsigned int*)&Ab[r * ASW + k0 + 2 * tg];
                a[mt][1] = *(const unsigned int*)&Ab[(r + 8) * ASW + k0 + 2 * tg];
                a[mt][2] = *(const unsigned int*)&Ab[r * ASW + k0 + 2 * tg + 8];
                a[mt][3] = *(const unsigned int*)&Ab[(r + 8) * ASW + k0 + 2 * tg + 8];
            }
#pragma unroll
            for (int nt = 0; nt < 8; nt++) {
                int n = wn + nt * 8 + gr;
                unsigned int b[2];
                b[0] = *(const unsigned int*)&Bb[n * ASW + k0 + 2 * tg];
                b[1] = *(const unsigned int*)&Bb[n * ASW + k0 + 2 * tg + 8];
                mma_f16(acc[0][nt], a[0], b);
                mma_f16(acc[1][nt], a[1], b);
            }
        }
        __syncthreads();
    }

    if (do_pool) {
        float ps[4] = {0.f, 0.f, 0.f, 0.f};
#pragma unroll
        for (int mt = 0; mt < 2; mt++)
#pragma unroll
            for (int nt = 0; nt < 8; nt++) {
                int col = wn + nt * 8 + 2 * tg;
                float w0 = Wc[col], w1 = Wc[col + 1];
                float b0 = bS[col], b1 = bS[col + 1];
                ps[mt * 2 + 0] += fmaxf(acc[mt][nt][0] + b0, 0.f) * w0 +
                                  fmaxf(acc[mt][nt][1] + b1, 0.f) * w1;
                ps[mt * 2 + 1] += fmaxf(acc[mt][nt][2] + b0, 0.f) * w0 +
                                  fmaxf(acc[mt][nt][3] + b1, 0.f) * w1;
            }
#pragma unroll
        for (int j = 0; j < 4; j++) {
            ps[j] += __shfl_xor_sync(0xFFFFFFFFu, ps[j], 1);
            ps[j] += __shfl_xor_sync(0xFFFFFFFFu, ps[j], 2);
        }
        if (tg == 0) {
#pragma unroll
            for (int mt = 0; mt < 2; mt++) {
                int r0 = rowBase + wm + mt * 16 + gr;
                int r1 = r0 + 8;
                if (r0 < NP) atomicAdd(&pool_out[batch[r0]], ps[mt * 2]);
                if (r1 < NP) atomicAdd(&pool_out[batch[r1]], ps[mt * 2 + 1]);
            }
        }
    } else {
#pragma unroll
        for (int mt = 0; mt < 2; mt++) {
#pragma unroll
            for (int nt = 0; nt < 8; nt++) {
                int col = wn + nt * 8 + 2 * tg;
                float b0 = bS[col], b1 = bS[col + 1];
                int r0 = rowBase + wm + mt * 16 + gr;
                if (r0 < NP) {
                    __half2 v = __floats2half2_rn(fmaxf(acc[mt][nt][0] + b0, 0.f),
                                                  fmaxf(acc[mt][nt][1] + b1, 0.f));
                    *(__half2*)(out + (size_t)r0 * HD + col) = v;
                }
                int r1 = r0 + 8;
                if (r1 < NP) {
                    __half2 v = __floats2half2_rn(fmaxf(acc[mt][nt][2] + b0, 0.f),
                                                  fmaxf(acc[mt][nt][3] + b1, 0.f));
                    *(__half2*)(out + (size_t)r1 * HD + col) = v;
                }
            }
        }
    }
}

// -------- finalize + reset scratch state for the next (replayed) call --------
__global__ void fin_k(float* out, float* gc, const float* __restrict__ bc,
                      int* cnt, int* cur) {
    int g = blockIdx.x * blockDim.x + threadIdx.x;
    if (g < NG) {
        out[g] = out[g] / fmaxf(gc[g], 1.0f) + bc[0];
        gc[g] = 0.f;
    }
    if (g < SCAN_N) { cnt[g] = 0; cur[g] = 0; }
}

// -------------------------------- launcher -----------------------------------
extern "C" void kernel_launch(void* const* d_in, const int* in_sizes, int n_in,
                              void* d_out, int out_size) {
    const float* x_player = (const float*)d_in[0];
    const float* x_hist   = (const float*)d_in[1];
    const int*   e_t      = (const int*)d_in[2];
    const int*   e_e      = (const int*)d_in[3];
    const int*   e_h      = (const int*)d_in[4];
    const int*   batch    = (const int*)d_in[5];
    const float* emb_p    = (const float*)d_in[6];
    const float* emb_h0   = (const float*)d_in[7];
    const float* emb_h3   = (const float*)d_in[8];
    const float* Wp       = (const float*)d_in[9];
    const float* bp       = (const float*)d_in[10];
    const float* Wh       = (const float*)d_in[11];
    const float* bh       = (const float*)d_in[12];
    const float* sWl      = (const float*)d_in[13];
    const float* sb       = (const float*)d_in[14];
    const float* sWr      = (const float*)d_in[15];
    const float* Wc       = (const float*)d_in[16];
    const float* bc       = (const float*)d_in[17];
    float* out = (float*)d_out;

    __half *Rp, *P1, *Hc, *Xh, *X, *Wb0, *Wb1;
    float *bS, *GC;
    int *cnt, *cur, *offs, *bsum, *sorted;
    cudaGetSymbolAddress((void**)&Rp, g_Rp);
    cudaGetSymbolAddress((void**)&P1, g_P1);
    cudaGetSymbolAddress((void**)&Hc, g_Hc);
    cudaGetSymbolAddress((void**)&Xh, g_Xh);
    cudaGetSymbolAddress((void**)&X, g_X);
    cudaGetSymbolAddress((void**)&Wb0, g_Wb0);
    cudaGetSymbolAddress((void**)&Wb1, g_Wb1);
    cudaGetSymbolAddress((void**)&bS, g_bSum);
    cudaGetSymbolAddress((void**)&GC, g_GC);
    cudaGetSymbolAddress((void**)&cnt, g_cnt);
    cudaGetSymbolAddress((void**)&cur, g_cur);
    cudaGetSymbolAddress((void**)&offs, g_offs);
    cudaGetSymbolAddress((void**)&bsum, g_bsum);
    cudaGetSymbolAddress((void**)&sorted, g_sorted);

    // 1) fused prologue (features, weights, out-zero, graph counts, edge counts)
    prologue_k<<<PRO_BLOCKS, 256>>>(x_player, emb_p, x_hist, emb_h0, emb_h3,
                                    sWl, sWr, sb, Wp, bp, Wh, bh, batch,
                                    e_t, e_e, e_h,
                                    Rp, Hc, Wb0, Wb1, bS, out, GC, cnt);

    // 2-5) CSR scan + scatter
    scan1<<<SCAN_BLOCKS, 256>>>(cnt, offs, bsum);
    scan2<<<1, 512>>>(bsum, SCAN_BLOCKS);
    scan3<<<(SCAN_N + 255) / 256, 256>>>(offs, bsum);
    scatter_all<<<(NE_ALL + 255) / 256, 256>>>(e_t, e_e, e_h, offs, cur, sorted);

    int mmaBlocks = (NP + 127) / 128;

    // 6) layer-0 gathers (t/e + hist fused)
    agg0_k<<<TE_BLOCKS + AH_BLOCKS, 256>>>(Rp, Hc, sorted, offs, cnt, X, Xh);

    // 7) layer-0 GEMM (K=320, folded encoder)
    sage_mma<<<mmaBlocks, 256>>>(X, 192, Xh, Rp, RPW, Wb0, K0, K0 / 32, bS,
                                 P1, batch, Wc, out, 0);

    // 8) layer-1 gathers
    agg1_k<<<TE_BLOCKS, 256>>>(P1, sorted, offs, cnt, X);

    // 9) layer-1 GEMM + fused pooling
    sage_mma<<<mmaBlocks, 256>>>(X, 256, Xh, P1, HD, Wb1, K1, K1 / 32, bS + HD,
                                 P1, batch, Wc, out, 1);

    // 10) finalize + state reset for next replay
    fin_k<<<(SCAN_N + 255) / 256, 256>>>(out, GC, bc, cnt, cur);
}

// round 15
// speedup vs baseline: 2.1490x; 1.0870x over previous
#include <cuda_runtime.h>
#include <cuda_fp16.h>
#include <cstdint>

#define NP 200000
#define NH 500000
#define NG 20000
#define NE_T 800000
#define NE_E 1000000
#define NE_H 500000
#define NE_ALL (NE_T + NE_E + NE_H)
#define HD 128
#define RPW 96              // raw player row width (85 -> 96)
#define HCW 32              // raw hist row width (26 -> 32)
#define K0 320              // layer-0 K: t96 | e96 | h32 | self96
#define K1 416              // layer-1 K: t128 | e128 | h32 | P128
#define ASW 40              // smem stage row stride (halfs)
#define NPW 4               // nodes per warp (gather pipeline depth)
#define SCAN_N (3 * NP)
#define SCAN_BLOCKS ((SCAN_N + 2047) / 2048)

// prologue block ranges
#define B_RP ((NP + 255) / 256)          // 782
#define B_HC ((NH + 255) / 256)          // 1954
#define B_W0 (HD * K0 / 256)             // 160
#define B_W1 (HD * K1 / 256)             // 208
#define B_ZO ((NG + 255) / 256)          // 79
#define B_GC ((NP + 255) / 256)          // 782
#define B_CNT ((NE_ALL + 255) / 256)     // 10157
#define PRO_BLOCKS (B_RP + B_HC + B_W0 + B_W1 + B_ZO + B_GC + B_CNT)

// agg block ranges: one WARP per NPW nodes (both edge types)
#define TE_BLOCKS (NP / NPW * 32 / 256)  // 6250
#define AH_BLOCKS (NP * 16 / 256)        // 12500

// -------- static scratch (no allocations anywhere; zero-initialized) --------
__device__ __half g_Rp[(size_t)NP * RPW];
__device__ __half g_P1[(size_t)NP * HD];
__device__ __half g_Hc[(size_t)NH * HCW];
__device__ __half g_Xh[(size_t)NP * 32];
__device__ __half g_X[(size_t)NP * 256];
__device__ __half g_Wb0[HD * K0];
__device__ __half g_Wb1[HD * K1];
__device__ float g_bSum[2 * HD];
__device__ float g_GC[NG];
__device__ int g_cnt[SCAN_N];
__device__ int g_cur[SCAN_N];
__device__ int g_offs[SCAN_N];
__device__ int g_bsum[SCAN_BLOCKS];
__device__ int g_sorted[NE_ALL];

// ---------------------------- CSR build kernels ------------------------------
__global__ void scatter_all(const int* __restrict__ e_t, const int* __restrict__ e_e,
                            const int* __restrict__ e_h, const int* __restrict__ offs,
                            int* __restrict__ cur, int* __restrict__ sorted) {
    int i = blockIdx.x * blockDim.x + threadIdx.x;
    int s, d;
    if (i < NE_T) {
        s = e_t[i]; d = e_t[NE_T + i];
    } else if (i < NE_T + NE_E) {
        int j = i - NE_T;
        s = e_e[j]; d = NP + e_e[NE_E + j];
    } else if (i < NE_ALL) {
        int j = i - NE_T - NE_E;
        s = e_h[j]; d = 2 * NP + e_h[NE_H + j];
    } else return;
    int pos = offs[d] + atomicAdd(&cur[d], 1);
    sorted[pos] = s;
}

__global__ void scan1(const int* __restrict__ in, int* __restrict__ out, int* __restrict__ bsum) {
    __shared__ int ts[256];
    int base = blockIdx.x * 2048 + threadIdx.x * 8;
    int v[8];
    int s = 0;
#pragma unroll
    for (int j = 0; j < 8; j++) {
        int idx = base + j;
        v[j] = (idx < SCAN_N) ? in[idx] : 0;
        s += v[j];
    }
    ts[threadIdx.x] = s;
    __syncthreads();
    for (int off = 1; off < 256; off <<= 1) {
        int t = (threadIdx.x >= off) ? ts[threadIdx.x - off] : 0;
        __syncthreads();
        ts[threadIdx.x] += t;
        __syncthreads();
    }
    int run = ts[threadIdx.x] - s;
    if (threadIdx.x == 255) bsum[blockIdx.x] = ts[255];
#pragma unroll
    for (int j = 0; j < 8; j++) {
        int idx = base + j;
        if (idx < SCAN_N) out[idx] = run;
        run += v[j];
    }
}

__global__ void scan2(int* bsum, int n) {
    __shared__ int ts[512];
    int v = (threadIdx.x < n) ? bsum[threadIdx.x] : 0;
    ts[threadIdx.x] = v;
    __syncthreads();
    for (int off = 1; off < 512; off <<= 1) {
        int t = (threadIdx.x >= off) ? ts[threadIdx.x - off] : 0;
        __syncthreads();
        ts[threadIdx.x] += t;
        __syncthreads();
    }
    if (threadIdx.x < n) bsum[threadIdx.x] = ts[threadIdx.x] - v;
}

__global__ void scan3(int* out, const int* __restrict__ bsum) {
    int idx = blockIdx.x * blockDim.x + threadIdx.x;
    if (idx < SCAN_N) out[idx] += bsum[idx >> 11];
}

// ----------------------------- fused prologue --------------------------------
__global__ __launch_bounds__(256) void prologue_k(
    const float* __restrict__ xp, const float* __restrict__ embp,
    const float* __restrict__ xh, const float* __restrict__ e0,
    const float* __restrict__ e3,
    const float* __restrict__ sWl, const float* __restrict__ sWr,
    const float* __restrict__ sb, const float* __restrict__ Wp,
    const float* __restrict__ bp, const float* __restrict__ Wh,
    const float* __restrict__ bh, const int* __restrict__ batch,
    const int* __restrict__ e_t, const int* __restrict__ e_e,
    const int* __restrict__ e_h,
    __half* __restrict__ Rp, __half* __restrict__ Hc,
    __half* __restrict__ Wb0, __half* __restrict__ Wb1,
    float* __restrict__ bS, float* __restrict__ out, float* __restrict__ gc,
    int* __restrict__ cnt) {
    int b = blockIdx.x;
    int t = threadIdx.x;
    if (b < B_RP) {
        int r = b * 256 + t;
        if (r >= NP) return;
        const float* x = xp + (size_t)r * 10;
        __half h[RPW];
        h[0] = __float2half(x[0]);
        h[1] = __float2half(x[6]);
        h[2] = __float2half(x[7]);
        h[3] = __float2half(x[8]);
        h[4] = __float2half(x[9]);
#pragma unroll
        for (int j = 0; j < 5; j++) {
            int ci = min(max((int)x[1 + j], 0), 199);
            const float* e = embp + ((size_t)j * 200 + ci) * 16;
#pragma unroll
            for (int q = 0; q < 16; q++) h[5 + j * 16 + q] = __float2half(e[q]);
        }
#pragma unroll
        for (int q = 85; q < RPW; q++) h[q] = __float2half(0.f);
#pragma unroll
        for (int q = 0; q < RPW / 8; q++)
            *(uint4*)(Rp + (size_t)r * RPW + q * 8) = *(uint4*)&h[q * 8];
        return;
    }
    b -= B_RP;
    if (b < B_HC) {
        int r = b * 256 + t;
        if (r >= NH) return;
        const float* x = xh + (size_t)r * 8;
        float f[32];
        f[0] = x[1]; f[1] = x[2]; f[2] = x[4]; f[3] = x[5]; f[4] = x[6]; f[5] = x[7];
        int c0 = min(max((int)x[0], 0), 1999);
        int c3 = min(max((int)x[3], 0), 9);
#pragma unroll
        for (int j = 0; j < 16; j++) f[6 + j] = e0[c0 * 16 + j];
#pragma unroll
        for (int j = 0; j < 4; j++) f[22 + j] = e3[c3 * 4 + j];
#pragma unroll
        for (int j = 26; j < 32; j++) f[j] = 0.f;
        __half h[32];
#pragma unroll
        for (int j = 0; j < 32; j++) h[j] = __float2half(f[j]);
#pragma unroll
        for (int q = 0; q < 4; q++)
            *(uint4*)(Hc + (size_t)r * HCW + q * 8) = *(uint4*)&h[q * 8];
        return;
    }
    b -= B_HC;
    if (b < B_W0) {
        int i = b * 256 + t;
        int o = i / K0, k = i - o * K0;
        float v = 0.f;
        if (k < 192) {
            int type = k / 96, kt = k - type * 96;
            const float* wl = sWl + ((size_t)type * HD + o) * HD;
            if (kt < 85) {
                for (int j = 0; j < HD; j++) v += wl[j] * Wp[j * 85 + kt];
            } else if (kt == 85) {
                for (int j = 0; j < HD; j++) v += wl[j] * bp[j];
            }
        } else if (k < 224) {
            int kh = k - 192;
            const float* wl = sWl + ((size_t)2 * HD + o) * HD;
            if (kh < 26) {
                for (int j = 0; j < HD; j++) v += wl[j] * Wh[j * 26 + kh];
            } else if (kh == 26) {
                for (int j = 0; j < HD; j++) v += wl[j] * bh[j];
            }
        } else {
            int ks = k - 224;
            if (ks < 85) {
                for (int j = 0; j < HD; j++) {
                    float wr = sWr[((size_t)0 * HD + o) * HD + j] +
                               sWr[((size_t)1 * HD + o) * HD + j] +
                               sWr[((size_t)2 * HD + o) * HD + j];
                    v += wr * Wp[j * 85 + ks];
                }
            }
        }
        Wb0[o * K0 + k] = __float2half(v);
        if (k == 0) {
            float bb = sb[0 * HD + o] + sb[1 * HD + o] + sb[2 * HD + o];
            for (int j = 0; j < HD; j++) {
                float wr = sWr[((size_t)0 * HD + o) * HD + j] +
                           sWr[((size_t)1 * HD + o) * HD + j] +
                           sWr[((size_t)2 * HD + o) * HD + j];
                bb += wr * bp[j];
            }
            bS[o] = bb;
        }
        return;
    }
    b -= B_W0;
    if (b < B_W1) {
        int i = b * 256 + t;
        int o = i / K1, k = i - o * K1;
        float v = 0.f;
        if (k < 256) {
            int part = k >> 7, kk = k & 127;
            v = sWl[((size_t)(3 + part) * HD + o) * HD + kk];
        } else if (k < 282) {
            int kh = k - 256;
            const float* wl = sWl + ((size_t)(3 + 2) * HD + o) * HD;
            for (int j = 0; j < HD; j++) v += wl[j] * Wh[j * 26 + kh];
        } else if (k == 282) {
            const float* wl = sWl + ((size_t)(3 + 2) * HD + o) * HD;
            for (int j = 0; j < HD; j++) v += wl[j] * bh[j];
        } else if (k < 288) {
            v = 0.f;
        } else {
            int kk = k - 288;
            v = sWr[((size_t)(3 + 0) * HD + o) * HD + kk] +
                sWr[((size_t)(3 + 1) * HD + o) * HD + kk] +
                sWr[((size_t)(3 + 2) * HD + o) * HD + kk];
        }
        Wb1[o * K1 + k] = __float2half(v);
        if (k == 0)
            bS[HD + o] = sb[(3 + 0) * HD + o] + sb[(3 + 1) * HD + o] +
                         sb[(3 + 2) * HD + o];
        return;
    }
    b -= B_W1;
    if (b < B_ZO) {
        int i = b * 256 + t;
        if (i < NG) out[i] = 0.f;
        return;
    }
    b -= B_ZO;
    if (b < B_GC) {
        int i = b * 256 + t;
        if (i < NP) atomicAdd(&gc[batch[i]], 1.0f);
        return;
    }
    b -= B_GC;
    {
        int i = b * 256 + t;
        if (i < NE_T) {
            atomicAdd(&cnt[e_t[NE_T + i]], 1);
        } else if (i < NE_T + NE_E) {
            int j = i - NE_T;
            atomicAdd(&cnt[NP + e_e[NE_E + j]], 1);
        } else if (i < NE_ALL) {
            int j = i - NE_T - NE_E;
            atomicAdd(&cnt[2 * NP + e_h[NE_H + j]], 1);
        }
    }
}

// --------------------------- gather device bodies ----------------------------
__device__ __forceinline__ void acc8(float* a, uint4 v) {
    float2 f;
    f = __half22float2(*(__half2*)&v.x); a[0] += f.x; a[1] += f.y;
    f = __half22float2(*(__half2*)&v.y); a[2] += f.x; a[3] += f.y;
    f = __half22float2(*(__half2*)&v.z); a[4] += f.x; a[5] += f.y;
    f = __half22float2(*(__half2*)&v.w); a[6] += f.x; a[7] += f.y;
}

// predicated load: zero vector when s < 0 (fp16 +0 adds exactly nothing)
template <int SRCW>
__device__ __forceinline__ uint4 ld_row(const __half* __restrict__ src, int s, int lane) {
    if (s >= 0) return __ldg((const uint4*)(src + (size_t)s * SRCW + lane * 8));
    return make_uint4(0u, 0u, 0u, 0u);
}

// Strip-mined warp gather: one warp handles NPW consecutive nodes, both edge
// types (lanes 0-15 teammate, 16-31 enemy), with a 3-stage rolling pipeline:
//   A: offs/cnt for node i+2,  B: index vector for node i+1,  C: rows node i.
// Index waves overlap row waves of the previous node -> ~1 exposed wave/node.
template <int SRCW>
__device__ __forceinline__ void agg_strip(const __half* __restrict__ src,
                                          const int* __restrict__ sorted,
                                          const int* __restrict__ offs,
                                          const int* __restrict__ cnt,
                                          __half* __restrict__ X, int nodeBase) {
    constexpr int NL = SRCW / 8;
    int lane16 = threadIdx.x & 15;
    int hbase = threadIdx.x & 16;
    int type = hbase >> 4;
    bool io = (lane16 < NL);

    int n0 = min(nodeBase, NP - 1);
    int n1 = min(nodeBase + 1, NP - 1);
    int st0 = offs[type * NP + n0], c0 = cnt[type * NP + n0];
    int st1 = offs[type * NP + n1], c1 = cnt[type * NP + n1];
    int my0 = (lane16 < c0) ? __ldg(sorted + st0 + lane16) : -1;

#pragma unroll
    for (int i = 0; i < NPW; i++) {
        // stage A: offsets for node i+2
        int st2 = 0, c2 = 0;
        if (i + 2 < NPW) {
            int n2 = min(nodeBase + i + 2, NP - 1);
            st2 = offs[type * NP + n2];
            c2 = cnt[type * NP + n2];
        }
        // stage B: index vector for node i+1
        int my1 = -1;
        if (i + 1 < NPW) my1 = (lane16 < c1) ? __ldg(sorted + st1 + lane16) : -1;

        // stage C: process node i
        int node = nodeBase + i;
        int cmax = max(c0, __shfl_xor_sync(0xFFFFFFFFu, c0, 16));
        float a[8] = {0.f, 0.f, 0.f, 0.f, 0.f, 0.f, 0.f, 0.f};
        int my = my0;
        for (int e0 = 0; e0 < cmax; e0 += 16) {
            if (e0 > 0) my = (e0 + lane16 < c0) ? __ldg(sorted + st0 + e0 + lane16) : -1;
            int nmax = min(16, cmax - e0);
            int e = 0;
            for (; e + 4 <= nmax; e += 4) {
                int s0 = __shfl_sync(0xFFFFFFFFu, my, hbase + e);
                int s1 = __shfl_sync(0xFFFFFFFFu, my, hbase + e + 1);
                int s2 = __shfl_sync(0xFFFFFFFFu, my, hbase + e + 2);
                int s3 = __shfl_sync(0xFFFFFFFFu, my, hbase + e + 3);
                if (io) {
                    uint4 v0 = ld_row<SRCW>(src, s0, lane16);
                    uint4 v1 = ld_row<SRCW>(src, s1, lane16);
                    uint4 v2 = ld_row<SRCW>(src, s2, lane16);
                    uint4 v3 = ld_row<SRCW>(src, s3, lane16);
                    acc8(a, v0); acc8(a, v1); acc8(a, v2); acc8(a, v3);
                }
            }
            for (; e < nmax; e++) {
                int s = __shfl_sync(0xFFFFFFFFu, my, hbase + e);
                if (io) {
                    uint4 v = ld_row<SRCW>(src, s, lane16);
                    acc8(a, v);
                }
            }
        }
        if (io && node < NP) {
            float inv = 1.0f / fmaxf((float)c0, 1.0f);
            __half2 h0 = __floats2half2_rn(a[0] * inv, a[1] * inv);
            __half2 h1 = __floats2half2_rn(a[2] * inv, a[3] * inv);
            __half2 h2 = __floats2half2_rn(a[4] * inv, a[5] * inv);
            __half2 h3 = __floats2half2_rn(a[6] * inv, a[7] * inv);
            if (SRCW == RPW && lane16 == 10) {
                h2 = __floats2half2_rn(a[4] * inv, (c0 > 0) ? 1.f : 0.f);
                h3 = __floats2half2_rn(0.f, 0.f);
            }
            uint4 ov;
            ov.x = *(unsigned int*)&h0; ov.y = *(unsigned int*)&h1;
            ov.z = *(unsigned int*)&h2; ov.w = *(unsigned int*)&h3;
            __stcs((uint4*)(X + (size_t)node * (2 * SRCW) + type * SRCW + lane16 * 8), ov);
        }
        // rotate pipeline
        st0 = st1; c0 = c1; my0 = my1;
        st1 = st2; c1 = c2;
    }
}

__device__ __forceinline__ void agg_h_body(const __half* __restrict__ Hc,
                                           const int* __restrict__ sorted,
                                           const int* __restrict__ offs,
                                           const int* __restrict__ cnt,
                                           __half* __restrict__ Xh, int idx) {
    int hw = idx >> 4;
    int lane = threadIdx.x & 15;
    if (hw >= NP) return;
    int start = offs[hw], c = cnt[hw];
    float2 a = make_float2(0.f, 0.f);
    for (int e = 0; e < c; e++) {
        int s = __ldg(sorted + start + e);
        unsigned int v = __ldg((const unsigned int*)(Hc + (size_t)s * HCW + lane * 2));
        float2 f = __half22float2(*(__half2*)&v);
        a.x += f.x; a.y += f.y;
    }
    float inv = 1.0f / fmaxf((float)c, 1.0f);
    int col = lane * 2;
    float v0 = a.x * inv, v1 = a.y * inv;
    if (col == 26) { v0 = (c > 0) ? 1.f : 0.f; v1 = 0.f; }
    else if (col > 26) { v0 = 0.f; v1 = 0.f; }
    __half2 o = __floats2half2_rn(v0, v1);
    __stcs((int*)(Xh + (size_t)hw * 32 + col), *(int*)&o);
}

// ---- layer-0 aggregation: t/e gathers (range 0) + hist gathers (range 1) ----
__global__ __launch_bounds__(256) void agg0_k(const __half* __restrict__ Rp,
                                              const __half* __restrict__ Hc,
                                              const int* __restrict__ sorted,
                                              const int* __restrict__ offs,
                                              const int* __restrict__ cnt,
                                              __half* __restrict__ X,
                                              __half* __restrict__ Xh) {
    if (blockIdx.x < TE_BLOCKS) {
        int warpId = (blockIdx.x * 256 + threadIdx.x) >> 5;
        agg_strip<RPW>(Rp, sorted, offs, cnt, X, warpId * NPW);
    } else {
        int idx = (blockIdx.x - TE_BLOCKS) * 256 + threadIdx.x;
        agg_h_body(Hc, sorted, offs + 2 * NP, cnt + 2 * NP, Xh, idx);
    }
}

__global__ __launch_bounds__(256) void agg1_k(const __half* __restrict__ P1,
                                              const int* __restrict__ sorted,
                                              const int* __restrict__ offs,
                                              const int* __restrict__ cnt,
                                              __half* __restrict__ X) {
    int warpId = (blockIdx.x * 256 + threadIdx.x) >> 5;
    agg_strip<HD>(P1, sorted, offs, cnt, X, warpId * NPW);
}

// ------------------------------- cp.async ------------------------------------
__device__ __forceinline__ void cp16(void* smem, const void* gmem) {
    unsigned int s = (unsigned int)__cvta_generic_to_shared(smem);
    asm volatile("cp.async.cg.shared.global [%0], [%1], 16;" :: "r"(s), "l"(gmem));
}
__device__ __forceinline__ void cp_commit() { asm volatile("cp.async.commit_group;"); }
template <int N>
__device__ __forceinline__ void cp_wait() {
    asm volatile("cp.async.wait_group %0;" :: "n"(N));
}

// ------------------------------- fp16 MMA ------------------------------------
__device__ __forceinline__ void mma_f16(float* c, const unsigned int* a, const unsigned int* b) {
    asm volatile(
        "mma.sync.aligned.m16n8k16.row.col.f32.f16.f16.f32 "
        "{%0,%1,%2,%3}, {%4,%5,%6,%7}, {%8,%9}, {%0,%1,%2,%3};"
        : "+f"(c[0]), "+f"(c[1]), "+f"(c[2]), "+f"(c[3])
        : "r"(a[0]), "r"(a[1]), "r"(a[2]), "r"(a[3]), "r"(b[0]), "r"(b[1]));
}

__global__ __launch_bounds__(256) void sage_mma(const __half* __restrict__ Xte, int xtew,
                                                const __half* __restrict__ Xh,
                                                const __half* __restrict__ Ps, int psw,
                                                const __half* __restrict__ Wb, int wstride,
                                                int nChunks,
                                                const float* __restrict__ bS,
                                                __half* __restrict__ out,
                                                const int* __restrict__ batch,
                                                const float* __restrict__ Wc,
                                                float* __restrict__ pool_out,
                                                int do_pool) {
    __shared__ __half As[2][128 * ASW];
    __shared__ __half Bs[2][128 * ASW];
    int tid = threadIdx.x, wid = tid >> 5, lane = tid & 31;
    int gr = lane >> 2, tg = lane & 3;
    int rowBase = blockIdx.x * 128;
    int wm = (wid >> 1) * 32, wn = (wid & 1) * 64;

    int lr = tid >> 2;
    int lc8 = (tid & 3) * 8;

    auto issue = [&](int kc, int buf) {
#pragma unroll
        for (int t = 0; t < 2; t++) {
            int r = lr + t * 64;
            int row = min(rowBase + r, NP - 1);
            const __half* sp;
            if (kc < xtew)
                sp = Xte + (size_t)row * xtew + kc + lc8;
            else if (kc < xtew + 32)
                sp = Xh + (size_t)row * 32 + (kc - xtew) + lc8;
            else
                sp = Ps + (size_t)row * psw + (kc - xtew - 32) + lc8;
            cp16(&As[buf][r * ASW + lc8], sp);
            cp16(&Bs[buf][r * ASW + lc8], Wb + (size_t)r * wstride + kc + lc8);
        }
    };

    float acc[2][8][4];
#pragma unroll
    for (int i = 0; i < 2; i++)
#pragma unroll
        for (int j = 0; j < 8; j++)
#pragma unroll
            for (int k = 0; k < 4; k++) acc[i][j][k] = 0.f;

    issue(0, 0);
    cp_commit();
    for (int i = 0; i < nChunks; i++) {
        if (i + 1 < nChunks) {
            issue((i + 1) * 32, (i + 1) & 1);
            cp_commit();
            cp_wait<1>();
        } else {
            cp_wait<0>();
        }
        __syncthreads();
        const __half* Ab = As[i & 1];
        const __half* Bb = Bs[i & 1];
#pragma unroll
        for (int ks = 0; ks < 2; ks++) {
            int k0 = ks * 16;
            unsigned int a[2][4];
#pragma unroll
            for (int mt = 0; mt < 2; mt++) {
                int r = wm + mt * 16 + gr;
                a[mt][0] = *(const unsigned int*)&Ab[r * ASW + k0 + 2 * tg];
                a[mt][1] = *(const unsigned int*)&Ab[(r + 8) * ASW + k0 + 2 * tg];
                a[mt][2] = *(const unsigned int*)&Ab[r * ASW + k0 + 2 * tg + 8];
                a[mt][3] = *(const unsigned int*)&Ab[(r + 8) * ASW + k0 + 2 * tg + 8];
            }
#pragma unroll
            for (int nt = 0; nt < 8; nt++) {
                int n = wn + nt * 8 + gr;
                unsigned int b[2];
                b[0] = *(const unsigned int*)&Bb[n * ASW + k0 + 2 * tg];
                b[1] = *(const unsigned int*)&Bb[n * ASW + k0 + 2 * tg + 8];
                mma_f16(acc[0][nt], a[0], b);
                mma_f16(acc[1][nt], a[1], b);
            }
        }
        __syncthreads();
    }

    if (do_pool) {
        float ps[4] = {0.f, 0.f, 0.f, 0.f};
#pragma unroll
        for (int mt = 0; mt < 2; mt++)
#pragma unroll
            for (int nt = 0; nt < 8; nt++) {
                int col = wn + nt * 8 + 2 * tg;
                float w0 = Wc[col], w1 = Wc[col + 1];
                float b0 = bS[col], b1 = bS[col + 1];
                ps[mt * 2 + 0] += fmaxf(acc[mt][nt][0] + b0, 0.f) * w0 +
                                  fmaxf(acc[mt][nt][1] + b1, 0.f) * w1;
                ps[mt * 2 + 1] += fmaxf(acc[mt][nt][2] + b0, 0.f) * w0 +
                                  fmaxf(acc[mt][nt][3] + b1, 0.f) * w1;
            }
#pragma unroll
        for (int j = 0; j < 4; j++) {
            ps[j] += __shfl_xor_sync(0xFFFFFFFFu, ps[j], 1);
            ps[j] += __shfl_xor_sync(0xFFFFFFFFu, ps[j], 2);
        }
        if (tg == 0) {
#pragma unroll
            for (int mt = 0; mt < 2; mt++) {
                int r0 = rowBase + wm + mt * 16 + gr;
                int r1 = r0 + 8;
                if (r0 < NP) atomicAdd(&pool_out[batch[r0]], ps[mt * 2]);
                if (r1 < NP) atomicAdd(&pool_out[batch[r1]], ps[mt * 2 + 1]);
            }
        }
    } else {
#pragma unroll
        for (int mt = 0; mt < 2; mt++) {
#pragma unroll
            for (int nt = 0; nt < 8; nt++) {
                int col = wn + nt * 8 + 2 * tg;
                float b0 = bS[col], b1 = bS[col + 1];
                int r0 = rowBase + wm + mt * 16 + gr;
                if (r0 < NP) {
                    __half2 v = __floats2half2_rn(fmaxf(acc[mt][nt][0] + b0, 0.f),
                                                  fmaxf(acc[mt][nt][1] + b1, 0.f));
                    *(__half2*)(out + (size_t)r0 * HD + col) = v;
                }
                int r1 = r0 + 8;
                if (r1 < NP) {
                    __half2 v = __floats2half2_rn(fmaxf(acc[mt][nt][2] + b0, 0.f),
                                                  fmaxf(acc[mt][nt][3] + b1, 0.f));
                    *(__half2*)(out + (size_t)r1 * HD + col) = v;
                }
            }
        }
    }
}

// -------- finalize + reset scratch state for the next (replayed) call --------
__global__ void fin_k(float* out, float* gc, const float* __restrict__ bc,
                      int* cnt, int* cur) {
    int g = blockIdx.x * blockDim.x + threadIdx.x;
    if (g < NG) {
        out[g] = out[g] / fmaxf(gc[g], 1.0f) + bc[0];
        gc[g] = 0.f;
    }
    if (g < SCAN_N) { cnt[g] = 0; cur[g] = 0; }
}

// -------------------------------- launcher -----------------------------------
extern "C" void kernel_launch(void* const* d_in, const int* in_sizes, int n_in,
                              void* d_out, int out_size) {
    const float* x_player = (const float*)d_in[0];
    const float* x_hist   = (const float*)d_in[1];
    const int*   e_t      = (const int*)d_in[2];
    const int*   e_e      = (const int*)d_in[3];
    const int*   e_h      = (const int*)d_in[4];
    const int*   batch    = (const int*)d_in[5];
    const float* emb_p    = (const float*)d_in[6];
    const float* emb_h0   = (const float*)d_in[7];
    const float* emb_h3   = (const float*)d_in[8];
    const float* Wp       = (const float*)d_in[9];
    const float* bp       = (const float*)d_in[10];
    const float* Wh       = (const float*)d_in[11];
    const float* bh       = (const float*)d_in[12];
    const float* sWl      = (const float*)d_in[13];
    const float* sb       = (const float*)d_in[14];
    const float* sWr      = (const float*)d_in[15];
    const float* Wc       = (const float*)d_in[16];
    const float* bc       = (const float*)d_in[17];
    float* out = (float*)d_out;

    __half *Rp, *P1, *Hc, *Xh, *X, *Wb0, *Wb1;
    float *bS, *GC;
    int *cnt, *cur, *offs, *bsum, *sorted;
    cudaGetSymbolAddress((void**)&Rp, g_Rp);
    cudaGetSymbolAddress((void**)&P1, g_P1);
    cudaGetSymbolAddress((void**)&Hc, g_Hc);
    cudaGetSymbolAddress((void**)&Xh, g_Xh);
    cudaGetSymbolAddress((void**)&X, g_X);
    cudaGetSymbolAddress((void**)&Wb0, g_Wb0);
    cudaGetSymbolAddress((void**)&Wb1, g_Wb1);
    cudaGetSymbolAddress((void**)&bS, g_bSum);
    cudaGetSymbolAddress((void**)&GC, g_GC);
    cudaGetSymbolAddress((void**)&cnt, g_cnt);
    cudaGetSymbolAddress((void**)&cur, g_cur);
    cudaGetSymbolAddress((void**)&offs, g_offs);
    cudaGetSymbolAddress((void**)&bsum, g_bsum);
    cudaGetSymbolAddress((void**)&sorted, g_sorted);

    // 1) fused prologue (features, weights, out-zero, graph counts, edge counts)
    prologue_k<<<PRO_BLOCKS, 256>>>(x_player, emb_p, x_hist, emb_h0, emb_h3,
                                    sWl, sWr, sb, Wp, bp, Wh, bh, batch,
                                    e_t, e_e, e_h,
                                    Rp, Hc, Wb0, Wb1, bS, out, GC, cnt);

    // 2-5) CSR scan + scatter
    scan1<<<SCAN_BLOCKS, 256>>>(cnt, offs, bsum);
    scan2<<<1, 512>>>(bsum, SCAN_BLOCKS);
    scan3<<<(SCAN_N + 255) / 256, 256>>>(offs, bsum);
    scatter_all<<<(NE_ALL + 255) / 256, 256>>>(e_t, e_e, e_h, offs, cur, sorted);

    int mmaBlocks = (NP + 127) / 128;

    // 6) layer-0 gathers (t/e strip-mined + hist fused)
    agg0_k<<<TE_BLOCKS + AH_BLOCKS, 256>>>(Rp, Hc, sorted, offs, cnt, X, Xh);

    // 7) layer-0 GEMM (K=320, folded encoder)
    sage_mma<<<mmaBlocks, 256>>>(X, 192, Xh, Rp, RPW, Wb0, K0, K0 / 32, bS,
                                 P1, batch, Wc, out, 0);

    // 8) layer-1 gathers (strip-mined)
    agg1_k<<<TE_BLOCKS, 256>>>(P1, sorted, offs, cnt, X);

    // 9) layer-1 GEMM + fused pooling
    sage_mma<<<mmaBlocks, 256>>>(X, 256, Xh, P1, HD, Wb1, K1, K1 / 32, bS + HD,
                                 P1, batch, Wc, out, 1);

    // 10) finalize + state reset for next replay
    fin_k<<<(SCAN_N + 255) / 256, 256>>>(out, GC, bc, cnt, cur);
}

// round 16
// speedup vs baseline: 2.1698x; 1.0097x over previous
#include <cuda_runtime.h>
#include <cuda_fp16.h>
#include <cstdint>

#define NP 200000
#define NH 500000
#define NG 20000
#define NE_T 800000
#define NE_E 1000000
#define NE_H 500000
#define NE_ALL (NE_T + NE_E + NE_H)
#define HD 128
#define RPW 96              // raw player row width (85 -> 96)
#define HCW 32              // raw hist row width (26 -> 32)
#define K0 320              // layer-0 K: t96 | e96 | h32 | self96
#define K1 416              // layer-1 K: t128 | e128 | h32 | P128
#define ASW 40              // smem stage row stride (halfs)
#define NPW 8               // nodes per warp (gather pipeline depth)
#define SCAN_N (3 * NP)
#define SCAN_BLOCKS ((SCAN_N + 2047) / 2048)

// prologue block ranges
#define B_RP ((NP + 255) / 256)          // 782
#define B_HC ((NH + 255) / 256)          // 1954
#define B_W0 (HD * K0 / 256)             // 160
#define B_W1 (HD * K1 / 256)             // 208
#define B_ZO ((NG + 255) / 256)          // 79
#define B_GC ((NP + 255) / 256)          // 782
#define B_CNT ((NE_ALL + 255) / 256)     // 10157
#define PRO_BLOCKS (B_RP + B_HC + B_W0 + B_W1 + B_ZO + B_GC + B_CNT)

// agg block ranges: one WARP per NPW nodes (both edge types)
#define TE_BLOCKS (NP / NPW * 32 / 256)  // 3125
#define AH_BLOCKS (NP * 16 / 256)        // 12500

// -------- static scratch (no allocations anywhere; zero-initialized) --------
__device__ __half g_Rp[(size_t)NP * RPW];
__device__ __half g_P1[(size_t)NP * HD];
__device__ __half g_Hc[(size_t)NH * HCW];
__device__ __half g_Xh[(size_t)NP * 32];
__device__ __half g_X[(size_t)NP * 256];
__device__ __half g_Wb0[HD * K0];
__device__ __half g_Wb1[HD * K1];
__device__ float g_bSum[2 * HD];
__device__ float g_GC[NG];
__device__ int g_cnt[SCAN_N];
__device__ int g_cur[SCAN_N];
__device__ int g_offs[SCAN_N];
__device__ int g_bsum[SCAN_BLOCKS];
__device__ int g_sorted[NE_ALL];

// ---------------------------- CSR build kernels ------------------------------
__global__ void scatter_all(const int* __restrict__ e_t, const int* __restrict__ e_e,
                            const int* __restrict__ e_h, const int* __restrict__ offs,
                            int* __restrict__ cur, int* __restrict__ sorted) {
    int i = blockIdx.x * blockDim.x + threadIdx.x;
    int s, d;
    if (i < NE_T) {
        s = e_t[i]; d = e_t[NE_T + i];
    } else if (i < NE_T + NE_E) {
        int j = i - NE_T;
        s = e_e[j]; d = NP + e_e[NE_E + j];
    } else if (i < NE_ALL) {
        int j = i - NE_T - NE_E;
        s = e_h[j]; d = 2 * NP + e_h[NE_H + j];
    } else return;
    int pos = offs[d] + atomicAdd(&cur[d], 1);
    sorted[pos] = s;
}

__global__ void scan1(const int* __restrict__ in, int* __restrict__ out, int* __restrict__ bsum) {
    __shared__ int ts[256];
    int base = blockIdx.x * 2048 + threadIdx.x * 8;
    int v[8];
    int s = 0;
#pragma unroll
    for (int j = 0; j < 8; j++) {
        int idx = base + j;
        v[j] = (idx < SCAN_N) ? in[idx] : 0;
        s += v[j];
    }
    ts[threadIdx.x] = s;
    __syncthreads();
    for (int off = 1; off < 256; off <<= 1) {
        int t = (threadIdx.x >= off) ? ts[threadIdx.x - off] : 0;
        __syncthreads();
        ts[threadIdx.x] += t;
        __syncthreads();
    }
    int run = ts[threadIdx.x] - s;
    if (threadIdx.x == 255) bsum[blockIdx.x] = ts[255];
#pragma unroll
    for (int j = 0; j < 8; j++) {
        int idx = base + j;
        if (idx < SCAN_N) out[idx] = run;
        run += v[j];
    }
}

__global__ void scan2(int* bsum, int n) {
    __shared__ int ts[512];
    int v = (threadIdx.x < n) ? bsum[threadIdx.x] : 0;
    ts[threadIdx.x] = v;
    __syncthreads();
    for (int off = 1; off < 512; off <<= 1) {
        int t = (threadIdx.x >= off) ? ts[threadIdx.x - off] : 0;
        __syncthreads();
        ts[threadIdx.x] += t;
        __syncthreads();
    }
    if (threadIdx.x < n) bsum[threadIdx.x] = ts[threadIdx.x] - v;
}

__global__ void scan3(int* out, const int* __restrict__ bsum) {
    int idx = blockIdx.x * blockDim.x + threadIdx.x;
    if (idx < SCAN_N) out[idx] += bsum[idx >> 11];
}

// ----------------------------- fused prologue --------------------------------
__global__ __launch_bounds__(256) void prologue_k(
    const float* __restrict__ xp, const float* __restrict__ embp,
    const float* __restrict__ xh, const float* __restrict__ e0,
    const float* __restrict__ e3,
    const float* __restrict__ sWl, const float* __restrict__ sWr,
    const float* __restrict__ sb, const float* __restrict__ Wp,
    const float* __restrict__ bp, const float* __restrict__ Wh,
    const float* __restrict__ bh, const int* __restrict__ batch,
    const int* __restrict__ e_t, const int* __restrict__ e_e,
    const int* __restrict__ e_h,
    __half* __restrict__ Rp, __half* __restrict__ Hc,
    __half* __restrict__ Wb0, __half* __restrict__ Wb1,
    float* __restrict__ bS, float* __restrict__ out, float* __restrict__ gc,
    int* __restrict__ cnt) {
    int b = blockIdx.x;
    int t = threadIdx.x;
    if (b < B_RP) {
        int r = b * 256 + t;
        if (r >= NP) return;
        const float* x = xp + (size_t)r * 10;
        __half h[RPW];
        h[0] = __float2half(x[0]);
        h[1] = __float2half(x[6]);
        h[2] = __float2half(x[7]);
        h[3] = __float2half(x[8]);
        h[4] = __float2half(x[9]);
#pragma unroll
        for (int j = 0; j < 5; j++) {
            int ci = min(max((int)x[1 + j], 0), 199);
            const float* e = embp + ((size_t)j * 200 + ci) * 16;
#pragma unroll
            for (int q = 0; q < 16; q++) h[5 + j * 16 + q] = __float2half(e[q]);
        }
#pragma unroll
        for (int q = 85; q < RPW; q++) h[q] = __float2half(0.f);
#pragma unroll
        for (int q = 0; q < RPW / 8; q++)
            *(uint4*)(Rp + (size_t)r * RPW + q * 8) = *(uint4*)&h[q * 8];
        return;
    }
    b -= B_RP;
    if (b < B_HC) {
        int r = b * 256 + t;
        if (r >= NH) return;
        const float* x = xh + (size_t)r * 8;
        float f[32];
        f[0] = x[1]; f[1] = x[2]; f[2] = x[4]; f[3] = x[5]; f[4] = x[6]; f[5] = x[7];
        int c0 = min(max((int)x[0], 0), 1999);
        int c3 = min(max((int)x[3], 0), 9);
#pragma unroll
        for (int j = 0; j < 16; j++) f[6 + j] = e0[c0 * 16 + j];
#pragma unroll
        for (int j = 0; j < 4; j++) f[22 + j] = e3[c3 * 4 + j];
#pragma unroll
        for (int j = 26; j < 32; j++) f[j] = 0.f;
        __half h[32];
#pragma unroll
        for (int j = 0; j < 32; j++) h[j] = __float2half(f[j]);
#pragma unroll
        for (int q = 0; q < 4; q++)
            *(uint4*)(Hc + (size_t)r * HCW + q * 8) = *(uint4*)&h[q * 8];
        return;
    }
    b -= B_HC;
    if (b < B_W0) {
        int i = b * 256 + t;
        int o = i / K0, k = i - o * K0;
        float v = 0.f;
        if (k < 192) {
            int type = k / 96, kt = k - type * 96;
            const float* wl = sWl + ((size_t)type * HD + o) * HD;
            if (kt < 85) {
                for (int j = 0; j < HD; j++) v += wl[j] * Wp[j * 85 + kt];
            } else if (kt == 85) {
                for (int j = 0; j < HD; j++) v += wl[j] * bp[j];
            }
        } else if (k < 224) {
            int kh = k - 192;
            const float* wl = sWl + ((size_t)2 * HD + o) * HD;
            if (kh < 26) {
                for (int j = 0; j < HD; j++) v += wl[j] * Wh[j * 26 + kh];
            } else if (kh == 26) {
                for (int j = 0; j < HD; j++) v += wl[j] * bh[j];
            }
        } else {
            int ks = k - 224;
            if (ks < 85) {
                for (int j = 0; j < HD; j++) {
                    float wr = sWr[((size_t)0 * HD + o) * HD + j] +
                               sWr[((size_t)1 * HD + o) * HD + j] +
                               sWr[((size_t)2 * HD + o) * HD + j];
                    v += wr * Wp[j * 85 + ks];
                }
            }
        }
        Wb0[o * K0 + k] = __float2half(v);
        if (k == 0) {
            float bb = sb[0 * HD + o] + sb[1 * HD + o] + sb[2 * HD + o];
            for (int j = 0; j < HD; j++) {
                float wr = sWr[((size_t)0 * HD + o) * HD + j] +
                           sWr[((size_t)1 * HD + o) * HD + j] +
                           sWr[((size_t)2 * HD + o) * HD + j];
                bb += wr * bp[j];
            }
            bS[o] = bb;
        }
        return;
    }
    b -= B_W0;
    if (b < B_W1) {
        int i = b * 256 + t;
        int o = i / K1, k = i - o * K1;
        float v = 0.f;
        if (k < 256) {
            int part = k >> 7, kk = k & 127;
            v = sWl[((size_t)(3 + part) * HD + o) * HD + kk];
        } else if (k < 282) {
            int kh = k - 256;
            const float* wl = sWl + ((size_t)(3 + 2) * HD + o) * HD;
            for (int j = 0; j < HD; j++) v += wl[j] * Wh[j * 26 + kh];
        } else if (k == 282) {
            const float* wl = sWl + ((size_t)(3 + 2) * HD + o) * HD;
            for (int j = 0; j < HD; j++) v += wl[j] * bh[j];
        } else if (k < 288) {
            v = 0.f;
        } else {
            int kk = k - 288;
            v = sWr[((size_t)(3 + 0) * HD + o) * HD + kk] +
                sWr[((size_t)(3 + 1) * HD + o) * HD + kk] +
                sWr[((size_t)(3 + 2) * HD + o) * HD + kk];
        }
        Wb1[o * K1 + k] = __float2half(v);
        if (k == 0)
            bS[HD + o] = sb[(3 + 0) * HD + o] + sb[(3 + 1) * HD + o] +
                         sb[(3 + 2) * HD + o];
        return;
    }
    b -= B_W1;
    if (b < B_ZO) {
        int i = b * 256 + t;
        if (i < NG) out[i] = 0.f;
        return;
    }
    b -= B_ZO;
    if (b < B_GC) {
        int i = b * 256 + t;
        if (i < NP) atomicAdd(&gc[batch[i]], 1.0f);
        return;
    }
    b -= B_GC;
    {
        int i = b * 256 + t;
        if (i < NE_T) {
            atomicAdd(&cnt[e_t[NE_T + i]], 1);
        } else if (i < NE_T + NE_E) {
            int j = i - NE_T;
            atomicAdd(&cnt[NP + e_e[NE_E + j]], 1);
        } else if (i < NE_ALL) {
            int j = i - NE_T - NE_E;
            atomicAdd(&cnt[2 * NP + e_h[NE_H + j]], 1);
        }
    }
}

// --------------------------- gather device bodies ----------------------------
__device__ __forceinline__ void acc8(float* a, uint4 v) {
    float2 f;
    f = __half22float2(*(__half2*)&v.x); a[0] += f.x; a[1] += f.y;
    f = __half22float2(*(__half2*)&v.y); a[2] += f.x; a[3] += f.y;
    f = __half22float2(*(__half2*)&v.z); a[4] += f.x; a[5] += f.y;
    f = __half22float2(*(__half2*)&v.w); a[6] += f.x; a[7] += f.y;
}

// predicated load: zero vector when s < 0 (fp16 +0 adds exactly nothing)
template <int SRCW>
__device__ __forceinline__ uint4 ld_row(const __half* __restrict__ src, int s, int lane) {
    if (s >= 0) return __ldg((const uint4*)(src + (size_t)s * SRCW + lane * 8));
    return make_uint4(0u, 0u, 0u, 0u);
}

// Strip-mined warp gather: one warp handles NPW consecutive nodes, both edge
// types (lanes 0-15 teammate, 16-31 enemy), with a 3-stage rolling pipeline:
//   A: offs/cnt for node i+2,  B: index vector for node i+1,  C: rows node i.
template <int SRCW>
__device__ __forceinline__ void agg_strip(const __half* __restrict__ src,
                                          const int* __restrict__ sorted,
                                          const int* __restrict__ offs,
                                          const int* __restrict__ cnt,
                                          __half* __restrict__ X, int nodeBase) {
    constexpr int NL = SRCW / 8;
    int lane16 = threadIdx.x & 15;
    int hbase = threadIdx.x & 16;
    int type = hbase >> 4;
    bool io = (lane16 < NL);

    int n0 = min(nodeBase, NP - 1);
    int n1 = min(nodeBase + 1, NP - 1);
    int st0 = offs[type * NP + n0], c0 = cnt[type * NP + n0];
    int st1 = offs[type * NP + n1], c1 = cnt[type * NP + n1];
    int my0 = (lane16 < c0) ? __ldg(sorted + st0 + lane16) : -1;

#pragma unroll
    for (int i = 0; i < NPW; i++) {
        // stage A: offsets for node i+2
        int st2 = 0, c2 = 0;
        if (i + 2 < NPW) {
            int n2 = min(nodeBase + i + 2, NP - 1);
            st2 = offs[type * NP + n2];
            c2 = cnt[type * NP + n2];
        }
        // stage B: index vector for node i+1
        int my1 = -1;
        if (i + 1 < NPW) my1 = (lane16 < c1) ? __ldg(sorted + st1 + lane16) : -1;

        // stage C: process node i
        int node = nodeBase + i;
        int cmax = max(c0, __shfl_xor_sync(0xFFFFFFFFu, c0, 16));
        float a[8] = {0.f, 0.f, 0.f, 0.f, 0.f, 0.f, 0.f, 0.f};
        int my = my0;
        for (int e0 = 0; e0 < cmax; e0 += 16) {
            if (e0 > 0) my = (e0 + lane16 < c0) ? __ldg(sorted + st0 + e0 + lane16) : -1;
            int nmax = min(16, cmax - e0);
            int e = 0;
            for (; e + 4 <= nmax; e += 4) {
                int s0 = __shfl_sync(0xFFFFFFFFu, my, hbase + e);
                int s1 = __shfl_sync(0xFFFFFFFFu, my, hbase + e + 1);
                int s2 = __shfl_sync(0xFFFFFFFFu, my, hbase + e + 2);
                int s3 = __shfl_sync(0xFFFFFFFFu, my, hbase + e + 3);
                if (io) {
                    uint4 v0 = ld_row<SRCW>(src, s0, lane16);
                    uint4 v1 = ld_row<SRCW>(src, s1, lane16);
                    uint4 v2 = ld_row<SRCW>(src, s2, lane16);
                    uint4 v3 = ld_row<SRCW>(src, s3, lane16);
                    acc8(a, v0); acc8(a, v1); acc8(a, v2); acc8(a, v3);
                }
            }
            for (; e < nmax; e++) {
                int s = __shfl_sync(0xFFFFFFFFu, my, hbase + e);
                if (io) {
                    uint4 v = ld_row<SRCW>(src, s, lane16);
                    acc8(a, v);
                }
            }
        }
        if (io && node < NP) {
            float inv = 1.0f / fmaxf((float)c0, 1.0f);
            __half2 h0 = __floats2half2_rn(a[0] * inv, a[1] * inv);
            __half2 h1 = __floats2half2_rn(a[2] * inv, a[3] * inv);
            __half2 h2 = __floats2half2_rn(a[4] * inv, a[5] * inv);
            __half2 h3 = __floats2half2_rn(a[6] * inv, a[7] * inv);
            if (SRCW == RPW && lane16 == 10) {
                h2 = __floats2half2_rn(a[4] * inv, (c0 > 0) ? 1.f : 0.f);
                h3 = __floats2half2_rn(0.f, 0.f);
            }
            uint4 ov;
            ov.x = *(unsigned int*)&h0; ov.y = *(unsigned int*)&h1;
            ov.z = *(unsigned int*)&h2; ov.w = *(unsigned int*)&h3;
            __stcs((uint4*)(X + (size_t)node * (2 * SRCW) + type * SRCW + lane16 * 8), ov);
        }
        // rotate pipeline
        st0 = st1; c0 = c1; my0 = my1;
        st1 = st2; c1 = c2;
    }
}

// hist gather: half-warp per node, MLP-4 unrolled (4 broadcast index loads,
// then 4 independent row loads in flight).
__device__ __forceinline__ void agg_h_body(const __half* __restrict__ Hc,
                                           const int* __restrict__ sorted,
                                           const int* __restrict__ offs,
                                           const int* __restrict__ cnt,
                                           __half* __restrict__ Xh, int idx) {
    int hw = idx >> 4;
    int lane = threadIdx.x & 15;
    if (hw >= NP) return;
    int start = offs[hw], c = cnt[hw];
    float2 a = make_float2(0.f, 0.f);
    int e = 0;
    for (; e + 4 <= c; e += 4) {
        int s0 = __ldg(sorted + start + e);
        int s1 = __ldg(sorted + start + e + 1);
        int s2 = __ldg(sorted + start + e + 2);
        int s3 = __ldg(sorted + start + e + 3);
        unsigned int v0 = __ldg((const unsigned int*)(Hc + (size_t)s0 * HCW + lane * 2));
        unsigned int v1 = __ldg((const unsigned int*)(Hc + (size_t)s1 * HCW + lane * 2));
        unsigned int v2 = __ldg((const unsigned int*)(Hc + (size_t)s2 * HCW + lane * 2));
        unsigned int v3 = __ldg((const unsigned int*)(Hc + (size_t)s3 * HCW + lane * 2));
        float2 f;
        f = __half22float2(*(__half2*)&v0); a.x += f.x; a.y += f.y;
        f = __half22float2(*(__half2*)&v1); a.x += f.x; a.y += f.y;
        f = __half22float2(*(__half2*)&v2); a.x += f.x; a.y += f.y;
        f = __half22float2(*(__half2*)&v3); a.x += f.x; a.y += f.y;
    }
    for (; e < c; e++) {
        int s = __ldg(sorted + start + e);
        unsigned int v = __ldg((const unsigned int*)(Hc + (size_t)s * HCW + lane * 2));
        float2 f = __half22float2(*(__half2*)&v);
        a.x += f.x; a.y += f.y;
    }
    float inv = 1.0f / fmaxf((float)c, 1.0f);
    int col = lane * 2;
    float v0 = a.x * inv, v1 = a.y * inv;
    if (col == 26) { v0 = (c > 0) ? 1.f : 0.f; v1 = 0.f; }
    else if (col > 26) { v0 = 0.f; v1 = 0.f; }
    __half2 o = __floats2half2_rn(v0, v1);
    __stcs((int*)(Xh + (size_t)hw * 32 + col), *(int*)&o);
}

// ---- layer-0 aggregation: t/e gathers (range 0) + hist gathers (range 1) ----
__global__ __launch_bounds__(256) void agg0_k(const __half* __restrict__ Rp,
                                              const __half* __restrict__ Hc,
                                              const int* __restrict__ sorted,
                                              const int* __restrict__ offs,
                                              const int* __restrict__ cnt,
                                              __half* __restrict__ X,
                                              __half* __restrict__ Xh) {
    if (blockIdx.x < TE_BLOCKS) {
        int warpId = (blockIdx.x * 256 + threadIdx.x) >> 5;
        agg_strip<RPW>(Rp, sorted, offs, cnt, X, warpId * NPW);
    } else {
        int idx = (blockIdx.x - TE_BLOCKS) * 256 + threadIdx.x;
        agg_h_body(Hc, sorted, offs + 2 * NP, cnt + 2 * NP, Xh, idx);
    }
}

__global__ __launch_bounds__(256) void agg1_k(const __half* __restrict__ P1,
                                              const int* __restrict__ sorted,
                                              const int* __restrict__ offs,
                                              const int* __restrict__ cnt,
                                              __half* __restrict__ X) {
    int warpId = (blockIdx.x * 256 + threadIdx.x) >> 5;
    agg_strip<HD>(P1, sorted, offs, cnt, X, warpId * NPW);
}

// ------------------------------- cp.async ------------------------------------
__device__ __forceinline__ void cp16(void* smem, const void* gmem) {
    unsigned int s = (unsigned int)__cvta_generic_to_shared(smem);
    asm volatile("cp.async.cg.shared.global [%0], [%1], 16;" :: "r"(s), "l"(gmem));
}
__device__ __forceinline__ void cp_commit() { asm volatile("cp.async.commit_group;"); }
template <int N>
__device__ __forceinline__ void cp_wait() {
    asm volatile("cp.async.wait_group %0;" :: "n"(N));
}

// ------------------------------- fp16 MMA ------------------------------------
__device__ __forceinline__ void mma_f16(float* c, const unsigned int* a, const unsigned int* b) {
    asm volatile(
        "mma.sync.aligned.m16n8k16.row.col.f32.f16.f16.f32 "
        "{%0,%1,%2,%3}, {%4,%5,%6,%7}, {%8,%9}, {%0,%1,%2,%3};"
        : "+f"(c[0]), "+f"(c[1]), "+f"(c[2]), "+f"(c[3])
        : "r"(a[0]), "r"(a[1]), "r"(a[2]), "r"(a[3]), "r"(b[0]), "r"(b[1]));
}

__global__ __launch_bounds__(256) void sage_mma(const __half* __restrict__ Xte, int xtew,
                                                const __half* __restrict__ Xh,
                                                const __half* __restrict__ Ps, int psw,
                                                const __half* __restrict__ Wb, int wstride,
                                                int nChunks,
                                                const float* __restrict__ bS,
                                                __half* __restrict__ out,
                                                const int* __restrict__ batch,
                                                const float* __restrict__ Wc,
                                                float* __restrict__ pool_out,
                                                int do_pool) {
    __shared__ __half As[2][128 * ASW];
    __shared__ __half Bs[2][128 * ASW];
    int tid = threadIdx.x, wid = tid >> 5, lane = tid & 31;
    int gr = lane >> 2, tg = lane & 3;
    int rowBase = blockIdx.x * 128;
    int wm = (wid >> 1) * 32, wn = (wid & 1) * 64;

    int lr = tid >> 2;
    int lc8 = (tid & 3) * 8;

    auto issue = [&](int kc, int buf) {
#pragma unroll
        for (int t = 0; t < 2; t++) {
            int r = lr + t * 64;
            int row = min(rowBase + r, NP - 1);
            const __half* sp;
            if (kc < xtew)
                sp = Xte + (size_t)row * xtew + kc + lc8;
            else if (kc < xtew + 32)
                sp = Xh + (size_t)row * 32 + (kc - xtew) + lc8;
            else
                sp = Ps + (size_t)row * psw + (kc - xtew - 32) + lc8;
            cp16(&As[buf][r * ASW + lc8], sp);
            cp16(&Bs[buf][r * ASW + lc8], Wb + (size_t)r * wstride + kc + lc8);
        }
    };

    float acc[2][8][4];
#pragma unroll
    for (int i = 0; i < 2; i++)
#pragma unroll
        for (int j = 0; j < 8; j++)
#pragma unroll
            for (int k = 0; k < 4; k++) acc[i][j][k] = 0.f;

    issue(0, 0);
    cp_commit();
    for (int i = 0; i < nChunks; i++) {
        if (i + 1 < nChunks) {
            issue((i + 1) * 32, (i + 1) & 1);
            cp_commit();
            cp_wait<1>();
        } else {
            cp_wait<0>();
        }
        __syncthreads();
        const __half* Ab = As[i & 1];
        const __half* Bb = Bs[i & 1];
#pragma unroll
        for (int ks = 0; ks < 2; ks++) {
            int k0 = ks * 16;
            unsigned int a[2][4];
#pragma unroll
            for (int mt = 0; mt < 2; mt++) {
                int r = wm + mt * 16 + gr;
                a[mt][0] = *(const unsigned int*)&Ab[r * ASW + k0 + 2 * tg];
                a[mt][1] = *(const unsigned int*)&Ab[(r + 8) * ASW + k0 + 2 * tg];
                a[mt][2] = *(const unsigned int*)&Ab[r * ASW + k0 + 2 * tg + 8];
                a[mt][3] = *(const unsigned int*)&Ab[(r + 8) * ASW + k0 + 2 * tg + 8];
            }
#pragma unroll
            for (int nt = 0; nt < 8; nt++) {
                int n = wn + nt * 8 + gr;
                unsigned int b[2];
                b[0] = *(const unsigned int*)&Bb[n * ASW + k0 + 2 * tg];
                b[1] = *(const unsigned int*)&Bb[n * ASW + k0 + 2 * tg + 8];
                mma_f16(acc[0][nt], a[0], b);
                mma_f16(acc[1][nt], a[1], b);
            }
        }
        __syncthreads();
    }

    if (do_pool) {
        float ps[4] = {0.f, 0.f, 0.f, 0.f};
#pragma unroll
        for (int mt = 0; mt < 2; mt++)
#pragma unroll
            for (int nt = 0; nt < 8; nt++) {
                int col = wn + nt * 8 + 2 * tg;
                float w0 = Wc[col], w1 = Wc[col + 1];
                float b0 = bS[col], b1 = bS[col + 1];
                ps[mt * 2 + 0] += fmaxf(acc[mt][nt][0] + b0, 0.f) * w0 +
                                  fmaxf(acc[mt][nt][1] + b1, 0.f) * w1;
                ps[mt * 2 + 1] += fmaxf(acc[mt][nt][2] + b0, 0.f) * w0 +
                                  fmaxf(acc[mt][nt][3] + b1, 0.f) * w1;
            }
#pragma unroll
        for (int j = 0; j < 4; j++) {
            ps[j] += __shfl_xor_sync(0xFFFFFFFFu, ps[j], 1);
            ps[j] += __shfl_xor_sync(0xFFFFFFFFu, ps[j], 2);
        }
        if (tg == 0) {
#pragma unroll
            for (int mt = 0; mt < 2; mt++) {
                int r0 = rowBase + wm + mt * 16 + gr;
                int r1 = r0 + 8;
                if (r0 < NP) atomicAdd(&pool_out[batch[r0]], ps[mt * 2]);
                if (r1 < NP) atomicAdd(&pool_out[batch[r1]], ps[mt * 2 + 1]);
            }
        }
    } else {
#pragma unroll
        for (int mt = 0; mt < 2; mt++) {
#pragma unroll
            for (int nt = 0; nt < 8; nt++) {
                int col = wn + nt * 8 + 2 * tg;
                float b0 = bS[col], b1 = bS[col + 1];
                int r0 = rowBase + wm + mt * 16 + gr;
                if (r0 < NP) {
                    __half2 v = __floats2half2_rn(fmaxf(acc[mt][nt][0] + b0, 0.f),
                                                  fmaxf(acc[mt][nt][1] + b1, 0.f));
                    *(__half2*)(out + (size_t)r0 * HD + col) = v;
                }
                int r1 = r0 + 8;
                if (r1 < NP) {
                    __half2 v = __floats2half2_rn(fmaxf(acc[mt][nt][2] + b0, 0.f),
                                                  fmaxf(acc[mt][nt][3] + b1, 0.f));
                    *(__half2*)(out + (size_t)r1 * HD + col) = v;
                }
            }
        }
    }
}

// -------- finalize + reset scratch state for the next (replayed) call --------
__global__ void fin_k(float* out, float* gc, const float* __restrict__ bc,
                      int* cnt, int* cur) {
    int g = blockIdx.x * blockDim.x + threadIdx.x;
    if (g < NG) {
        out[g] = out[g] / fmaxf(gc[g], 1.0f) + bc[0];
        gc[g] = 0.f;
    }
    if (g < SCAN_N) { cnt[g] = 0; cur[g] = 0; }
}

// -------------------------------- launcher -----------------------------------
extern "C" void kernel_launch(void* const* d_in, const int* in_sizes, int n_in,
                              void* d_out, int out_size) {
    const float* x_player = (const float*)d_in[0];
    const float* x_hist   = (const float*)d_in[1];
    const int*   e_t      = (const int*)d_in[2];
    const int*   e_e      = (const int*)d_in[3];
    const int*   e_h      = (const int*)d_in[4];
    const int*   batch    = (const int*)d_in[5];
    const float* emb_p    = (const float*)d_in[6];
    const float* emb_h0   = (const float*)d_in[7];
    const float* emb_h3   = (const float*)d_in[8];
    const float* Wp       = (const float*)d_in[9];
    const float* bp       = (const float*)d_in[10];
    const float* Wh       = (const float*)d_in[11];
    const float* bh       = (const float*)d_in[12];
    const float* sWl      = (const float*)d_in[13];
    const float* sb       = (const float*)d_in[14];
    const float* sWr      = (const float*)d_in[15];
    const float* Wc       = (const float*)d_in[16];
    const float* bc       = (const float*)d_in[17];
    float* out = (float*)d_out;

    __half *Rp, *P1, *Hc, *Xh, *X, *Wb0, *Wb1;
    float *bS, *GC;
    int *cnt, *cur, *offs, *bsum, *sorted;
    cudaGetSymbolAddress((void**)&Rp, g_Rp);
    cudaGetSymbolAddress((void**)&P1, g_P1);
    cudaGetSymbolAddress((void**)&Hc, g_Hc);
    cudaGetSymbolAddress((void**)&Xh, g_Xh);
    cudaGetSymbolAddress((void**)&X, g_X);
    cudaGetSymbolAddress((void**)&Wb0, g_Wb0);
    cudaGetSymbolAddress((void**)&Wb1, g_Wb1);
    cudaGetSymbolAddress((void**)&bS, g_bSum);
    cudaGetSymbolAddress((void**)&GC, g_GC);
    cudaGetSymbolAddress((void**)&cnt, g_cnt);
    cudaGetSymbolAddress((void**)&cur, g_cur);
    cudaGetSymbolAddress((void**)&offs, g_offs);
    cudaGetSymbolAddress((void**)&bsum, g_bsum);
    cudaGetSymbolAddress((void**)&sorted, g_sorted);

    // 1) fused prologue (features, weights, out-zero, graph counts, edge counts)
    prologue_k<<<PRO_BLOCKS, 256>>>(x_player, emb_p, x_hist, emb_h0, emb_h3,
                                    sWl, sWr, sb, Wp, bp, Wh, bh, batch,
                                    e_t, e_e, e_h,
                                    Rp, Hc, Wb0, Wb1, bS, out, GC, cnt);

    // 2-5) CSR scan + scatter
    scan1<<<SCAN_BLOCKS, 256>>>(cnt, offs, bsum);
    scan2<<<1, 512>>>(bsum, SCAN_BLOCKS);
    scan3<<<(SCAN_N + 255) / 256, 256>>>(offs, bsum);
    scatter_all<<<(NE_ALL + 255) / 256, 256>>>(e_t, e_e, e_h, offs, cur, sorted);

    int mmaBlocks = (NP + 127) / 128;

    // 6) layer-0 gathers (t/e strip-mined + hist MLP-4)
    agg0_k<<<TE_BLOCKS + AH_BLOCKS, 256>>>(Rp, Hc, sorted, offs, cnt, X, Xh);

    // 7) layer-0 GEMM (K=320, folded encoder)
    sage_mma<<<mmaBlocks, 256>>>(X, 192, Xh, Rp, RPW, Wb0, K0, K0 / 32, bS,
                                 P1, batch, Wc, out, 0);

    // 8) layer-1 gathers (strip-mined)
    agg1_k<<<TE_BLOCKS, 256>>>(P1, sorted, offs, cnt, X);

    // 9) layer-1 GEMM + fused pooling
    sage_mma<<<mmaBlocks, 256>>>(X, 256, Xh, P1, HD, Wb1, K1, K1 / 32, bS + HD,
                                 P1, batch, Wc, out, 1);

    // 10) finalize + state reset for next replay
    fin_k<<<(SCAN_N + 255) / 256, 256>>>(out, GC, bc, cnt, cur);
}